// round 5
// baseline (speedup 1.0000x reference)
#include <cuda_runtime.h>
#include <cstdint>
#include <cstddef>

#define TT 4
#define BB 4
#define CC 384
#define NN 4096
#define IMG 16
#define BCN (BB*CC*NN)
#define HEADS 6
#define DH 64
#define PADW 66
#define EPS 1e-5f

// ---------------- scratch (static device globals) ----------------
__device__ __align__(256) float g_XS [IMG*NN*CC];         // spikes of x (NHWC)
__device__ __align__(256) float g_PAD[IMG*PADW*PADW*CC];  // bn1+pad (NHWC, 66x66)
__device__ __align__(256) float g_DW [IMG*NN*CC];         // depthwise out (NHWC)
__device__ __align__(256) float g_BR [IMG*NN*CC];         // branch out / attention a (NHWC)
__device__ __align__(256) float g_QS [IMG*NN*CC];
__device__ __align__(256) float g_KS [IMG*NN*CC];
__device__ __align__(256) float g_VS [IMG*NN*CC];
__device__ __align__(256) float g_AS [IMG*NN*CC];
__device__ __align__(256) float g_KVP[4*TT*BB*HEADS*DH*DH];
__device__ __align__(256) float g_KV [TT*BB*HEADS*DH*DH];

__device__ __forceinline__ float tf32r(float x) {
    uint32_t u;
    asm("cvt.rna.tf32.f32 %0, %1;" : "=r"(u) : "f"(x));
    return __uint_as_float(u);
}
__device__ __forceinline__ void mma8(float* c, uint32_t a0, uint32_t a1, uint32_t a2, uint32_t a3,
                                     uint32_t b0, uint32_t b1) {
    asm volatile("mma.sync.aligned.m16n8k8.row.col.f32.tf32.tf32.f32 "
                 "{%0,%1,%2,%3}, {%4,%5,%6,%7}, {%8,%9}, {%0,%1,%2,%3};"
                 : "+f"(c[0]), "+f"(c[1]), "+f"(c[2]), "+f"(c[3])
                 : "r"(a0), "r"(a1), "r"(a2), "r"(a3), "r"(b0), "r"(b1));
}

// smem word layout (floats). ROWS_W MUST be even (8B-aligned float2 smem loads);
// 40 gives conflict-free lds.64 fragment loads (lr*40+2*lc mod 32 = lr*8+2*lc, all distinct).
#define ROWS_W 40
#define SA_H 0
#define SA_L (128*ROWS_W)       // 5120
#define SB_H (2*128*ROWS_W)     // 10240
#define SB_L (3*128*ROWS_W)     // 15360
#define SCL  (4*128*ROWS_W)     // 20480
#define SBS  (SCL+128)          // 20608
#define SMEM_FLOATS (SBS+128)   // 20736
#define SMEM_BYTES  (SMEM_FLOATS*4)

// k permutation within each 8-block: pairs (k, k+4) adjacent.
// global k = q*4+i (q=0..7 quad, i component) -> word = (q>>1)*8 + 2*i + (q&1)
__device__ __forceinline__ int kperm(int q, int i) { return ((q >> 1) << 3) + (i << 1) + (q & 1); }

// ---------------- mma.sync tf32 split-precision conv1x1 ----------------
// D[p][o] = sum_c X[p][c] * W[o][c]  (M=128 spatial tile, N=128 outch tile, K=384)
// mode 0: binary input (2 passes), bn1 epilogue, write PAD interior (NHWC)
// mode 1: dense input (3 passes), bn2*bn3 epilogue, write NHWC
// mode 2: dense input (3 passes), bn2*bn3 epilogue, write NCHW (d_out)
__global__ void __launch_bounds__(256, 1)
conv_mma_kernel(const float* __restrict__ X, const float* __restrict__ W,
                float* __restrict__ OUT,
                const float* __restrict__ wA, const float* __restrict__ bA,
                const float* __restrict__ mA, const float* __restrict__ vA,
                const float* __restrict__ wB, const float* __restrict__ bB2,
                const float* __restrict__ mB, const float* __restrict__ vB,
                int mode) {
    extern __shared__ float sm[];
    int tx = threadIdx.x;
    int wid = tx >> 5, lane = tx & 31;
    int lr = lane >> 2, lc = lane & 3;
    int wm = wid & 1, wn = wid >> 1;        // warp grid 2(m) x 4(n)
    int img = blockIdx.z;
    int p0 = blockIdx.x * 128;
    int n0 = blockIdx.y * 128;

    // fused BN scale/bias (for this CTA's 128 out-channels)
    if (tx < 128) {
        int o = n0 + tx;
        float s, bias;
        if (mode == 0) {
            float inv = wA[o] * rsqrtf(vA[o] + EPS);
            s = inv; bias = bA[o] - mA[o] * inv;
        } else {
            float s2 = wA[o] * rsqrtf(vA[o] + EPS);
            float t2 = bA[o] - mA[o] * s2;
            float s3 = wB[o] * rsqrtf(vB[o] + EPS);
            float t3 = bB2[o] - mB[o] * s3;
            s = s2 * s3; bias = t2 * s3 + t3;
        }
        sm[SCL + tx] = s;
        sm[SBS + tx] = bias;
    }

    const float* Xp = X + ((size_t)img * NN + p0) * CC;
    const float* Wp = W + (size_t)n0 * CC;
    bool dense = (mode != 0);

    float acc[4][4][4];
#pragma unroll
    for (int a = 0; a < 4; a++)
#pragma unroll
        for (int b = 0; b < 4; b++)
#pragma unroll
            for (int c = 0; c < 4; c++) acc[a][b][c] = 0.0f;

    for (int ch = 0; ch < 12; ch++) {
        int c0 = ch * 32;
        // ---- load B (weights) 128 rows x 32 k, split hi/lo ----
#pragma unroll
        for (int it = 0; it < 4; it++) {
            int u = tx + it * 256;
            int row = u >> 3, q = u & 7;
            float4 v = *(const float4*)(Wp + (size_t)row * CC + c0 + q * 4);
            float h, l;
            h = tf32r(v.x); l = tf32r(v.x - h);
            sm[SB_H + row * ROWS_W + kperm(q, 0)] = h; sm[SB_L + row * ROWS_W + kperm(q, 0)] = l;
            h = tf32r(v.y); l = tf32r(v.y - h);
            sm[SB_H + row * ROWS_W + kperm(q, 1)] = h; sm[SB_L + row * ROWS_W + kperm(q, 1)] = l;
            h = tf32r(v.z); l = tf32r(v.z - h);
            sm[SB_H + row * ROWS_W + kperm(q, 2)] = h; sm[SB_L + row * ROWS_W + kperm(q, 2)] = l;
            h = tf32r(v.w); l = tf32r(v.w - h);
            sm[SB_H + row * ROWS_W + kperm(q, 3)] = h; sm[SB_L + row * ROWS_W + kperm(q, 3)] = l;
        }
        // ---- load A (activations) 128 rows x 32 k ----
#pragma unroll
        for (int it = 0; it < 4; it++) {
            int u = tx + it * 256;
            int row = u >> 3, q = u & 7;
            float4 v = *(const float4*)(Xp + (size_t)row * CC + c0 + q * 4);
            if (!dense) {
                sm[SA_H + row * ROWS_W + kperm(q, 0)] = v.x;
                sm[SA_H + row * ROWS_W + kperm(q, 1)] = v.y;
                sm[SA_H + row * ROWS_W + kperm(q, 2)] = v.z;
                sm[SA_H + row * ROWS_W + kperm(q, 3)] = v.w;
            } else {
                float h, l;
                h = tf32r(v.x); l = tf32r(v.x - h);
                sm[SA_H + row * ROWS_W + kperm(q, 0)] = h; sm[SA_L + row * ROWS_W + kperm(q, 0)] = l;
                h = tf32r(v.y); l = tf32r(v.y - h);
                sm[SA_H + row * ROWS_W + kperm(q, 1)] = h; sm[SA_L + row * ROWS_W + kperm(q, 1)] = l;
                h = tf32r(v.z); l = tf32r(v.z - h);
                sm[SA_H + row * ROWS_W + kperm(q, 2)] = h; sm[SA_L + row * ROWS_W + kperm(q, 2)] = l;
                h = tf32r(v.w); l = tf32r(v.w - h);
                sm[SA_H + row * ROWS_W + kperm(q, 3)] = h; sm[SA_L + row * ROWS_W + kperm(q, 3)] = l;
            }
        }
        __syncthreads();

#pragma unroll
        for (int kk = 0; kk < 4; kk++) {
            int kb = kk * 8 + 2 * lc;
            uint32_t A0[4], A1[4], A2[4], A3[4];
#pragma unroll
            for (int mt = 0; mt < 4; mt++) {
                int r = wm * 64 + mt * 16 + lr;
                float2 u0 = *(float2*)&sm[SA_H + r * ROWS_W + kb];
                float2 u1 = *(float2*)&sm[SA_H + (r + 8) * ROWS_W + kb];
                A0[mt] = __float_as_uint(u0.x); A2[mt] = __float_as_uint(u0.y);
                A1[mt] = __float_as_uint(u1.x); A3[mt] = __float_as_uint(u1.y);
            }
            uint32_t Bh0[4], Bh1[4], Bl0[4], Bl1[4];
#pragma unroll
            for (int nt = 0; nt < 4; nt++) {
                int n = wn * 32 + nt * 8 + lr;
                float2 vh = *(float2*)&sm[SB_H + n * ROWS_W + kb];
                float2 vl = *(float2*)&sm[SB_L + n * ROWS_W + kb];
                Bh0[nt] = __float_as_uint(vh.x); Bh1[nt] = __float_as_uint(vh.y);
                Bl0[nt] = __float_as_uint(vl.x); Bl1[nt] = __float_as_uint(vl.y);
            }
#pragma unroll
            for (int mt = 0; mt < 4; mt++)
#pragma unroll
                for (int nt = 0; nt < 4; nt++)
                    mma8(acc[mt][nt], A0[mt], A1[mt], A2[mt], A3[mt], Bh0[nt], Bh1[nt]);
#pragma unroll
            for (int mt = 0; mt < 4; mt++)
#pragma unroll
                for (int nt = 0; nt < 4; nt++)
                    mma8(acc[mt][nt], A0[mt], A1[mt], A2[mt], A3[mt], Bl0[nt], Bl1[nt]);
            if (dense) {
#pragma unroll
                for (int mt = 0; mt < 4; mt++) {
                    int r = wm * 64 + mt * 16 + lr;
                    float2 u0 = *(float2*)&sm[SA_L + r * ROWS_W + kb];
                    float2 u1 = *(float2*)&sm[SA_L + (r + 8) * ROWS_W + kb];
                    A0[mt] = __float_as_uint(u0.x); A2[mt] = __float_as_uint(u0.y);
                    A1[mt] = __float_as_uint(u1.x); A3[mt] = __float_as_uint(u1.y);
                }
#pragma unroll
                for (int mt = 0; mt < 4; mt++)
#pragma unroll
                    for (int nt = 0; nt < 4; nt++)
                        mma8(acc[mt][nt], A0[mt], A1[mt], A2[mt], A3[mt], Bh0[nt], Bh1[nt]);
            }
        }
        __syncthreads();
    }

    // ---------------- epilogue ----------------
    if (mode != 2) {
#pragma unroll
        for (int mt = 0; mt < 4; mt++) {
            int pa = p0 + wm * 64 + mt * 16 + lr;
            int pb = pa + 8;
#pragma unroll
            for (int nt = 0; nt < 4; nt++) {
                int ol = wn * 32 + nt * 8 + 2 * lc;
                float s0 = sm[SCL + ol], s1 = sm[SCL + ol + 1];
                float z0 = sm[SBS + ol], z1 = sm[SBS + ol + 1];
                float2 v0 = make_float2(acc[mt][nt][0] * s0 + z0, acc[mt][nt][1] * s1 + z1);
                float2 v1 = make_float2(acc[mt][nt][2] * s0 + z0, acc[mt][nt][3] * s1 + z1);
                if (mode == 0) {
                    int ra = pa >> 6, ca = pa & 63;
                    int rb = pb >> 6, cb = pb & 63;
                    *(float2*)(OUT + ((((size_t)img * PADW + ra + 1) * PADW + ca + 1) * CC) + n0 + ol) = v0;
                    *(float2*)(OUT + ((((size_t)img * PADW + rb + 1) * PADW + cb + 1) * CC) + n0 + ol) = v1;
                } else {
                    *(float2*)(OUT + ((size_t)img * NN + pa) * CC + n0 + ol) = v0;
                    *(float2*)(OUT + ((size_t)img * NN + pb) * CC + n0 + ol) = v1;
                }
            }
        }
    } else {
        // NCHW output: stage per-warp 32(n) x 64(m) tile in smem, then coalesced rows
        float* T = sm + wid * (32 * 66);
#pragma unroll
        for (int mt = 0; mt < 4; mt++) {
            int ma = mt * 16 + lr;
#pragma unroll
            for (int nt = 0; nt < 4; nt++) {
                int nl = nt * 8 + 2 * lc;
                int ol = wn * 32 + nl;
                float s0 = sm[SCL + ol], s1 = sm[SCL + ol + 1];
                float z0 = sm[SBS + ol], z1 = sm[SBS + ol + 1];
                T[nl * 66 + ma]           = acc[mt][nt][0] * s0 + z0;
                T[(nl + 1) * 66 + ma]     = acc[mt][nt][1] * s1 + z1;
                T[nl * 66 + ma + 8]       = acc[mt][nt][2] * s0 + z0;
                T[(nl + 1) * 66 + ma + 8] = acc[mt][nt][3] * s1 + z1;
            }
        }
        __syncwarp();
#pragma unroll
        for (int ol = 0; ol < 32; ol++) {
            int o = n0 + wn * 32 + ol;
            float2 v = make_float2(T[ol * 66 + lane * 2], T[ol * 66 + lane * 2 + 1]);
            *(float2*)(OUT + ((size_t)img * CC + o) * NN + p0 + wm * 64 + lane * 2) = v;
        }
    }
}

// ---------------- ALIF: first (NCHW in -> NHWC spikes out, transpose) ----------------
__global__ void alif_first_kernel(const float* __restrict__ in, float* __restrict__ out,
                                  const float* __restrict__ vth_ptr) {
    __shared__ float s[32][33];
    int tx = threadIdx.x, ty = threadIdx.y;
    int n0 = blockIdx.x * 32;
    int c0 = blockIdx.y * 32;
    int b = blockIdx.z;
    float vth = vth_ptr[0];
    float v[4] = {0.f, 0.f, 0.f, 0.f};
#pragma unroll
    for (int t = 0; t < TT; t++) {
#pragma unroll
        for (int k = 0; k < 4; k++) {
            int c = c0 + ty + 8 * k;
            float xv = in[(((size_t)(t * BB + b) * CC + c) * NN) + n0 + tx];
            v[k] = v[k] + (xv - v[k]) * 0.5f;
            s[ty + 8 * k][tx] = (v[k] - vth >= 0.0f) ? 1.0f : 0.0f;
        }
        __syncthreads();
#pragma unroll
        for (int k = 0; k < 4; k++) {
            int n = n0 + ty + 8 * k;
            out[((size_t)(t * BB + b) * NN + n) * CC + c0 + tx] = s[tx][ty + 8 * k];
        }
        __syncthreads();
    }
}

// ---------------- ALIF generic (elementwise scan over t) ----------------
__global__ void alif_kernel(const float* __restrict__ in, float* __restrict__ out,
                            const float* __restrict__ vth_ptr, int vidx) {
    int j = blockIdx.x * blockDim.x + threadIdx.x;
    if (j >= BCN) return;
    float vth = vth_ptr[vidx];
    float v = 0.0f;
#pragma unroll
    for (int t = 0; t < TT; t++) {
        float x = in[(size_t)j + (size_t)t * BCN];
        v = v + (x - v) * 0.5f;
        out[(size_t)j + (size_t)t * BCN] = (v - vth >= 0.0f) ? 1.0f : 0.0f;
    }
}

// ---------------- pad border fill (NHWC) ----------------
__global__ void padfill_kernel(float* __restrict__ pad,
                               const float* __restrict__ bw, const float* __restrict__ bb,
                               const float* __restrict__ bm, const float* __restrict__ bv) {
    int t = blockIdx.x;
    int img = blockIdx.y;
    int c = threadIdx.x;
    float inv = bw[c] * rsqrtf(bv[c] + EPS);
    float pv = bb[c] - bm[c] * inv;
    int r, cl;
    if      (t < 66)  { r = 0;           cl = t;        }
    else if (t < 132) { r = 65;          cl = t - 66;   }
    else if (t < 196) { r = t - 132 + 1; cl = 0;        }
    else              { r = t - 196 + 1; cl = 65;       }
    pad[(((size_t)img * PADW + r) * PADW + cl) * CC + c] = pv;
}

// ---------------- depthwise 3x3 VALID (NHWC) ----------------
__global__ void dwconv_kernel(const float* __restrict__ pad, const float* __restrict__ w9,
                              float* __restrict__ out) {
    int c = threadIdx.x;
    int p = blockIdx.x;
    int img = blockIdx.y;
    int r = p >> 6, cl = p & 63;
    const float* base = pad + (((size_t)img * PADW + r) * PADW + cl) * CC + c;
    float wr[9];
#pragma unroll
    for (int k = 0; k < 9; k++) wr[k] = __ldg(w9 + c * 9 + k);
    float sacc = 0.0f;
#pragma unroll
    for (int i = 0; i < 3; i++)
#pragma unroll
        for (int j = 0; j < 3; j++)
            sacc += wr[i * 3 + j] * base[(size_t)(i * PADW + j) * CC];
    out[((size_t)img * NN + p) * CC + c] = sacc;
}

// ---------------- kv partial (NHWC): kvp[seg][tbh][d][e] ----------------
__global__ void kv_kernel(const float* __restrict__ K, const float* __restrict__ V,
                          float* __restrict__ KVP) {
    int seg = blockIdx.x;
    int tbh = blockIdx.y;
    int tb = tbh / HEADS, h = tbh % HEADS;
    __shared__ float Ks[64][65];
    __shared__ float Vs[64][65];
    int tx = threadIdx.x;
    int td = tx >> 4, te = tx & 15;
    const float* Kb = K + (size_t)tb * NN * CC + h * DH;
    const float* Vb = V + (size_t)tb * NN * CC + h * DH;
    float acc[4][4];
#pragma unroll
    for (int i = 0; i < 4; i++)
#pragma unroll
        for (int j = 0; j < 4; j++) acc[i][j] = 0.0f;

    for (int n0 = seg * 1024; n0 < (seg + 1) * 1024; n0 += 64) {
#pragma unroll
        for (int u = 0; u < 16; u++) {
            int e = tx + u * 256;
            int n = e >> 6, d = e & 63;
            Ks[n][d] = Kb[(size_t)(n0 + n) * CC + d];
            Vs[n][d] = Vb[(size_t)(n0 + n) * CC + d];
        }
        __syncthreads();
#pragma unroll
        for (int n = 0; n < 64; n++) {
            float a0 = Ks[n][td * 4 + 0], a1 = Ks[n][td * 4 + 1];
            float a2 = Ks[n][td * 4 + 2], a3 = Ks[n][td * 4 + 3];
            float b0 = Vs[n][te * 4 + 0], b1 = Vs[n][te * 4 + 1];
            float b2 = Vs[n][te * 4 + 2], b3 = Vs[n][te * 4 + 3];
            acc[0][0] += a0 * b0; acc[0][1] += a0 * b1; acc[0][2] += a0 * b2; acc[0][3] += a0 * b3;
            acc[1][0] += a1 * b0; acc[1][1] += a1 * b1; acc[1][2] += a1 * b2; acc[1][3] += a1 * b3;
            acc[2][0] += a2 * b0; acc[2][1] += a2 * b1; acc[2][2] += a2 * b2; acc[2][3] += a2 * b3;
            acc[3][0] += a3 * b0; acc[3][1] += a3 * b1; acc[3][2] += a3 * b2; acc[3][3] += a3 * b3;
        }
        __syncthreads();
    }
#pragma unroll
    for (int i = 0; i < 4; i++)
#pragma unroll
        for (int j = 0; j < 4; j++)
            KVP[((size_t)seg * (TT * BB * HEADS) + tbh) * (DH * DH) + (td * 4 + i) * DH + te * 4 + j] =
                acc[i][j];
}

__global__ void kvred_kernel(const float* __restrict__ KVP, float* __restrict__ KV) {
    int idx = blockIdx.x * blockDim.x + threadIdx.x;
    const int tot = TT * BB * HEADS * DH * DH;
    if (idx >= tot) return;
    float s = 0.f;
#pragma unroll
    for (int g = 0; g < 4; g++) s += KVP[(size_t)g * tot + idx];
    KV[idx] = s;
}

// ---------------- av (NHWC): A[tb][n][h*64+e] = sum_d Q[tb][n][h*64+d]*KV[tbh][d][e] ----------------
__global__ void av_kernel(const float* __restrict__ Q, const float* __restrict__ KV,
                          float* __restrict__ A) {
    int nt = blockIdx.x;
    int tbh = blockIdx.y;
    int tb = tbh / HEADS, h = tbh % HEADS;
    __shared__ float kvs[64][65];
    __shared__ float Qs[64][65];
    int tx = threadIdx.x;
    int tn = tx >> 4, te = tx & 15;
    int n0 = nt * 64;
    const float* Qb = Q + (size_t)tb * NN * CC + h * DH;
#pragma unroll
    for (int u = 0; u < 16; u++) {
        int e = tx + u * 256;
        int r = e >> 6, x = e & 63;
        kvs[r][x] = KV[(size_t)tbh * DH * DH + r * DH + x];
        Qs[r][x] = Qb[(size_t)(n0 + r) * CC + x];
    }
    __syncthreads();
    float acc[4][4];
#pragma unroll
    for (int i = 0; i < 4; i++)
#pragma unroll
        for (int j = 0; j < 4; j++) acc[i][j] = 0.0f;
#pragma unroll
    for (int d = 0; d < 64; d++) {
        float a0 = Qs[tn * 4 + 0][d], a1 = Qs[tn * 4 + 1][d];
        float a2 = Qs[tn * 4 + 2][d], a3 = Qs[tn * 4 + 3][d];
        float b0 = kvs[d][te * 4 + 0], b1 = kvs[d][te * 4 + 1];
        float b2 = kvs[d][te * 4 + 2], b3 = kvs[d][te * 4 + 3];
        acc[0][0] += a0 * b0; acc[0][1] += a0 * b1; acc[0][2] += a0 * b2; acc[0][3] += a0 * b3;
        acc[1][0] += a1 * b0; acc[1][1] += a1 * b1; acc[1][2] += a1 * b2; acc[1][3] += a1 * b3;
        acc[2][0] += a2 * b0; acc[2][1] += a2 * b1; acc[2][2] += a2 * b2; acc[2][3] += a2 * b3;
        acc[3][0] += a3 * b0; acc[3][1] += a3 * b1; acc[3][2] += a3 * b2; acc[3][3] += a3 * b3;
    }
#pragma unroll
    for (int i = 0; i < 4; i++) {
        int n = n0 + tn * 4 + i;
        float4 w4;
        w4.x = acc[i][0]; w4.y = acc[i][1]; w4.z = acc[i][2]; w4.w = acc[i][3];
        *(float4*)(A + ((size_t)tb * NN + n) * CC + h * DH + te * 4) = w4;
    }
}

// ---------------- host orchestration ----------------
static void run_branch(const float* in, int i, float* out, int out_mode,
                       const float* w1, const float* dw, const float* pw,
                       const float* b1w, const float* b1b, const float* b1m, const float* b1v,
                       const float* b2w, const float* b2b, const float* b2m, const float* b2v,
                       const float* b3w, const float* b3b, const float* b3m, const float* b3v,
                       float* PAD, float* DWB) {
    padfill_kernel<<<dim3(260, IMG), CC>>>(PAD, b1w + i * CC, b1b + i * CC, b1m + i * CC, b1v + i * CC);
    conv_mma_kernel<<<dim3(32, 3, IMG), 256, SMEM_BYTES>>>(in, w1 + (size_t)i * CC * CC, PAD,
        b1w + i * CC, b1b + i * CC, b1m + i * CC, b1v + i * CC,
        nullptr, nullptr, nullptr, nullptr, 0);
    dwconv_kernel<<<dim3(NN, IMG), CC>>>(PAD, dw + (size_t)i * CC * 9, DWB);
    conv_mma_kernel<<<dim3(32, 3, IMG), 256, SMEM_BYTES>>>(DWB, pw + (size_t)i * CC * CC, out,
        b2w + i * CC, b2b + i * CC, b2m + i * CC, b2v + i * CC,
        b3w + i * CC, b3b + i * CC, b3m + i * CC, b3v + i * CC, out_mode);
}

extern "C" void kernel_launch(void* const* d_in, const int* in_sizes, int n_in,
                              void* d_out, int out_size) {
    const float* x   = (const float*)d_in[0];
    const float* w1  = (const float*)d_in[1];
    const float* dw  = (const float*)d_in[2];
    const float* pw  = (const float*)d_in[3];
    const float* b1w = (const float*)d_in[4];
    const float* b1b = (const float*)d_in[5];
    const float* b1m = (const float*)d_in[6];
    const float* b1v = (const float*)d_in[7];
    const float* b2w = (const float*)d_in[8];
    const float* b2b = (const float*)d_in[9];
    const float* b2m = (const float*)d_in[10];
    const float* b2v = (const float*)d_in[11];
    const float* b3w = (const float*)d_in[12];
    const float* b3b = (const float*)d_in[13];
    const float* b3m = (const float*)d_in[14];
    const float* b3v = (const float*)d_in[15];
    const float* vth = (const float*)d_in[16];
    float* out = (float*)d_out;

    cudaFuncSetAttribute(conv_mma_kernel, cudaFuncAttributeMaxDynamicSharedMemorySize, SMEM_BYTES);

    float *XS, *PAD, *DWB, *BR, *QS, *KS, *VS, *AS, *KVP, *KV;
    cudaGetSymbolAddress((void**)&XS,  g_XS);
    cudaGetSymbolAddress((void**)&PAD, g_PAD);
    cudaGetSymbolAddress((void**)&DWB, g_DW);
    cudaGetSymbolAddress((void**)&BR,  g_BR);
    cudaGetSymbolAddress((void**)&QS,  g_QS);
    cudaGetSymbolAddress((void**)&KS,  g_KS);
    cudaGetSymbolAddress((void**)&VS,  g_VS);
    cudaGetSymbolAddress((void**)&AS,  g_AS);
    cudaGetSymbolAddress((void**)&KVP, g_KVP);
    cudaGetSymbolAddress((void**)&KV,  g_KV);

    const int athreads = 256;
    const int ablocks = (BCN + athreads - 1) / athreads;

    // 1) alif on x, NCHW -> NHWC spikes
    alif_first_kernel<<<dim3(NN / 32, CC / 32, BB), dim3(32, 8)>>>(x, XS, vth);

    // 2) q/k/v branches (NHWC throughout)
    float* sp[3] = {QS, KS, VS};
    for (int i = 0; i < 3; i++) {
        run_branch(XS, i, BR, 1, w1, dw, pw,
                   b1w, b1b, b1m, b1v, b2w, b2b, b2m, b2v, b3w, b3b, b3m, b3v, PAD, DWB);
        alif_kernel<<<ablocks, athreads>>>(BR, sp[i], vth, 1 + i);
    }

    // 3) linear attention (exact fp32)
    kv_kernel<<<dim3(4, TT * BB * HEADS), 256>>>(KS, VS, KVP);
    kvred_kernel<<<(TT * BB * HEADS * DH * DH + 255) / 256, 256>>>(KVP, KV);
    av_kernel<<<dim3(64, TT * BB * HEADS), 256>>>(QS, KV, BR);
    alif_kernel<<<ablocks, athreads>>>(BR, AS, vth, 4);

    // 4) final branch -> d_out (NCHW)
    run_branch(AS, 3, out, 2, w1, dw, pw,
               b1w, b1b, b1m, b1v, b2w, b2b, b2m, b2v, b3w, b3b, b3m, b3v, PAD, DWB);
}

// round 6
// speedup vs baseline: 1.2398x; 1.2398x over previous
#include <cuda_runtime.h>
#include <cstdint>
#include <cstddef>

#define TT 4
#define BB 4
#define CC 384
#define NN 4096
#define IMG 16
#define BCN (BB*CC*NN)
#define HEADS 6
#define DH 64
#define PADW 66
#define EPS 1e-5f

// ---------------- scratch (static device globals) ----------------
__device__ __align__(256) float g_XS [IMG*NN*CC];         // spikes of x (NHWC, K-permuted chans)
__device__ __align__(256) float g_PAD[IMG*PADW*PADW*CC];  // bn1+pad (NHWC, natural chans)
__device__ __align__(256) float g_DWH[IMG*NN*CC];         // depthwise out hi (permuted)
__device__ __align__(256) float g_DWL[IMG*NN*CC];         // depthwise out lo (permuted)
__device__ __align__(256) float g_BR [IMG*NN*CC];         // branch out / attention a (natural)
__device__ __align__(256) float g_QS [IMG*NN*CC];
__device__ __align__(256) float g_KS [IMG*NN*CC];
__device__ __align__(256) float g_VS [IMG*NN*CC];
__device__ __align__(256) float g_AS [IMG*NN*CC];         // spikes of attention (permuted)
__device__ __align__(256) float g_WH [CC*CC];             // presplit weights hi (permuted k)
__device__ __align__(256) float g_WL [CC*CC];
__device__ __align__(256) float g_KVP[4*TT*BB*HEADS*DH*DH];
__device__ __align__(256) float g_KV [TT*BB*HEADS*DH*DH];

__device__ __forceinline__ float tf32r(float x) {
    uint32_t u;
    asm("cvt.rna.tf32.f32 %0, %1;" : "=r"(u) : "f"(x));
    return __uint_as_float(u);
}
__device__ __forceinline__ void mma8(float* c, uint32_t a0, uint32_t a1, uint32_t a2, uint32_t a3,
                                     uint32_t b0, uint32_t b1) {
    asm volatile("mma.sync.aligned.m16n8k8.row.col.f32.tf32.tf32.f32 "
                 "{%0,%1,%2,%3}, {%4,%5,%6,%7}, {%8,%9}, {%0,%1,%2,%3};"
                 : "+f"(c[0]), "+f"(c[1]), "+f"(c[2]), "+f"(c[3])
                 : "r"(a0), "r"(a1), "r"(a2), "r"(a3), "r"(b0), "r"(b1));
}
__device__ __forceinline__ void cp16(uint32_t dst, const void* src) {
    asm volatile("cp.async.cg.shared.global [%0], [%1], 16;" :: "r"(dst), "l"(src));
}
#define CP_COMMIT() asm volatile("cp.async.commit_group;" ::: "memory")
#define CP_WAIT0()  asm volatile("cp.async.wait_group 0;" ::: "memory")
#define CP_WAIT1()  asm volatile("cp.async.wait_group 1;" ::: "memory")
__device__ __forceinline__ uint32_t s2u(const void* p) {
    uint32_t a;
    asm("{ .reg .u64 t; cvta.to.shared.u64 t, %1; cvt.u32.u64 %0, t; }" : "=r"(a) : "l"(p));
    return a;
}
// K permutation within each 32-chunk: k = kk*8+j -> 8*(j&3) + 2*kk + (j>>2)
// (pairs (lc, lc+4) for kk and kk+1 land in one float4 -> lds.128 fragments)
__device__ __forceinline__ int permc(int c) {
    int ch = c & ~31, r = c & 31, kk = r >> 3, j = r & 7;
    return ch + 8 * (j & 3) + 2 * kk + (j >> 2);
}

// ---- smem layout (floats): 2 stages of [A_H 256x36 | A_L 256x36 | B_H 128x36 | B_L 128x36]
#define RSW 36
#define SAH 0
#define SAL (256*RSW)            // 9216
#define SBH (2*256*RSW)          // 18432
#define SBL (SBH + 128*RSW)      // 23040
#define STAGE (SBL + 128*RSW)    // 27648 floats = 110592 B
#define SCL (2*STAGE)            // 55296
#define SBS (SCL + 128)
#define SMEM_FLOATS (SBS + 128)  // 55552
#define SMEM_BYTES (SMEM_FLOATS*4)   // 222208

// ---------------- conv1x1: cp.async double-buffered split-tf32 mma ----------------
// D[p][o] = sum_c A[p][c]*W[o][c]; CTA tile 256(M) x 128(N), K=384 in 12 chunks of 32.
// mode 0: A binary (AH only, 2 passes), bn1 epilogue -> PAD interior (NHWC)
// mode 1: A split hi/lo (3 passes), bn2*bn3 epilogue -> NHWC
// mode 2: like 1 but writes NCHW (d_out)
__global__ void __launch_bounds__(256, 1)
conv_mma_kernel(const float* __restrict__ AH, const float* __restrict__ AL,
                const float* __restrict__ WH, const float* __restrict__ WL,
                float* __restrict__ OUT,
                const float* __restrict__ wA, const float* __restrict__ bA,
                const float* __restrict__ mA, const float* __restrict__ vA,
                const float* __restrict__ wB, const float* __restrict__ bB2,
                const float* __restrict__ mB, const float* __restrict__ vB,
                int mode) {
    extern __shared__ float sm[];
    const int tx = threadIdx.x;
    const int wid = tx >> 5, lane = tx & 31;
    const int lr = lane >> 2, lc = lane & 3;
    const int wm = wid >> 1, wn = wid & 1;          // 4(m) x 2(n) warps; warp tile 64x64
    const int img = blockIdx.z;
    const int p0 = blockIdx.x * 256;
    const int n0 = blockIdx.y * 128;
    const bool dense = (mode != 0);
    const size_t arow0 = (size_t)img * NN + p0;
    const uint32_t smb = s2u(sm);

    if (tx < 128) {
        int o = n0 + tx;
        float s, bias;
        if (mode == 0) {
            float inv = wA[o] * rsqrtf(vA[o] + EPS);
            s = inv; bias = bA[o] - mA[o] * inv;
        } else {
            float s2 = wA[o] * rsqrtf(vA[o] + EPS);
            float t2 = bA[o] - mA[o] * s2;
            float s3 = wB[o] * rsqrtf(vB[o] + EPS);
            float t3 = bB2[o] - mB[o] * s3;
            s = s2 * s3; bias = t2 * s3 + t3;
        }
        sm[SCL + tx] = s;
        sm[SBS + tx] = bias;
    }

    auto issue_chunk = [&](int ch, int st) {
        int c0 = ch * 32;
        uint32_t stb = smb + (uint32_t)st * (STAGE * 4);
#pragma unroll
        for (int it = 0; it < 8; it++) {
            int u = tx + it * 256;
            int row = u >> 3, q = u & 7;
            cp16(stb + SAH * 4 + row * 144 + q * 16,
                 AH + (arow0 + row) * CC + c0 + q * 4);
        }
        if (dense) {
#pragma unroll
            for (int it = 0; it < 8; it++) {
                int u = tx + it * 256;
                int row = u >> 3, q = u & 7;
                cp16(stb + SAL * 4 + row * 144 + q * 16,
                     AL + (arow0 + row) * CC + c0 + q * 4);
            }
        }
#pragma unroll
        for (int it = 0; it < 4; it++) {
            int u = tx + it * 256;
            int row = u >> 3, q = u & 7;
            cp16(stb + SBH * 4 + row * 144 + q * 16,
                 WH + (size_t)(n0 + row) * CC + c0 + q * 4);
            cp16(stb + SBL * 4 + row * 144 + q * 16,
                 WL + (size_t)(n0 + row) * CC + c0 + q * 4);
        }
    };

    float acc[4][8][4];
#pragma unroll
    for (int a = 0; a < 4; a++)
#pragma unroll
        for (int b = 0; b < 8; b++)
#pragma unroll
            for (int c = 0; c < 4; c++) acc[a][b][c] = 0.0f;

    auto compute = [&](int st) {
        const float* S = sm + st * STAGE;
#pragma unroll
        for (int kk2 = 0; kk2 < 2; kk2++) {
            int off = 8 * lc + 4 * kk2;
            float4 Ah[4][2];
#pragma unroll
            for (int mt = 0; mt < 4; mt++) {
                int r = wm * 64 + mt * 16 + lr;
                Ah[mt][0] = *(const float4*)&S[SAH + r * RSW + off];
                Ah[mt][1] = *(const float4*)&S[SAH + (r + 8) * RSW + off];
            }
            float4 Bh[8];
#pragma unroll
            for (int nt = 0; nt < 8; nt++) {
                int n = wn * 64 + nt * 8 + lr;
                Bh[nt] = *(const float4*)&S[SBH + n * RSW + off];
            }
            // pass 1: Ah * Bh
#pragma unroll
            for (int mt = 0; mt < 4; mt++)
#pragma unroll
                for (int nt = 0; nt < 8; nt++) {
                    mma8(acc[mt][nt],
                         __float_as_uint(Ah[mt][0].x), __float_as_uint(Ah[mt][1].x),
                         __float_as_uint(Ah[mt][0].y), __float_as_uint(Ah[mt][1].y),
                         __float_as_uint(Bh[nt].x), __float_as_uint(Bh[nt].y));
                    mma8(acc[mt][nt],
                         __float_as_uint(Ah[mt][0].z), __float_as_uint(Ah[mt][1].z),
                         __float_as_uint(Ah[mt][0].w), __float_as_uint(Ah[mt][1].w),
                         __float_as_uint(Bh[nt].z), __float_as_uint(Bh[nt].w));
                }
            // pass 2: Ah * Bl (Bl streamed)
#pragma unroll
            for (int nt = 0; nt < 8; nt++) {
                int n = wn * 64 + nt * 8 + lr;
                float4 Bl = *(const float4*)&S[SBL + n * RSW + off];
#pragma unroll
                for (int mt = 0; mt < 4; mt++) {
                    mma8(acc[mt][nt],
                         __float_as_uint(Ah[mt][0].x), __float_as_uint(Ah[mt][1].x),
                         __float_as_uint(Ah[mt][0].y), __float_as_uint(Ah[mt][1].y),
                         __float_as_uint(Bl.x), __float_as_uint(Bl.y));
                    mma8(acc[mt][nt],
                         __float_as_uint(Ah[mt][0].z), __float_as_uint(Ah[mt][1].z),
                         __float_as_uint(Ah[mt][0].w), __float_as_uint(Ah[mt][1].w),
                         __float_as_uint(Bl.z), __float_as_uint(Bl.w));
                }
            }
            // pass 3 (dense): Al * Bh (Al streamed)
            if (dense) {
#pragma unroll
                for (int mt = 0; mt < 4; mt++) {
                    int r = wm * 64 + mt * 16 + lr;
                    float4 Al0 = *(const float4*)&S[SAL + r * RSW + off];
                    float4 Al1 = *(const float4*)&S[SAL + (r + 8) * RSW + off];
#pragma unroll
                    for (int nt = 0; nt < 8; nt++) {
                        mma8(acc[mt][nt],
                             __float_as_uint(Al0.x), __float_as_uint(Al1.x),
                             __float_as_uint(Al0.y), __float_as_uint(Al1.y),
                             __float_as_uint(Bh[nt].x), __float_as_uint(Bh[nt].y));
                        mma8(acc[mt][nt],
                             __float_as_uint(Al0.z), __float_as_uint(Al1.z),
                             __float_as_uint(Al0.w), __float_as_uint(Al1.w),
                             __float_as_uint(Bh[nt].z), __float_as_uint(Bh[nt].w));
                    }
                }
            }
        }
    };

    issue_chunk(0, 0);
    CP_COMMIT();
    for (int ch = 0; ch < 12; ch++) {
        if (ch < 11) {
            issue_chunk(ch + 1, (ch + 1) & 1);
            CP_COMMIT();
            CP_WAIT1();
        } else {
            CP_WAIT0();
        }
        __syncthreads();
        compute(ch & 1);
        __syncthreads();
    }

    // ---------------- epilogue ----------------
    if (mode != 2) {
#pragma unroll
        for (int mt = 0; mt < 4; mt++) {
            int pa = p0 + wm * 64 + mt * 16 + lr;
            int pb = pa + 8;
#pragma unroll
            for (int nt = 0; nt < 8; nt++) {
                int ol = wn * 64 + nt * 8 + 2 * lc;
                float s0 = sm[SCL + ol], s1 = sm[SCL + ol + 1];
                float z0 = sm[SBS + ol], z1 = sm[SBS + ol + 1];
                float2 v0 = make_float2(acc[mt][nt][0] * s0 + z0, acc[mt][nt][1] * s1 + z1);
                float2 v1 = make_float2(acc[mt][nt][2] * s0 + z0, acc[mt][nt][3] * s1 + z1);
                if (mode == 0) {
                    int ra = (pa & 4095) >> 6, ca = pa & 63;
                    int rb = (pb & 4095) >> 6, cb = pb & 63;
                    *(float2*)(OUT + ((((size_t)img * PADW + ra + 1) * PADW + ca + 1) * CC) + n0 + ol) = v0;
                    *(float2*)(OUT + ((((size_t)img * PADW + rb + 1) * PADW + cb + 1) * CC) + n0 + ol) = v1;
                } else {
                    *(float2*)(OUT + ((size_t)img * NN + pa) * CC + n0 + ol) = v0;
                    *(float2*)(OUT + ((size_t)img * NN + pb) * CC + n0 + ol) = v1;
                }
            }
        }
    } else {
        // NCHW out: per-warp 64(n) x 64(m) transpose via smem (stage area reusable after syncs)
        float* T = sm + wid * (64 * 68);
#pragma unroll
        for (int mt = 0; mt < 4; mt++) {
            int mm = mt * 16 + lr;
#pragma unroll
            for (int nt = 0; nt < 8; nt++) {
                int nl = nt * 8 + 2 * lc;
                int ol = wn * 64 + nl;
                float s0 = sm[SCL + ol], s1 = sm[SCL + ol + 1];
                float z0 = sm[SBS + ol], z1 = sm[SBS + ol + 1];
                T[nl * 68 + mm]           = acc[mt][nt][0] * s0 + z0;
                T[(nl + 1) * 68 + mm]     = acc[mt][nt][1] * s1 + z1;
                T[nl * 68 + mm + 8]       = acc[mt][nt][2] * s0 + z0;
                T[(nl + 1) * 68 + mm + 8] = acc[mt][nt][3] * s1 + z1;
            }
        }
        __syncwarp();
#pragma unroll
        for (int ol = 0; ol < 64; ol++) {
            int o = n0 + wn * 64 + ol;
            float2 v = *(float2*)&T[ol * 68 + lane * 2];
            *(float2*)(OUT + ((size_t)img * CC + o) * NN + p0 + wm * 64 + lane * 2) = v;
        }
    }
}

// ---------------- weight presplit (hi/lo tf32, k-permuted) ----------------
__global__ void presplit_kernel(const float* __restrict__ W,
                                float* __restrict__ WHo, float* __restrict__ WLo) {
    int idx = blockIdx.x * 256 + threadIdx.x;
    if (idx >= CC * CC) return;
    int o = idx / CC, c = idx % CC;
    float v = W[idx];
    float h = tf32r(v);
    WHo[(size_t)o * CC + permc(c)] = h;
    WLo[(size_t)o * CC + permc(c)] = tf32r(v - h);
}

// ---------------- ALIF first (NCHW in -> NHWC permuted spikes) ----------------
__global__ void alif_first_kernel(const float* __restrict__ in, float* __restrict__ out,
                                  const float* __restrict__ vth_ptr) {
    __shared__ float s[32][33];
    int tx = threadIdx.x, ty = threadIdx.y;
    int n0 = blockIdx.x * 32;
    int c0 = blockIdx.y * 32;
    int b = blockIdx.z;
    float vth = vth_ptr[0];
    int cp = c0 + permc(tx);
    float v[4] = {0.f, 0.f, 0.f, 0.f};
#pragma unroll
    for (int t = 0; t < TT; t++) {
#pragma unroll
        for (int k = 0; k < 4; k++) {
            int c = c0 + ty + 8 * k;
            float xv = in[(((size_t)(t * BB + b) * CC + c) * NN) + n0 + tx];
            v[k] = v[k] + (xv - v[k]) * 0.5f;
            s[ty + 8 * k][tx] = (v[k] - vth >= 0.0f) ? 1.0f : 0.0f;
        }
        __syncthreads();
#pragma unroll
        for (int k = 0; k < 4; k++) {
            int n = n0 + ty + 8 * k;
            out[((size_t)(t * BB + b) * NN + n) * CC + cp] = s[tx][ty + 8 * k];
        }
        __syncthreads();
    }
}

// ---------------- ALIF generic (perm flag permutes output channel slots) ----------------
__global__ void alif_kernel(const float* __restrict__ in, float* __restrict__ out,
                            const float* __restrict__ vth_ptr, int vidx, int perm) {
    int j = blockIdx.x * blockDim.x + threadIdx.x;
    if (j >= BCN) return;
    float vth = vth_ptr[vidx];
    int c = j % CC;
    size_t jo = perm ? (size_t)(j - c + permc(c)) : (size_t)j;
    float v = 0.0f;
#pragma unroll
    for (int t = 0; t < TT; t++) {
        float x = in[(size_t)j + (size_t)t * BCN];
        v = v + (x - v) * 0.5f;
        out[jo + (size_t)t * BCN] = (v - vth >= 0.0f) ? 1.0f : 0.0f;
    }
}

// ---------------- pad border fill (NHWC natural) ----------------
__global__ void padfill_kernel(float* __restrict__ pad,
                               const float* __restrict__ bw, const float* __restrict__ bb,
                               const float* __restrict__ bm, const float* __restrict__ bv) {
    int t = blockIdx.x;
    int img = blockIdx.y;
    int c = threadIdx.x;
    float inv = bw[c] * rsqrtf(bv[c] + EPS);
    float pv = bb[c] - bm[c] * inv;
    int r, cl;
    if      (t < 66)  { r = 0;           cl = t;        }
    else if (t < 132) { r = 65;          cl = t - 66;   }
    else if (t < 196) { r = t - 132 + 1; cl = 0;        }
    else              { r = t - 196 + 1; cl = 65;       }
    pad[(((size_t)img * PADW + r) * PADW + cl) * CC + c] = pv;
}

// ---------------- depthwise 3x3 (NHWC) -> split hi/lo, k-permuted ----------------
__global__ void dwconv_kernel(const float* __restrict__ pad, const float* __restrict__ w9,
                              float* __restrict__ outH, float* __restrict__ outL) {
    int c = threadIdx.x;
    int p = blockIdx.x;
    int img = blockIdx.y;
    int r = p >> 6, cl = p & 63;
    const float* base = pad + (((size_t)img * PADW + r) * PADW + cl) * CC + c;
    float wr[9];
#pragma unroll
    for (int k = 0; k < 9; k++) wr[k] = __ldg(w9 + c * 9 + k);
    float sacc = 0.0f;
#pragma unroll
    for (int i = 0; i < 3; i++)
#pragma unroll
        for (int j = 0; j < 3; j++)
            sacc += wr[i * 3 + j] * base[(size_t)(i * PADW + j) * CC];
    int pc = permc(c);
    float h = tf32r(sacc);
    outH[((size_t)img * NN + p) * CC + pc] = h;
    outL[((size_t)img * NN + p) * CC + pc] = tf32r(sacc - h);
}

// ---------------- kv partial (NHWC): kvp[seg][tbh][d][e] ----------------
__global__ void kv_kernel(const float* __restrict__ K, const float* __restrict__ V,
                          float* __restrict__ KVP) {
    int seg = blockIdx.x;
    int tbh = blockIdx.y;
    int tb = tbh / HEADS, h = tbh % HEADS;
    __shared__ float Ks[64][65];
    __shared__ float Vs[64][65];
    int tx = threadIdx.x;
    int td = tx >> 4, te = tx & 15;
    const float* Kb = K + (size_t)tb * NN * CC + h * DH;
    const float* Vb = V + (size_t)tb * NN * CC + h * DH;
    float acc[4][4];
#pragma unroll
    for (int i = 0; i < 4; i++)
#pragma unroll
        for (int j = 0; j < 4; j++) acc[i][j] = 0.0f;

    for (int n0 = seg * 1024; n0 < (seg + 1) * 1024; n0 += 64) {
#pragma unroll
        for (int u = 0; u < 16; u++) {
            int e = tx + u * 256;
            int n = e >> 6, d = e & 63;
            Ks[n][d] = Kb[(size_t)(n0 + n) * CC + d];
            Vs[n][d] = Vb[(size_t)(n0 + n) * CC + d];
        }
        __syncthreads();
#pragma unroll
        for (int n = 0; n < 64; n++) {
            float a0 = Ks[n][td * 4 + 0], a1 = Ks[n][td * 4 + 1];
            float a2 = Ks[n][td * 4 + 2], a3 = Ks[n][td * 4 + 3];
            float b0 = Vs[n][te * 4 + 0], b1 = Vs[n][te * 4 + 1];
            float b2 = Vs[n][te * 4 + 2], b3 = Vs[n][te * 4 + 3];
            acc[0][0] += a0 * b0; acc[0][1] += a0 * b1; acc[0][2] += a0 * b2; acc[0][3] += a0 * b3;
            acc[1][0] += a1 * b0; acc[1][1] += a1 * b1; acc[1][2] += a1 * b2; acc[1][3] += a1 * b3;
            acc[2][0] += a2 * b0; acc[2][1] += a2 * b1; acc[2][2] += a2 * b2; acc[2][3] += a2 * b3;
            acc[3][0] += a3 * b0; acc[3][1] += a3 * b1; acc[3][2] += a3 * b2; acc[3][3] += a3 * b3;
        }
        __syncthreads();
    }
#pragma unroll
    for (int i = 0; i < 4; i++)
#pragma unroll
        for (int j = 0; j < 4; j++)
            KVP[((size_t)seg * (TT * BB * HEADS) + tbh) * (DH * DH) + (td * 4 + i) * DH + te * 4 + j] =
                acc[i][j];
}

__global__ void kvred_kernel(const float* __restrict__ KVP, float* __restrict__ KV) {
    int idx = blockIdx.x * blockDim.x + threadIdx.x;
    const int tot = TT * BB * HEADS * DH * DH;
    if (idx >= tot) return;
    float s = 0.f;
#pragma unroll
    for (int g = 0; g < 4; g++) s += KVP[(size_t)g * tot + idx];
    KV[idx] = s;
}

// ---------------- av (NHWC): A[tb][n][h*64+e] = sum_d Q[tb][n][h*64+d]*KV[tbh][d][e] ----------------
__global__ void av_kernel(const float* __restrict__ Q, const float* __restrict__ KV,
                          float* __restrict__ A) {
    int nt = blockIdx.x;
    int tbh = blockIdx.y;
    int tb = tbh / HEADS, h = tbh % HEADS;
    __shared__ float kvs[64][65];
    __shared__ float Qs[64][65];
    int tx = threadIdx.x;
    int tn = tx >> 4, te = tx & 15;
    int n0 = nt * 64;
    const float* Qb = Q + (size_t)tb * NN * CC + h * DH;
#pragma unroll
    for (int u = 0; u < 16; u++) {
        int e = tx + u * 256;
        int r = e >> 6, x = e & 63;
        kvs[r][x] = KV[(size_t)tbh * DH * DH + r * DH + x];
        Qs[r][x] = Qb[(size_t)(n0 + r) * CC + x];
    }
    __syncthreads();
    float acc[4][4];
#pragma unroll
    for (int i = 0; i < 4; i++)
#pragma unroll
        for (int j = 0; j < 4; j++) acc[i][j] = 0.0f;
#pragma unroll
    for (int d = 0; d < 64; d++) {
        float a0 = Qs[tn * 4 + 0][d], a1 = Qs[tn * 4 + 1][d];
        float a2 = Qs[tn * 4 + 2][d], a3 = Qs[tn * 4 + 3][d];
        float b0 = kvs[d][te * 4 + 0], b1 = kvs[d][te * 4 + 1];
        float b2 = kvs[d][te * 4 + 2], b3 = kvs[d][te * 4 + 3];
        acc[0][0] += a0 * b0; acc[0][1] += a0 * b1; acc[0][2] += a0 * b2; acc[0][3] += a0 * b3;
        acc[1][0] += a1 * b0; acc[1][1] += a1 * b1; acc[1][2] += a1 * b2; acc[1][3] += a1 * b3;
        acc[2][0] += a2 * b0; acc[2][1] += a2 * b1; acc[2][2] += a2 * b2; acc[2][3] += a2 * b3;
        acc[3][0] += a3 * b0; acc[3][1] += a3 * b1; acc[3][2] += a3 * b2; acc[3][3] += a3 * b3;
    }
#pragma unroll
    for (int i = 0; i < 4; i++) {
        int n = n0 + tn * 4 + i;
        float4 w4;
        w4.x = acc[i][0]; w4.y = acc[i][1]; w4.z = acc[i][2]; w4.w = acc[i][3];
        *(float4*)(A + ((size_t)tb * NN + n) * CC + h * DH + te * 4) = w4;
    }
}

// ---------------- host orchestration ----------------
static void run_branch(const float* inSpk, int i, float* out, int out_mode,
                       const float* w1, const float* dw, const float* pw,
                       const float* b1w, const float* b1b, const float* b1m, const float* b1v,
                       const float* b2w, const float* b2b, const float* b2m, const float* b2v,
                       const float* b3w, const float* b3b, const float* b3m, const float* b3v,
                       float* PAD, float* DWH, float* DWL, float* WH, float* WL) {
    presplit_kernel<<<(CC * CC + 255) / 256, 256>>>(w1 + (size_t)i * CC * CC, WH, WL);
    padfill_kernel<<<dim3(260, IMG), CC>>>(PAD, b1w + i * CC, b1b + i * CC, b1m + i * CC, b1v + i * CC);
    conv_mma_kernel<<<dim3(16, 3, IMG), 256, SMEM_BYTES>>>(inSpk, inSpk, WH, WL, PAD,
        b1w + i * CC, b1b + i * CC, b1m + i * CC, b1v + i * CC,
        nullptr, nullptr, nullptr, nullptr, 0);
    dwconv_kernel<<<dim3(NN, IMG), CC>>>(PAD, dw + (size_t)i * CC * 9, DWH, DWL);
    presplit_kernel<<<(CC * CC + 255) / 256, 256>>>(pw + (size_t)i * CC * CC, WH, WL);
    conv_mma_kernel<<<dim3(16, 3, IMG), 256, SMEM_BYTES>>>(DWH, DWL, WH, WL, out,
        b2w + i * CC, b2b + i * CC, b2m + i * CC, b2v + i * CC,
        b3w + i * CC, b3b + i * CC, b3m + i * CC, b3v + i * CC, out_mode);
}

extern "C" void kernel_launch(void* const* d_in, const int* in_sizes, int n_in,
                              void* d_out, int out_size) {
    const float* x   = (const float*)d_in[0];
    const float* w1  = (const float*)d_in[1];
    const float* dw  = (const float*)d_in[2];
    const float* pw  = (const float*)d_in[3];
    const float* b1w = (const float*)d_in[4];
    const float* b1b = (const float*)d_in[5];
    const float* b1m = (const float*)d_in[6];
    const float* b1v = (const float*)d_in[7];
    const float* b2w = (const float*)d_in[8];
    const float* b2b = (const float*)d_in[9];
    const float* b2m = (const float*)d_in[10];
    const float* b2v = (const float*)d_in[11];
    const float* b3w = (const float*)d_in[12];
    const float* b3b = (const float*)d_in[13];
    const float* b3m = (const float*)d_in[14];
    const float* b3v = (const float*)d_in[15];
    const float* vth = (const float*)d_in[16];
    float* out = (float*)d_out;

    cudaFuncSetAttribute(conv_mma_kernel, cudaFuncAttributeMaxDynamicSharedMemorySize, SMEM_BYTES);

    float *XS, *PAD, *DWH, *DWL, *BR, *QS, *KS, *VS, *AS, *WH, *WL, *KVP, *KV;
    cudaGetSymbolAddress((void**)&XS,  g_XS);
    cudaGetSymbolAddress((void**)&PAD, g_PAD);
    cudaGetSymbolAddress((void**)&DWH, g_DWH);
    cudaGetSymbolAddress((void**)&DWL, g_DWL);
    cudaGetSymbolAddress((void**)&BR,  g_BR);
    cudaGetSymbolAddress((void**)&QS,  g_QS);
    cudaGetSymbolAddress((void**)&KS,  g_KS);
    cudaGetSymbolAddress((void**)&VS,  g_VS);
    cudaGetSymbolAddress((void**)&AS,  g_AS);
    cudaGetSymbolAddress((void**)&WH,  g_WH);
    cudaGetSymbolAddress((void**)&WL,  g_WL);
    cudaGetSymbolAddress((void**)&KVP, g_KVP);
    cudaGetSymbolAddress((void**)&KV,  g_KV);

    const int athreads = 256;
    const int ablocks = (BCN + athreads - 1) / athreads;

    // 1) alif on x, NCHW -> NHWC (k-permuted channel slots; XS only feeds conv1)
    alif_first_kernel<<<dim3(NN / 32, CC / 32, BB), dim3(32, 8)>>>(x, XS, vth);

    // 2) q/k/v branches
    float* sp[3] = {QS, KS, VS};
    for (int i = 0; i < 3; i++) {
        run_branch(XS, i, BR, 1, w1, dw, pw,
                   b1w, b1b, b1m, b1v, b2w, b2b, b2m, b2v, b3w, b3b, b3m, b3v,
                   PAD, DWH, DWL, WH, WL);
        alif_kernel<<<ablocks, athreads>>>(BR, sp[i], vth, 1 + i, 0);
    }

    // 3) linear attention (exact fp32, natural channels)
    kv_kernel<<<dim3(4, TT * BB * HEADS), 256>>>(KS, VS, KVP);
    kvred_kernel<<<(TT * BB * HEADS * DH * DH + 255) / 256, 256>>>(KVP, KV);
    av_kernel<<<dim3(64, TT * BB * HEADS), 256>>>(QS, KV, BR);
    alif_kernel<<<ablocks, athreads>>>(BR, AS, vth, 4, 1);   // AS feeds conv1 -> permuted

    // 4) final branch -> d_out (NCHW)
    run_branch(AS, 3, out, 2, w1, dw, pw,
               b1w, b1b, b1m, b1v, b2w, b2b, b2m, b2v, b3w, b3b, b3m, b3v,
               PAD, DWH, DWL, WH, WL);
}

// round 7
// speedup vs baseline: 1.2461x; 1.0051x over previous
#include <cuda_runtime.h>
#include <cstdint>
#include <cstddef>

#define TT 4
#define BB 4
#define CC 384
#define NN 4096
#define IMG 16
#define BCN (BB*CC*NN)
#define HEADS 6
#define DH 64
#define PADW 66
#define EPS 1e-5f

// ---------------- scratch (static device globals) ----------------
__device__ __align__(256) float g_XS [IMG*NN*CC];         // spikes of x (NHWC, K-permuted chans)
__device__ __align__(256) float g_PAD[IMG*PADW*PADW*CC];  // bn1+pad (NHWC, natural chans)
__device__ __align__(256) float g_DWH[IMG*NN*CC];         // depthwise out hi (permuted)
__device__ __align__(256) float g_DWL[IMG*NN*CC];         // depthwise out lo (permuted)
__device__ __align__(256) float g_BR [IMG*NN*CC];         // branch out / attention a (natural)
__device__ __align__(256) float g_QS [IMG*NN*CC];
__device__ __align__(256) float g_KS [IMG*NN*CC];
__device__ __align__(256) float g_VS [IMG*NN*CC];
__device__ __align__(256) float g_AS [IMG*NN*CC];         // spikes of attention (permuted)
__device__ __align__(256) float g_WH [CC*CC];             // presplit weights hi (permuted k)
__device__ __align__(256) float g_WL [CC*CC];
__device__ __align__(256) float g_KVP[4*TT*BB*HEADS*DH*DH];
__device__ __align__(256) float g_KV [TT*BB*HEADS*DH*DH];

__device__ __forceinline__ float tf32r(float x) {
    uint32_t u;
    asm("cvt.rna.tf32.f32 %0, %1;" : "=r"(u) : "f"(x));
    return __uint_as_float(u);
}
__device__ __forceinline__ void mma8(float* c, uint32_t a0, uint32_t a1, uint32_t a2, uint32_t a3,
                                     uint32_t b0, uint32_t b1) {
    asm volatile("mma.sync.aligned.m16n8k8.row.col.f32.tf32.tf32.f32 "
                 "{%0,%1,%2,%3}, {%4,%5,%6,%7}, {%8,%9}, {%0,%1,%2,%3};"
                 : "+f"(c[0]), "+f"(c[1]), "+f"(c[2]), "+f"(c[3])
                 : "r"(a0), "r"(a1), "r"(a2), "r"(a3), "r"(b0), "r"(b1));
}
__device__ __forceinline__ void cp16(uint32_t dst, const void* src) {
    asm volatile("cp.async.cg.shared.global [%0], [%1], 16;" :: "r"(dst), "l"(src));
}
#define CP_COMMIT() asm volatile("cp.async.commit_group;" ::: "memory")
#define CP_WAIT0()  asm volatile("cp.async.wait_group 0;" ::: "memory")
#define CP_WAIT1()  asm volatile("cp.async.wait_group 1;" ::: "memory")
__device__ __forceinline__ uint32_t s2u(const void* p) {
    uint32_t a;
    asm("{ .reg .u64 t; cvta.to.shared.u64 t, %1; cvt.u32.u64 %0, t; }" : "=r"(a) : "l"(p));
    return a;
}
// K permutation within each 32-chunk: k = kk*8+j -> 8*(j&3) + 2*kk + (j>>2)
__device__ __forceinline__ int permc(int c) {
    int ch = c & ~31, r = c & 31, kk = r >> 3, j = r & 7;
    return ch + 8 * (j & 3) + 2 * kk + (j >> 2);
}

// ---- smem layout (floats): 2 stages of [A_H 256x36 | A_L 256x36 | B_H 128x36 | B_L 128x36]
#define RSW 36
#define SAH 0
#define SAL (256*RSW)            // 9216
#define SBH (2*256*RSW)          // 18432
#define SBL (SBH + 128*RSW)      // 23040
#define STAGE (SBL + 128*RSW)    // 27648 floats = 110592 B
#define SCL (2*STAGE)            // 55296
#define SBS (SCL + 128)
#define SMEM_FLOATS (SBS + 128)  // 55552
#define SMEM_BYTES (SMEM_FLOATS*4)   // 222208

// ---------------- conv1x1: cp.async double-buffered split-tf32 mma, 512 thr ----------------
// D[p][o] = sum_c A[p][c]*W[o][c]; CTA tile 256(M) x 128(N), K=384 in 12 chunks of 32.
// 16 warps in 4(m) x 4(n) grid; warp tile 64x32.
// mode 0: A binary (AH only, 2 passes), bn1 epilogue -> PAD interior (NHWC)
// mode 1: A split hi/lo (3 passes), bn2*bn3 epilogue -> NHWC
// mode 2: like 1 but writes NCHW (d_out)
__global__ void __launch_bounds__(512, 1)
conv_mma_kernel(const float* __restrict__ AH, const float* __restrict__ AL,
                const float* __restrict__ WH, const float* __restrict__ WL,
                float* __restrict__ OUT,
                const float* __restrict__ wA, const float* __restrict__ bA,
                const float* __restrict__ mA, const float* __restrict__ vA,
                const float* __restrict__ wB, const float* __restrict__ bB2,
                const float* __restrict__ mB, const float* __restrict__ vB,
                int mode) {
    extern __shared__ float sm[];
    const int tx = threadIdx.x;
    const int wid = tx >> 5, lane = tx & 31;
    const int lr = lane >> 2, lc = lane & 3;
    const int wm = wid >> 2, wn = wid & 3;          // 4(m) x 4(n); warp tile 64x32
    const int img = blockIdx.z;
    const int p0 = blockIdx.x * 256;
    const int n0 = blockIdx.y * 128;
    const bool dense = (mode != 0);
    const size_t arow0 = (size_t)img * NN + p0;
    const uint32_t smb = s2u(sm);

    if (tx < 128) {
        int o = n0 + tx;
        float s, bias;
        if (mode == 0) {
            float inv = wA[o] * rsqrtf(vA[o] + EPS);
            s = inv; bias = bA[o] - mA[o] * inv;
        } else {
            float s2 = wA[o] * rsqrtf(vA[o] + EPS);
            float t2 = bA[o] - mA[o] * s2;
            float s3 = wB[o] * rsqrtf(vB[o] + EPS);
            float t3 = bB2[o] - mB[o] * s3;
            s = s2 * s3; bias = t2 * s3 + t3;
        }
        sm[SCL + tx] = s;
        sm[SBS + tx] = bias;
    }

    auto issue_chunk = [&](int ch, int st) {
        int c0 = ch * 32;
        uint32_t stb = smb + (uint32_t)st * (STAGE * 4);
#pragma unroll
        for (int it = 0; it < 4; it++) {
            int u = tx + it * 512;
            int row = u >> 3, q = u & 7;
            cp16(stb + SAH * 4 + row * 144 + q * 16,
                 AH + (arow0 + row) * CC + c0 + q * 4);
        }
        if (dense) {
#pragma unroll
            for (int it = 0; it < 4; it++) {
                int u = tx + it * 512;
                int row = u >> 3, q = u & 7;
                cp16(stb + SAL * 4 + row * 144 + q * 16,
                     AL + (arow0 + row) * CC + c0 + q * 4);
            }
        }
#pragma unroll
        for (int it = 0; it < 2; it++) {
            int u = tx + it * 512;
            int row = u >> 3, q = u & 7;
            cp16(stb + SBH * 4 + row * 144 + q * 16,
                 WH + (size_t)(n0 + row) * CC + c0 + q * 4);
            cp16(stb + SBL * 4 + row * 144 + q * 16,
                 WL + (size_t)(n0 + row) * CC + c0 + q * 4);
        }
    };

    float acc[4][4][4];
#pragma unroll
    for (int a = 0; a < 4; a++)
#pragma unroll
        for (int b = 0; b < 4; b++)
#pragma unroll
            for (int c = 0; c < 4; c++) acc[a][b][c] = 0.0f;

    auto compute = [&](int st) {
        const float* S = sm + st * STAGE;
#pragma unroll
        for (int kk2 = 0; kk2 < 2; kk2++) {
            int off = 8 * lc + 4 * kk2;
            float4 Ah[4][2];
#pragma unroll
            for (int mt = 0; mt < 4; mt++) {
                int r = wm * 64 + mt * 16 + lr;
                Ah[mt][0] = *(const float4*)&S[SAH + r * RSW + off];
                Ah[mt][1] = *(const float4*)&S[SAH + (r + 8) * RSW + off];
            }
            float4 Bh[4];
#pragma unroll
            for (int nt = 0; nt < 4; nt++) {
                int n = wn * 32 + nt * 8 + lr;
                Bh[nt] = *(const float4*)&S[SBH + n * RSW + off];
            }
            // pass 1: Ah * Bh
#pragma unroll
            for (int mt = 0; mt < 4; mt++)
#pragma unroll
                for (int nt = 0; nt < 4; nt++) {
                    mma8(acc[mt][nt],
                         __float_as_uint(Ah[mt][0].x), __float_as_uint(Ah[mt][1].x),
                         __float_as_uint(Ah[mt][0].y), __float_as_uint(Ah[mt][1].y),
                         __float_as_uint(Bh[nt].x), __float_as_uint(Bh[nt].y));
                    mma8(acc[mt][nt],
                         __float_as_uint(Ah[mt][0].z), __float_as_uint(Ah[mt][1].z),
                         __float_as_uint(Ah[mt][0].w), __float_as_uint(Ah[mt][1].w),
                         __float_as_uint(Bh[nt].z), __float_as_uint(Bh[nt].w));
                }
            // pass 2: Ah * Bl (Bl streamed)
#pragma unroll
            for (int nt = 0; nt < 4; nt++) {
                int n = wn * 32 + nt * 8 + lr;
                float4 Bl = *(const float4*)&S[SBL + n * RSW + off];
#pragma unroll
                for (int mt = 0; mt < 4; mt++) {
                    mma8(acc[mt][nt],
                         __float_as_uint(Ah[mt][0].x), __float_as_uint(Ah[mt][1].x),
                         __float_as_uint(Ah[mt][0].y), __float_as_uint(Ah[mt][1].y),
                         __float_as_uint(Bl.x), __float_as_uint(Bl.y));
                    mma8(acc[mt][nt],
                         __float_as_uint(Ah[mt][0].z), __float_as_uint(Ah[mt][1].z),
                         __float_as_uint(Ah[mt][0].w), __float_as_uint(Ah[mt][1].w),
                         __float_as_uint(Bl.z), __float_as_uint(Bl.w));
                }
            }
            // pass 3 (dense): Al * Bh (Al streamed)
            if (dense) {
#pragma unroll
                for (int mt = 0; mt < 4; mt++) {
                    int r = wm * 64 + mt * 16 + lr;
                    float4 Al0 = *(const float4*)&S[SAL + r * RSW + off];
                    float4 Al1 = *(const float4*)&S[SAL + (r + 8) * RSW + off];
#pragma unroll
                    for (int nt = 0; nt < 4; nt++) {
                        mma8(acc[mt][nt],
                             __float_as_uint(Al0.x), __float_as_uint(Al1.x),
                             __float_as_uint(Al0.y), __float_as_uint(Al1.y),
                             __float_as_uint(Bh[nt].x), __float_as_uint(Bh[nt].y));
                        mma8(acc[mt][nt],
                             __float_as_uint(Al0.z), __float_as_uint(Al1.z),
                             __float_as_uint(Al0.w), __float_as_uint(Al1.w),
                             __float_as_uint(Bh[nt].z), __float_as_uint(Bh[nt].w));
                    }
                }
            }
        }
    };

    issue_chunk(0, 0);
    CP_COMMIT();
    for (int ch = 0; ch < 12; ch++) {
        if (ch < 11) {
            issue_chunk(ch + 1, (ch + 1) & 1);
            CP_COMMIT();
            CP_WAIT1();
        } else {
            CP_WAIT0();
        }
        __syncthreads();
        compute(ch & 1);
        __syncthreads();
    }

    // ---------------- epilogue ----------------
    if (mode != 2) {
#pragma unroll
        for (int mt = 0; mt < 4; mt++) {
            int pa = p0 + wm * 64 + mt * 16 + lr;
            int pb = pa + 8;
#pragma unroll
            for (int nt = 0; nt < 4; nt++) {
                int ol = wn * 32 + nt * 8 + 2 * lc;
                float s0 = sm[SCL + ol], s1 = sm[SCL + ol + 1];
                float z0 = sm[SBS + ol], z1 = sm[SBS + ol + 1];
                float2 v0 = make_float2(acc[mt][nt][0] * s0 + z0, acc[mt][nt][1] * s1 + z1);
                float2 v1 = make_float2(acc[mt][nt][2] * s0 + z0, acc[mt][nt][3] * s1 + z1);
                if (mode == 0) {
                    int ra = (pa & 4095) >> 6, ca = pa & 63;
                    int rb = (pb & 4095) >> 6, cb = pb & 63;
                    *(float2*)(OUT + ((((size_t)img * PADW + ra + 1) * PADW + ca + 1) * CC) + n0 + ol) = v0;
                    *(float2*)(OUT + ((((size_t)img * PADW + rb + 1) * PADW + cb + 1) * CC) + n0 + ol) = v1;
                } else {
                    *(float2*)(OUT + ((size_t)img * NN + pa) * CC + n0 + ol) = v0;
                    *(float2*)(OUT + ((size_t)img * NN + pb) * CC + n0 + ol) = v1;
                }
            }
        }
    } else {
        // NCHW out: per-warp 32(n) x 64(m) transpose via smem (stage area reused)
        float* T = sm + wid * (32 * 68);
#pragma unroll
        for (int mt = 0; mt < 4; mt++) {
            int mm = mt * 16 + lr;
#pragma unroll
            for (int nt = 0; nt < 4; nt++) {
                int nl = nt * 8 + 2 * lc;
                int ol = wn * 32 + nl;
                float s0 = sm[SCL + ol], s1 = sm[SCL + ol + 1];
                float z0 = sm[SBS + ol], z1 = sm[SBS + ol + 1];
                T[nl * 68 + mm]           = acc[mt][nt][0] * s0 + z0;
                T[(nl + 1) * 68 + mm]     = acc[mt][nt][1] * s1 + z1;
                T[nl * 68 + mm + 8]       = acc[mt][nt][2] * s0 + z0;
                T[(nl + 1) * 68 + mm + 8] = acc[mt][nt][3] * s1 + z1;
            }
        }
        __syncwarp();
#pragma unroll
        for (int ol = 0; ol < 32; ol++) {
            int o = n0 + wn * 32 + ol;
            float2 v = *(float2*)&T[ol * 68 + lane * 2];
            *(float2*)(OUT + ((size_t)img * CC + o) * NN + p0 + wm * 64 + lane * 2) = v;
        }
    }
}

// ---------------- weight presplit (hi/lo tf32, k-permuted) ----------------
__global__ void presplit_kernel(const float* __restrict__ W,
                                float* __restrict__ WHo, float* __restrict__ WLo) {
    int idx = blockIdx.x * 256 + threadIdx.x;
    if (idx >= CC * CC) return;
    int o = idx / CC, c = idx % CC;
    float v = W[idx];
    float h = tf32r(v);
    WHo[(size_t)o * CC + permc(c)] = h;
    WLo[(size_t)o * CC + permc(c)] = tf32r(v - h);
}

// ---------------- ALIF first (NCHW in -> NHWC permuted spikes) ----------------
__global__ void alif_first_kernel(const float* __restrict__ in, float* __restrict__ out,
                                  const float* __restrict__ vth_ptr) {
    __shared__ float s[32][33];
    int tx = threadIdx.x, ty = threadIdx.y;
    int n0 = blockIdx.x * 32;
    int c0 = blockIdx.y * 32;
    int b = blockIdx.z;
    float vth = vth_ptr[0];
    int cp = c0 + permc(tx);
    float v[4] = {0.f, 0.f, 0.f, 0.f};
#pragma unroll
    for (int t = 0; t < TT; t++) {
#pragma unroll
        for (int k = 0; k < 4; k++) {
            int c = c0 + ty + 8 * k;
            float xv = in[(((size_t)(t * BB + b) * CC + c) * NN) + n0 + tx];
            v[k] = v[k] + (xv - v[k]) * 0.5f;
            s[ty + 8 * k][tx] = (v[k] - vth >= 0.0f) ? 1.0f : 0.0f;
        }
        __syncthreads();
#pragma unroll
        for (int k = 0; k < 4; k++) {
            int n = n0 + ty + 8 * k;
            out[((size_t)(t * BB + b) * NN + n) * CC + cp] = s[tx][ty + 8 * k];
        }
        __syncthreads();
    }
}

// ---------------- ALIF generic (perm flag permutes output channel slots) ----------------
__global__ void alif_kernel(const float* __restrict__ in, float* __restrict__ out,
                            const float* __restrict__ vth_ptr, int vidx, int perm) {
    int j = blockIdx.x * blockDim.x + threadIdx.x;
    if (j >= BCN) return;
    float vth = vth_ptr[vidx];
    int c = j % CC;
    size_t jo = perm ? (size_t)(j - c + permc(c)) : (size_t)j;
    float v = 0.0f;
#pragma unroll
    for (int t = 0; t < TT; t++) {
        float x = in[(size_t)j + (size_t)t * BCN];
        v = v + (x - v) * 0.5f;
        out[jo + (size_t)t * BCN] = (v - vth >= 0.0f) ? 1.0f : 0.0f;
    }
}

// ---------------- pad border fill (NHWC natural) ----------------
__global__ void padfill_kernel(float* __restrict__ pad,
                               const float* __restrict__ bw, const float* __restrict__ bb,
                               const float* __restrict__ bm, const float* __restrict__ bv) {
    int t = blockIdx.x;
    int img = blockIdx.y;
    int c = threadIdx.x;
    float inv = bw[c] * rsqrtf(bv[c] + EPS);
    float pv = bb[c] - bm[c] * inv;
    int r, cl;
    if      (t < 66)  { r = 0;           cl = t;        }
    else if (t < 132) { r = 65;          cl = t - 66;   }
    else if (t < 196) { r = t - 132 + 1; cl = 0;        }
    else              { r = t - 196 + 1; cl = 65;       }
    pad[(((size_t)img * PADW + r) * PADW + cl) * CC + c] = pv;
}

// ---------------- depthwise 3x3 (NHWC) -> split hi/lo, k-permuted ----------------
__global__ void dwconv_kernel(const float* __restrict__ pad, const float* __restrict__ w9,
                              float* __restrict__ outH, float* __restrict__ outL) {
    int c = threadIdx.x;
    int p = blockIdx.x;
    int img = blockIdx.y;
    int r = p >> 6, cl = p & 63;
    const float* base = pad + (((size_t)img * PADW + r) * PADW + cl) * CC + c;
    float wr[9];
#pragma unroll
    for (int k = 0; k < 9; k++) wr[k] = __ldg(w9 + c * 9 + k);
    float sacc = 0.0f;
#pragma unroll
    for (int i = 0; i < 3; i++)
#pragma unroll
        for (int j = 0; j < 3; j++)
            sacc += wr[i * 3 + j] * base[(size_t)(i * PADW + j) * CC];
    int pc = permc(c);
    float h = tf32r(sacc);
    outH[((size_t)img * NN + p) * CC + pc] = h;
    outL[((size_t)img * NN + p) * CC + pc] = tf32r(sacc - h);
}

// ---------------- kv partial (NHWC): kvp[seg][tbh][d][e] ----------------
__global__ void kv_kernel(const float* __restrict__ K, const float* __restrict__ V,
                          float* __restrict__ KVP) {
    int seg = blockIdx.x;
    int tbh = blockIdx.y;
    int tb = tbh / HEADS, h = tbh % HEADS;
    __shared__ float Ks[64][65];
    __shared__ float Vs[64][65];
    int tx = threadIdx.x;
    int td = tx >> 4, te = tx & 15;
    const float* Kb = K + (size_t)tb * NN * CC + h * DH;
    const float* Vb = V + (size_t)tb * NN * CC + h * DH;
    float acc[4][4];
#pragma unroll
    for (int i = 0; i < 4; i++)
#pragma unroll
        for (int j = 0; j < 4; j++) acc[i][j] = 0.0f;

    for (int n0 = seg * 1024; n0 < (seg + 1) * 1024; n0 += 64) {
#pragma unroll
        for (int u = 0; u < 16; u++) {
            int e = tx + u * 256;
            int n = e >> 6, d = e & 63;
            Ks[n][d] = Kb[(size_t)(n0 + n) * CC + d];
            Vs[n][d] = Vb[(size_t)(n0 + n) * CC + d];
        }
        __syncthreads();
#pragma unroll
        for (int n = 0; n < 64; n++) {
            float a0 = Ks[n][td * 4 + 0], a1 = Ks[n][td * 4 + 1];
            float a2 = Ks[n][td * 4 + 2], a3 = Ks[n][td * 4 + 3];
            float b0 = Vs[n][te * 4 + 0], b1 = Vs[n][te * 4 + 1];
            float b2 = Vs[n][te * 4 + 2], b3 = Vs[n][te * 4 + 3];
            acc[0][0] += a0 * b0; acc[0][1] += a0 * b1; acc[0][2] += a0 * b2; acc[0][3] += a0 * b3;
            acc[1][0] += a1 * b0; acc[1][1] += a1 * b1; acc[1][2] += a1 * b2; acc[1][3] += a1 * b3;
            acc[2][0] += a2 * b0; acc[2][1] += a2 * b1; acc[2][2] += a2 * b2; acc[2][3] += a2 * b3;
            acc[3][0] += a3 * b0; acc[3][1] += a3 * b1; acc[3][2] += a3 * b2; acc[3][3] += a3 * b3;
        }
        __syncthreads();
    }
#pragma unroll
    for (int i = 0; i < 4; i++)
#pragma unroll
        for (int j = 0; j < 4; j++)
            KVP[((size_t)seg * (TT * BB * HEADS) + tbh) * (DH * DH) + (td * 4 + i) * DH + te * 4 + j] =
                acc[i][j];
}

__global__ void kvred_kernel(const float* __restrict__ KVP, float* __restrict__ KV) {
    int idx = blockIdx.x * blockDim.x + threadIdx.x;
    const int tot = TT * BB * HEADS * DH * DH;
    if (idx >= tot) return;
    float s = 0.f;
#pragma unroll
    for (int g = 0; g < 4; g++) s += KVP[(size_t)g * tot + idx];
    KV[idx] = s;
}

// ---------------- av (NHWC): A[tb][n][h*64+e] = sum_d Q[tb][n][h*64+d]*KV[tbh][d][e] ----------------
__global__ void av_kernel(const float* __restrict__ Q, const float* __restrict__ KV,
                          float* __restrict__ A) {
    int nt = blockIdx.x;
    int tbh = blockIdx.y;
    int tb = tbh / HEADS, h = tbh % HEADS;
    __shared__ float kvs[64][65];
    __shared__ float Qs[64][65];
    int tx = threadIdx.x;
    int tn = tx >> 4, te = tx & 15;
    int n0 = nt * 64;
    const float* Qb = Q + (size_t)tb * NN * CC + h * DH;
#pragma unroll
    for (int u = 0; u < 16; u++) {
        int e = tx + u * 256;
        int r = e >> 6, x = e & 63;
        kvs[r][x] = KV[(size_t)tbh * DH * DH + r * DH + x];
        Qs[r][x] = Qb[(size_t)(n0 + r) * CC + x];
    }
    __syncthreads();
    float acc[4][4];
#pragma unroll
    for (int i = 0; i < 4; i++)
#pragma unroll
        for (int j = 0; j < 4; j++) acc[i][j] = 0.0f;
#pragma unroll
    for (int d = 0; d < 64; d++) {
        float a0 = Qs[tn * 4 + 0][d], a1 = Qs[tn * 4 + 1][d];
        float a2 = Qs[tn * 4 + 2][d], a3 = Qs[tn * 4 + 3][d];
        float b0 = kvs[d][te * 4 + 0], b1 = kvs[d][te * 4 + 1];
        float b2 = kvs[d][te * 4 + 2], b3 = kvs[d][te * 4 + 3];
        acc[0][0] += a0 * b0; acc[0][1] += a0 * b1; acc[0][2] += a0 * b2; acc[0][3] += a0 * b3;
        acc[1][0] += a1 * b0; acc[1][1] += a1 * b1; acc[1][2] += a1 * b2; acc[1][3] += a1 * b3;
        acc[2][0] += a2 * b0; acc[2][1] += a2 * b1; acc[2][2] += a2 * b2; acc[2][3] += a2 * b3;
        acc[3][0] += a3 * b0; acc[3][1] += a3 * b1; acc[3][2] += a3 * b2; acc[3][3] += a3 * b3;
    }
#pragma unroll
    for (int i = 0; i < 4; i++) {
        int n = n0 + tn * 4 + i;
        float4 w4;
        w4.x = acc[i][0]; w4.y = acc[i][1]; w4.z = acc[i][2]; w4.w = acc[i][3];
        *(float4*)(A + ((size_t)tb * NN + n) * CC + h * DH + te * 4) = w4;
    }
}

// ---------------- host orchestration ----------------
static void run_branch(const float* inSpk, int i, float* out, int out_mode,
                       const float* w1, const float* dw, const float* pw,
                       const float* b1w, const float* b1b, const float* b1m, const float* b1v,
                       const float* b2w, const float* b2b, const float* b2m, const float* b2v,
                       const float* b3w, const float* b3b, const float* b3m, const float* b3v,
                       float* PAD, float* DWH, float* DWL, float* WH, float* WL) {
    presplit_kernel<<<(CC * CC + 255) / 256, 256>>>(w1 + (size_t)i * CC * CC, WH, WL);
    padfill_kernel<<<dim3(260, IMG), CC>>>(PAD, b1w + i * CC, b1b + i * CC, b1m + i * CC, b1v + i * CC);
    conv_mma_kernel<<<dim3(16, 3, IMG), 512, SMEM_BYTES>>>(inSpk, inSpk, WH, WL, PAD,
        b1w + i * CC, b1b + i * CC, b1m + i * CC, b1v + i * CC,
        nullptr, nullptr, nullptr, nullptr, 0);
    dwconv_kernel<<<dim3(NN, IMG), CC>>>(PAD, dw + (size_t)i * CC * 9, DWH, DWL);
    presplit_kernel<<<(CC * CC + 255) / 256, 256>>>(pw + (size_t)i * CC * CC, WH, WL);
    conv_mma_kernel<<<dim3(16, 3, IMG), 512, SMEM_BYTES>>>(DWH, DWL, WH, WL, out,
        b2w + i * CC, b2b + i * CC, b2m + i * CC, b2v + i * CC,
        b3w + i * CC, b3b + i * CC, b3m + i * CC, b3v + i * CC, out_mode);
}

extern "C" void kernel_launch(void* const* d_in, const int* in_sizes, int n_in,
                              void* d_out, int out_size) {
    const float* x   = (const float*)d_in[0];
    const float* w1  = (const float*)d_in[1];
    const float* dw  = (const float*)d_in[2];
    const float* pw  = (const float*)d_in[3];
    const float* b1w = (const float*)d_in[4];
    const float* b1b = (const float*)d_in[5];
    const float* b1m = (const float*)d_in[6];
    const float* b1v = (const float*)d_in[7];
    const float* b2w = (const float*)d_in[8];
    const float* b2b = (const float*)d_in[9];
    const float* b2m = (const float*)d_in[10];
    const float* b2v = (const float*)d_in[11];
    const float* b3w = (const float*)d_in[12];
    const float* b3b = (const float*)d_in[13];
    const float* b3m = (const float*)d_in[14];
    const float* b3v = (const float*)d_in[15];
    const float* vth = (const float*)d_in[16];
    float* out = (float*)d_out;

    cudaFuncSetAttribute(conv_mma_kernel, cudaFuncAttributeMaxDynamicSharedMemorySize, SMEM_BYTES);

    float *XS, *PAD, *DWH, *DWL, *BR, *QS, *KS, *VS, *AS, *WH, *WL, *KVP, *KV;
    cudaGetSymbolAddress((void**)&XS,  g_XS);
    cudaGetSymbolAddress((void**)&PAD, g_PAD);
    cudaGetSymbolAddress((void**)&DWH, g_DWH);
    cudaGetSymbolAddress((void**)&DWL, g_DWL);
    cudaGetSymbolAddress((void**)&BR,  g_BR);
    cudaGetSymbolAddress((void**)&QS,  g_QS);
    cudaGetSymbolAddress((void**)&KS,  g_KS);
    cudaGetSymbolAddress((void**)&VS,  g_VS);
    cudaGetSymbolAddress((void**)&AS,  g_AS);
    cudaGetSymbolAddress((void**)&WH,  g_WH);
    cudaGetSymbolAddress((void**)&WL,  g_WL);
    cudaGetSymbolAddress((void**)&KVP, g_KVP);
    cudaGetSymbolAddress((void**)&KV,  g_KV);

    const int athreads = 256;
    const int ablocks = (BCN + athreads - 1) / athreads;

    // 1) alif on x, NCHW -> NHWC (k-permuted channel slots; XS only feeds conv1)
    alif_first_kernel<<<dim3(NN / 32, CC / 32, BB), dim3(32, 8)>>>(x, XS, vth);

    // 2) q/k/v branches
    float* sp[3] = {QS, KS, VS};
    for (int i = 0; i < 3; i++) {
        run_branch(XS, i, BR, 1, w1, dw, pw,
                   b1w, b1b, b1m, b1v, b2w, b2b, b2m, b2v, b3w, b3b, b3m, b3v,
                   PAD, DWH, DWL, WH, WL);
        alif_kernel<<<ablocks, athreads>>>(BR, sp[i], vth, 1 + i, 0);
    }

    // 3) linear attention (exact fp32, natural channels)
    kv_kernel<<<dim3(4, TT * BB * HEADS), 256>>>(KS, VS, KVP);
    kvred_kernel<<<(TT * BB * HEADS * DH * DH + 255) / 256, 256>>>(KVP, KV);
    av_kernel<<<dim3(64, TT * BB * HEADS), 256>>>(QS, KV, BR);
    alif_kernel<<<ablocks, athreads>>>(BR, AS, vth, 4, 1);   // AS feeds conv1 -> permuted

    // 4) final branch -> d_out (NCHW)
    run_branch(AS, 3, out, 2, w1, dw, pw,
               b1w, b1b, b1m, b1v, b2w, b2b, b2m, b2v, b3w, b3b, b3m, b3v,
               PAD, DWH, DWL, WH, WL);
}

// round 9
// speedup vs baseline: 1.9519x; 1.5664x over previous
#include <cuda_runtime.h>
#include <cuda_fp16.h>
#include <cstdint>
#include <cstddef>

#define TT 4
#define BB 4
#define CC 384
#define NN 4096
#define IMG 16
#define BCN (BB*CC*NN)
#define HEADS 6
#define DH 64
#define PADW 66
#define EPS 1e-5f

// ---------------- scratch (static device globals) ----------------
__device__ __align__(256) __half g_XS [IMG*NN*CC];        // spikes of x (NHWC, perm32 chans)
__device__ __align__(256) float  g_PAD[IMG*PADW*PADW*CC]; // bn1+pad (NHWC fp32, natural)
__device__ __align__(256) __half g_DWH[IMG*NN*CC];        // dwconv out hi (perm)
__device__ __align__(256) __half g_DW6[IMG*NN*CC];        // dwconv residual*2^6 (perm)
__device__ __align__(256) float  g_BR [IMG*NN*CC];        // branch out / attention a (natural)
__device__ __align__(256) float  g_QS [IMG*NN*CC];
__device__ __align__(256) float  g_KS [IMG*NN*CC];
__device__ __align__(256) float  g_VS [IMG*NN*CC];
__device__ __align__(256) __half g_AS [IMG*NN*CC];        // spikes of attention (perm)
__device__ __align__(256) __half g_WH [CC*CC];            // weight hi (perm k)
__device__ __align__(256) __half g_W6 [CC*CC];            // weight residual*2^6 (perm k)
__device__ __align__(256) float  g_KVP[4*TT*BB*HEADS*DH*DH];
__device__ __align__(256) float  g_KV [TT*BB*HEADS*DH*DH];

__device__ __forceinline__ void mmaf16(float* c, uint32_t a0, uint32_t a1, uint32_t a2, uint32_t a3,
                                       uint32_t b0, uint32_t b1) {
    asm volatile("mma.sync.aligned.m16n8k16.row.col.f32.f16.f16.f32 "
                 "{%0,%1,%2,%3}, {%4,%5,%6,%7}, {%8,%9}, {%0,%1,%2,%3};"
                 : "+f"(c[0]), "+f"(c[1]), "+f"(c[2]), "+f"(c[3])
                 : "r"(a0), "r"(a1), "r"(a2), "r"(a3), "r"(b0), "r"(b1));
}
__device__ __forceinline__ uint32_t h2s6(uint32_t x) {   // packed half2 * 2^-6
    uint32_t d;
    asm("mul.rn.f16x2 %0, %1, %2;" : "=r"(d) : "r"(x), "r"(0x24002400u));
    return d;
}
__device__ __forceinline__ void cp16(uint32_t dst, const void* src) {
    asm volatile("cp.async.cg.shared.global [%0], [%1], 16;" :: "r"(dst), "l"(src));
}
#define CP_COMMIT() asm volatile("cp.async.commit_group;" ::: "memory")
#define CP_WAIT0()  asm volatile("cp.async.wait_group 0;" ::: "memory")
#define CP_WAIT1()  asm volatile("cp.async.wait_group 1;" ::: "memory")
__device__ __forceinline__ uint32_t s2u(const void* p) {
    uint32_t a;
    asm("{ .reg .u64 t; cvta.to.shared.u64 t, %1; cvt.u32.u64 %0, t; }" : "=r"(a) : "l"(p));
    return a;
}
// perm within each 32-chunk so thread lc's fragment halves [2lc,2lc+1,2lc+8,2lc+9]
// for both k16 groups are 16 contiguous bytes: k=16g+8h+2q+b -> pos = q*8+g*4+h*2+b
__device__ __forceinline__ int perm32(int c) {
    int ch = c & ~31, r = c & 31;
    return ch + ((r & 7) >> 1) * 8 + ((r >> 4) & 1) * 4 + ((r >> 3) & 1) * 2 + (r & 1);
}

// ---- smem layout (bytes): 2 stages of [AH 16K | A6 16K | WH 8K | W6 8K]
#define AH_B 0
#define A6_B 16384
#define WH_B 32768
#define W6_B 40960
#define STAGE_B 49152
// transpose scratch (mode 2) reuses bytes [0, 139264); scale/bias parked above it
#define SCL_F 34816              // float index = byte 139264
#define SBS_F 34944              // byte 139776
#define SMEM_BYTES 140416

// ---------------- conv1x1: fp16 split-precision mma, cp.async double-buffered ----------------
// D[p][o] = sum_c A[p][c]*W[o][c]; CTA 256(M) x 128(N), K=384 in 12 chunks of 32.
// 16 warps 4(m)x4(n); warp tile 64x32; mma m16n8k16 f16 -> f32.
// mode 0: A binary (2 passes), bn1 epilogue -> PAD interior (NHWC fp32)
// mode 1: A hi/lo (3 passes), bn2*bn3 epilogue -> NHWC fp32
// mode 2: like 1, writes NCHW (d_out)
__global__ void __launch_bounds__(512, 1)
conv_mma_kernel(const __half* __restrict__ AHg, const __half* __restrict__ A6g,
                const __half* __restrict__ WHg, const __half* __restrict__ W6g,
                float* __restrict__ OUT,
                const float* __restrict__ wA, const float* __restrict__ bA,
                const float* __restrict__ mA, const float* __restrict__ vA,
                const float* __restrict__ wB, const float* __restrict__ bB2,
                const float* __restrict__ mB, const float* __restrict__ vB,
                int mode) {
    extern __shared__ char smem[];
    float* smf = (float*)smem;
    const int tx = threadIdx.x;
    const int wid = tx >> 5, lane = tx & 31;
    const int lr = lane >> 2, lc = lane & 3;
    const int wm = wid >> 2, wn = wid & 3;
    const int img = blockIdx.z;
    const int p0 = blockIdx.x * 256;
    const int n0 = blockIdx.y * 128;
    const bool dense = (mode != 0);
    const size_t arow0 = (size_t)img * NN + p0;
    const uint32_t smb = s2u(smem);

    if (tx < 128) {
        int o = n0 + tx;
        float s, bias;
        if (mode == 0) {
            float inv = wA[o] * rsqrtf(vA[o] + EPS);
            s = inv; bias = bA[o] - mA[o] * inv;
        } else {
            float s2 = wA[o] * rsqrtf(vA[o] + EPS);
            float t2 = bA[o] - mA[o] * s2;
            float s3 = wB[o] * rsqrtf(vB[o] + EPS);
            float t3 = bB2[o] - mB[o] * s3;
            s = s2 * s3; bias = t2 * s3 + t3;
        }
        smf[SCL_F + tx] = s;
        smf[SBS_F + tx] = bias;
    }

    auto issue_chunk = [&](int ch, int st) {
        int c0 = ch * 32;
        uint32_t stb = smb + (uint32_t)st * STAGE_B;
#pragma unroll
        for (int it = 0; it < 2; it++) {
            int u = tx + it * 512;
            int row = u >> 2, q = u & 3;
            cp16(stb + AH_B + row * 64 + q * 16, AHg + (arow0 + row) * CC + c0 + q * 8);
        }
        if (dense) {
#pragma unroll
            for (int it = 0; it < 2; it++) {
                int u = tx + it * 512;
                int row = u >> 2, q = u & 3;
                cp16(stb + A6_B + row * 64 + q * 16, A6g + (arow0 + row) * CC + c0 + q * 8);
            }
        }
        {
            int row = tx >> 2, q = tx & 3;
            cp16(stb + WH_B + row * 64 + q * 16, WHg + (size_t)(n0 + row) * CC + c0 + q * 8);
            cp16(stb + W6_B + row * 64 + q * 16, W6g + (size_t)(n0 + row) * CC + c0 + q * 8);
        }
    };

    float acc[4][4][4];
#pragma unroll
    for (int a = 0; a < 4; a++)
#pragma unroll
        for (int b = 0; b < 4; b++)
#pragma unroll
            for (int c = 0; c < 4; c++) acc[a][b][c] = 0.0f;

    auto compute = [&](int st) {
        const char* Sb = smem + st * STAGE_B;
        uint4 Bh[4], W6f[4];
#pragma unroll
        for (int nt = 0; nt < 4; nt++) {
            int n = wn * 32 + nt * 8 + lr;
            Bh[nt]  = *(const uint4*)(Sb + WH_B + n * 64 + lc * 16);
            W6f[nt] = *(const uint4*)(Sb + W6_B + n * 64 + lc * 16);
        }
#pragma unroll
        for (int mt = 0; mt < 4; mt++) {
            int r = wm * 64 + mt * 16 + lr;
            uint4 A0 = *(const uint4*)(Sb + AH_B + r * 64 + lc * 16);
            uint4 A1 = *(const uint4*)(Sb + AH_B + (r + 8) * 64 + lc * 16);
            // pass 1: Ah * Wh  (both k16 groups)
#pragma unroll
            for (int nt = 0; nt < 4; nt++) {
                mmaf16(acc[mt][nt], A0.x, A1.x, A0.y, A1.y, Bh[nt].x, Bh[nt].y);
                mmaf16(acc[mt][nt], A0.z, A1.z, A0.w, A1.w, Bh[nt].z, Bh[nt].w);
            }
            // pass 2: (Ah*2^-6) * W6
            A0.x = h2s6(A0.x); A0.y = h2s6(A0.y); A0.z = h2s6(A0.z); A0.w = h2s6(A0.w);
            A1.x = h2s6(A1.x); A1.y = h2s6(A1.y); A1.z = h2s6(A1.z); A1.w = h2s6(A1.w);
#pragma unroll
            for (int nt = 0; nt < 4; nt++) {
                mmaf16(acc[mt][nt], A0.x, A1.x, A0.y, A1.y, W6f[nt].x, W6f[nt].y);
                mmaf16(acc[mt][nt], A0.z, A1.z, A0.w, A1.w, W6f[nt].z, W6f[nt].w);
            }
        }
        if (dense) {
            // pass 3: A6 * (Wh*2^-6)
#pragma unroll
            for (int nt = 0; nt < 4; nt++) {
                Bh[nt].x = h2s6(Bh[nt].x); Bh[nt].y = h2s6(Bh[nt].y);
                Bh[nt].z = h2s6(Bh[nt].z); Bh[nt].w = h2s6(Bh[nt].w);
            }
#pragma unroll
            for (int mt = 0; mt < 4; mt++) {
                int r = wm * 64 + mt * 16 + lr;
                uint4 A0 = *(const uint4*)(Sb + A6_B + r * 64 + lc * 16);
                uint4 A1 = *(const uint4*)(Sb + A6_B + (r + 8) * 64 + lc * 16);
#pragma unroll
                for (int nt = 0; nt < 4; nt++) {
                    mmaf16(acc[mt][nt], A0.x, A1.x, A0.y, A1.y, Bh[nt].x, Bh[nt].y);
                    mmaf16(acc[mt][nt], A0.z, A1.z, A0.w, A1.w, Bh[nt].z, Bh[nt].w);
                }
            }
        }
    };

    issue_chunk(0, 0);
    CP_COMMIT();
    for (int ch = 0; ch < 12; ch++) {
        if (ch < 11) {
            issue_chunk(ch + 1, (ch + 1) & 1);
            CP_COMMIT();
            CP_WAIT1();
        } else {
            CP_WAIT0();
        }
        __syncthreads();
        compute(ch & 1);
        __syncthreads();
    }

    // ---------------- epilogue ----------------
    if (mode != 2) {
#pragma unroll
        for (int mt = 0; mt < 4; mt++) {
            int pa = p0 + wm * 64 + mt * 16 + lr;
            int pb = pa + 8;
#pragma unroll
            for (int nt = 0; nt < 4; nt++) {
                int ol = wn * 32 + nt * 8 + 2 * lc;
                float s0 = smf[SCL_F + ol], s1 = smf[SCL_F + ol + 1];
                float z0 = smf[SBS_F + ol], z1 = smf[SBS_F + ol + 1];
                float2 v0 = make_float2(acc[mt][nt][0] * s0 + z0, acc[mt][nt][1] * s1 + z1);
                float2 v1 = make_float2(acc[mt][nt][2] * s0 + z0, acc[mt][nt][3] * s1 + z1);
                if (mode == 0) {
                    int ra = (pa & 4095) >> 6, ca = pa & 63;
                    int rb = (pb & 4095) >> 6, cb = pb & 63;
                    *(float2*)(OUT + ((((size_t)img * PADW + ra + 1) * PADW + ca + 1) * CC) + n0 + ol) = v0;
                    *(float2*)(OUT + ((((size_t)img * PADW + rb + 1) * PADW + cb + 1) * CC) + n0 + ol) = v1;
                } else {
                    *(float2*)(OUT + ((size_t)img * NN + pa) * CC + n0 + ol) = v0;
                    *(float2*)(OUT + ((size_t)img * NN + pb) * CC + n0 + ol) = v1;
                }
            }
        }
    } else {
        // NCHW out: per-warp 32(n) x 64(m) transpose (reuses stage bytes; scale/bias parked above)
        float* T = smf + wid * (32 * 68);
#pragma unroll
        for (int mt = 0; mt < 4; mt++) {
            int mm = mt * 16 + lr;
#pragma unroll
            for (int nt = 0; nt < 4; nt++) {
                int nl = nt * 8 + 2 * lc;
                int ol = wn * 32 + nl;
                float s0 = smf[SCL_F + ol], s1 = smf[SCL_F + ol + 1];
                float z0 = smf[SBS_F + ol], z1 = smf[SBS_F + ol + 1];
                T[nl * 68 + mm]           = acc[mt][nt][0] * s0 + z0;
                T[(nl + 1) * 68 + mm]     = acc[mt][nt][1] * s1 + z1;
                T[nl * 68 + mm + 8]       = acc[mt][nt][2] * s0 + z0;
                T[(nl + 1) * 68 + mm + 8] = acc[mt][nt][3] * s1 + z1;
            }
        }
        __syncwarp();
#pragma unroll
        for (int ol = 0; ol < 32; ol++) {
            int o = n0 + wn * 32 + ol;
            float2 v = *(float2*)&T[ol * 68 + lane * 2];
            *(float2*)(OUT + ((size_t)img * CC + o) * NN + p0 + wm * 64 + lane * 2) = v;
        }
    }
}

// ---------------- weight presplit (fp16 hi + residual*2^6, k-permuted) ----------------
__global__ void presplit_kernel(const float* __restrict__ W,
                                __half* __restrict__ WHo, __half* __restrict__ W6o) {
    int idx = blockIdx.x * 256 + threadIdx.x;
    if (idx >= CC * CC) return;
    int o = idx / CC, c = idx % CC;
    float v = W[idx];
    __half h = __float2half_rn(v);
    float r = (v - __half2float(h)) * 64.0f;
    WHo[(size_t)o * CC + perm32(c)] = h;
    W6o[(size_t)o * CC + perm32(c)] = __float2half_rn(r);
}

// ---------------- ALIF first (NCHW fp32 -> NHWC perm fp16 spikes) ----------------
__global__ void alif_first_kernel(const float* __restrict__ in, __half* __restrict__ out,
                                  const float* __restrict__ vth_ptr) {
    __shared__ float s[32][33];
    int tx = threadIdx.x, ty = threadIdx.y;
    int n0 = blockIdx.x * 32;
    int c0 = blockIdx.y * 32;
    int b = blockIdx.z;
    float vth = vth_ptr[0];
    int cp = c0 + perm32(tx);
    float v[4] = {0.f, 0.f, 0.f, 0.f};
#pragma unroll
    for (int t = 0; t < TT; t++) {
#pragma unroll
        for (int k = 0; k < 4; k++) {
            int c = c0 + ty + 8 * k;
            float xv = in[(((size_t)(t * BB + b) * CC + c) * NN) + n0 + tx];
            v[k] = v[k] + (xv - v[k]) * 0.5f;
            s[ty + 8 * k][tx] = (v[k] - vth >= 0.0f) ? 1.0f : 0.0f;
        }
        __syncthreads();
#pragma unroll
        for (int k = 0; k < 4; k++) {
            int n = n0 + ty + 8 * k;
            out[((size_t)(t * BB + b) * NN + n) * CC + cp] = __float2half_rn(s[tx][ty + 8 * k]);
        }
        __syncthreads();
    }
}

// ---------------- ALIF fp32 out (q/k/v, natural layout) ----------------
__global__ void alif_kernel(const float* __restrict__ in, float* __restrict__ out,
                            const float* __restrict__ vth_ptr, int vidx) {
    int j = blockIdx.x * blockDim.x + threadIdx.x;
    if (j >= BCN) return;
    float vth = vth_ptr[vidx];
    float v = 0.0f;
#pragma unroll
    for (int t = 0; t < TT; t++) {
        float x = in[(size_t)j + (size_t)t * BCN];
        v = v + (x - v) * 0.5f;
        out[(size_t)j + (size_t)t * BCN] = (v - vth >= 0.0f) ? 1.0f : 0.0f;
    }
}

// ---------------- ALIF fp16 permuted out (attention spikes -> conv input) ----------------
__global__ void alif_f16p_kernel(const float* __restrict__ in, __half* __restrict__ out,
                                 const float* __restrict__ vth_ptr, int vidx) {
    int j = blockIdx.x * blockDim.x + threadIdx.x;
    if (j >= BCN) return;
    float vth = vth_ptr[vidx];
    int c = j % CC;
    size_t jo = (size_t)(j - c + perm32(c));
    float v = 0.0f;
#pragma unroll
    for (int t = 0; t < TT; t++) {
        float x = in[(size_t)j + (size_t)t * BCN];
        v = v + (x - v) * 0.5f;
        out[jo + (size_t)t * BCN] = __float2half_rn((v - vth >= 0.0f) ? 1.0f : 0.0f);
    }
}

// ---------------- pad border fill (NHWC fp32 natural) ----------------
__global__ void padfill_kernel(float* __restrict__ pad,
                               const float* __restrict__ bw, const float* __restrict__ bb,
                               const float* __restrict__ bm, const float* __restrict__ bv) {
    int t = blockIdx.x;
    int img = blockIdx.y;
    int c = threadIdx.x;
    float inv = bw[c] * rsqrtf(bv[c] + EPS);
    float pv = bb[c] - bm[c] * inv;
    int r, cl;
    if      (t < 66)  { r = 0;           cl = t;        }
    else if (t < 132) { r = 65;          cl = t - 66;   }
    else if (t < 196) { r = t - 132 + 1; cl = 0;        }
    else              { r = t - 196 + 1; cl = 65;       }
    pad[(((size_t)img * PADW + r) * PADW + cl) * CC + c] = pv;
}

// ---------------- depthwise 3x3 (NHWC fp32) -> fp16 hi + residual*2^6, perm ----------------
__global__ void dwconv_kernel(const float* __restrict__ pad, const float* __restrict__ w9,
                              __half* __restrict__ outH, __half* __restrict__ outL) {
    int c = threadIdx.x;
    int p = blockIdx.x;
    int img = blockIdx.y;
    int r = p >> 6, cl = p & 63;
    const float* base = pad + (((size_t)img * PADW + r) * PADW + cl) * CC + c;
    float wr[9];
#pragma unroll
    for (int k = 0; k < 9; k++) wr[k] = __ldg(w9 + c * 9 + k);
    float sacc = 0.0f;
#pragma unroll
    for (int i = 0; i < 3; i++)
#pragma unroll
        for (int j = 0; j < 3; j++)
            sacc += wr[i * 3 + j] * base[(size_t)(i * PADW + j) * CC];
    int pc = perm32(c);
    __half h = __float2half_rn(sacc);
    float rr = (sacc - __half2float(h)) * 64.0f;
    outH[((size_t)img * NN + p) * CC + pc] = h;
    outL[((size_t)img * NN + p) * CC + pc] = __float2half_rn(rr);
}

// ---------------- kv partial (NHWC fp32): kvp[seg][tbh][d][e] ----------------
__global__ void kv_kernel(const float* __restrict__ K, const float* __restrict__ V,
                          float* __restrict__ KVP) {
    int seg = blockIdx.x;
    int tbh = blockIdx.y;
    int tb = tbh / HEADS, h = tbh % HEADS;
    __shared__ float Ks[64][65];
    __shared__ float Vs[64][65];
    int tx = threadIdx.x;
    int td = tx >> 4, te = tx & 15;
    const float* Kb = K + (size_t)tb * NN * CC + h * DH;
    const float* Vb = V + (size_t)tb * NN * CC + h * DH;
    float acc[4][4];
#pragma unroll
    for (int i = 0; i < 4; i++)
#pragma unroll
        for (int j = 0; j < 4; j++) acc[i][j] = 0.0f;

    for (int n0 = seg * 1024; n0 < (seg + 1) * 1024; n0 += 64) {
#pragma unroll
        for (int u = 0; u < 16; u++) {
            int e = tx + u * 256;
            int n = e >> 6, d = e & 63;
            Ks[n][d] = Kb[(size_t)(n0 + n) * CC + d];
            Vs[n][d] = Vb[(size_t)(n0 + n) * CC + d];
        }
        __syncthreads();
#pragma unroll
        for (int n = 0; n < 64; n++) {
            float a0 = Ks[n][td * 4 + 0], a1 = Ks[n][td * 4 + 1];
            float a2 = Ks[n][td * 4 + 2], a3 = Ks[n][td * 4 + 3];
            float b0 = Vs[n][te * 4 + 0], b1 = Vs[n][te * 4 + 1];
            float b2 = Vs[n][te * 4 + 2], b3 = Vs[n][te * 4 + 3];
            acc[0][0] += a0 * b0; acc[0][1] += a0 * b1; acc[0][2] += a0 * b2; acc[0][3] += a0 * b3;
            acc[1][0] += a1 * b0; acc[1][1] += a1 * b1; acc[1][2] += a1 * b2; acc[1][3] += a1 * b3;
            acc[2][0] += a2 * b0; acc[2][1] += a2 * b1; acc[2][2] += a2 * b2; acc[2][3] += a2 * b3;
            acc[3][0] += a3 * b0; acc[3][1] += a3 * b1; acc[3][2] += a3 * b2; acc[3][3] += a3 * b3;
        }
        __syncthreads();
    }
#pragma unroll
    for (int i = 0; i < 4; i++)
#pragma unroll
        for (int j = 0; j < 4; j++)
            KVP[((size_t)seg * (TT * BB * HEADS) + tbh) * (DH * DH) + (td * 4 + i) * DH + te * 4 + j] =
                acc[i][j];
}

__global__ void kvred_kernel(const float* __restrict__ KVP, float* __restrict__ KV) {
    int idx = blockIdx.x * blockDim.x + threadIdx.x;
    const int tot = TT * BB * HEADS * DH * DH;
    if (idx >= tot) return;
    float s = 0.f;
#pragma unroll
    for (int g = 0; g < 4; g++) s += KVP[(size_t)g * tot + idx];
    KV[idx] = s;
}

// ---------------- av (NHWC fp32) ----------------
__global__ void av_kernel(const float* __restrict__ Q, const float* __restrict__ KV,
                          float* __restrict__ A) {
    int nt = blockIdx.x;
    int tbh = blockIdx.y;
    int tb = tbh / HEADS, h = tbh % HEADS;
    __shared__ float kvs[64][65];
    __shared__ float Qs[64][65];
    int tx = threadIdx.x;
    int tn = tx >> 4, te = tx & 15;
    int n0 = nt * 64;
    const float* Qb = Q + (size_t)tb * NN * CC + h * DH;
#pragma unroll
    for (int u = 0; u < 16; u++) {
        int e = tx + u * 256;
        int r = e >> 6, x = e & 63;
        kvs[r][x] = KV[(size_t)tbh * DH * DH + r * DH + x];
        Qs[r][x] = Qb[(size_t)(n0 + r) * CC + x];
    }
    __syncthreads();
    float acc[4][4];
#pragma unroll
    for (int i = 0; i < 4; i++)
#pragma unroll
        for (int j = 0; j < 4; j++) acc[i][j] = 0.0f;
#pragma unroll
    for (int d = 0; d < 64; d++) {
        float a0 = Qs[tn * 4 + 0][d], a1 = Qs[tn * 4 + 1][d];
        float a2 = Qs[tn * 4 + 2][d], a3 = Qs[tn * 4 + 3][d];
        float b0 = kvs[d][te * 4 + 0], b1 = kvs[d][te * 4 + 1];
        float b2 = kvs[d][te * 4 + 2], b3 = kvs[d][te * 4 + 3];
        acc[0][0] += a0 * b0; acc[0][1] += a0 * b1; acc[0][2] += a0 * b2; acc[0][3] += a0 * b3;
        acc[1][0] += a1 * b0; acc[1][1] += a1 * b1; acc[1][2] += a1 * b2; acc[1][3] += a1 * b3;
        acc[2][0] += a2 * b0; acc[2][1] += a2 * b1; acc[2][2] += a2 * b2; acc[2][3] += a2 * b3;
        acc[3][0] += a3 * b0; acc[3][1] += a3 * b1; acc[3][2] += a3 * b2; acc[3][3] += a3 * b3;
    }
#pragma unroll
    for (int i = 0; i < 4; i++) {
        int n = n0 + tn * 4 + i;
        float4 w4;
        w4.x = acc[i][0]; w4.y = acc[i][1]; w4.z = acc[i][2]; w4.w = acc[i][3];
        *(float4*)(A + ((size_t)tb * NN + n) * CC + h * DH + te * 4) = w4;
    }
}

// ---------------- host orchestration ----------------
static void run_branch(const __half* inSpk, int i, float* out, int out_mode,
                       const float* w1, const float* dw, const float* pw,
                       const float* b1w, const float* b1b, const float* b1m, const float* b1v,
                       const float* b2w, const float* b2b, const float* b2m, const float* b2v,
                       const float* b3w, const float* b3b, const float* b3m, const float* b3v,
                       float* PAD, __half* DWH, __half* DW6, __half* WH, __half* W6) {
    presplit_kernel<<<(CC * CC + 255) / 256, 256>>>(w1 + (size_t)i * CC * CC, WH, W6);
    padfill_kernel<<<dim3(260, IMG), CC>>>(PAD, b1w + i * CC, b1b + i * CC, b1m + i * CC, b1v + i * CC);
    conv_mma_kernel<<<dim3(16, 3, IMG), 512, SMEM_BYTES>>>(inSpk, inSpk, WH, W6, PAD,
        b1w + i * CC, b1b + i * CC, b1m + i * CC, b1v + i * CC,
        nullptr, nullptr, nullptr, nullptr, 0);
    dwconv_kernel<<<dim3(NN, IMG), CC>>>(PAD, dw + (size_t)i * CC * 9, DWH, DW6);
    presplit_kernel<<<(CC * CC + 255) / 256, 256>>>(pw + (size_t)i * CC * CC, WH, W6);
    conv_mma_kernel<<<dim3(16, 3, IMG), 512, SMEM_BYTES>>>(DWH, DW6, WH, W6, out,
        b2w + i * CC, b2b + i * CC, b2m + i * CC, b2v + i * CC,
        b3w + i * CC, b3b + i * CC, b3m + i * CC, b3v + i * CC, out_mode);
}

extern "C" void kernel_launch(void* const* d_in, const int* in_sizes, int n_in,
                              void* d_out, int out_size) {
    const float* x   = (const float*)d_in[0];
    const float* w1  = (const float*)d_in[1];
    const float* dw  = (const float*)d_in[2];
    const float* pw  = (const float*)d_in[3];
    const float* b1w = (const float*)d_in[4];
    const float* b1b = (const float*)d_in[5];
    const float* b1m = (const float*)d_in[6];
    const float* b1v = (const float*)d_in[7];
    const float* b2w = (const float*)d_in[8];
    const float* b2b = (const float*)d_in[9];
    const float* b2m = (const float*)d_in[10];
    const float* b2v = (const float*)d_in[11];
    const float* b3w = (const float*)d_in[12];
    const float* b3b = (const float*)d_in[13];
    const float* b3m = (const float*)d_in[14];
    const float* b3v = (const float*)d_in[15];
    const float* vth = (const float*)d_in[16];
    float* out = (float*)d_out;

    cudaFuncSetAttribute(conv_mma_kernel, cudaFuncAttributeMaxDynamicSharedMemorySize, SMEM_BYTES);

    float *PAD, *BR, *QS, *KS, *VS, *KVP, *KV;
    __half *XS, *AS, *DWH, *DW6, *WH, *W6;
    cudaGetSymbolAddress((void**)&XS,  g_XS);
    cudaGetSymbolAddress((void**)&PAD, g_PAD);
    cudaGetSymbolAddress((void**)&DWH, g_DWH);
    cudaGetSymbolAddress((void**)&DW6, g_DW6);
    cudaGetSymbolAddress((void**)&BR,  g_BR);
    cudaGetSymbolAddress((void**)&QS,  g_QS);
    cudaGetSymbolAddress((void**)&KS,  g_KS);
    cudaGetSymbolAddress((void**)&VS,  g_VS);
    cudaGetSymbolAddress((void**)&AS,  g_AS);
    cudaGetSymbolAddress((void**)&WH,  g_WH);
    cudaGetSymbolAddress((void**)&W6,  g_W6);
    cudaGetSymbolAddress((void**)&KVP, g_KVP);
    cudaGetSymbolAddress((void**)&KV,  g_KV);

    const int athreads = 256;
    const int ablocks = (BCN + athreads - 1) / athreads;

    // 1) alif on x: NCHW fp32 -> NHWC perm fp16 spikes
    alif_first_kernel<<<dim3(NN / 32, CC / 32, BB), dim3(32, 8)>>>(x, XS, vth);

    // 2) q/k/v branches
    float* sp[3] = {QS, KS, VS};
    for (int i = 0; i < 3; i++) {
        run_branch(XS, i, BR, 1, w1, dw, pw,
                   b1w, b1b, b1m, b1v, b2w, b2b, b2m, b2v, b3w, b3b, b3m, b3v,
                   PAD, DWH, DW6, WH, W6);
        alif_kernel<<<ablocks, athreads>>>(BR, sp[i], vth, 1 + i);
    }

    // 3) linear attention (exact fp32, natural channels)
    kv_kernel<<<dim3(4, TT * BB * HEADS), 256>>>(KS, VS, KVP);
    kvred_kernel<<<(TT * BB * HEADS * DH * DH + 255) / 256, 256>>>(KVP, KV);
    av_kernel<<<dim3(64, TT * BB * HEADS), 256>>>(QS, KV, BR);
    alif_f16p_kernel<<<ablocks, athreads>>>(BR, AS, vth, 4);

    // 4) final branch -> d_out (NCHW)
    run_branch(AS, 3, out, 2, w1, dw, pw,
               b1w, b1b, b1m, b1v, b2w, b2b, b2m, b2v, b3w, b3b, b3m, b3v,
               PAD, DWH, DW6, WH, W6);
}

// round 11
// speedup vs baseline: 2.0532x; 1.0519x over previous
#include <cuda_runtime.h>
#include <cuda_fp16.h>
#include <cstdint>
#include <cstddef>

#define TT 4
#define BB 4
#define CC 384
#define NN 4096
#define IMG 16
#define BCN (BB*CC*NN)
#define HEADS 6
#define DH 64
#define PADW 66
#define EPS 1e-5f

// ---------------- scratch (static device globals) ----------------
__device__ __align__(256) __half g_XS [IMG*NN*CC];        // spikes of x (NHWC, perm32 chans)
__device__ __align__(256) float  g_PAD[IMG*PADW*PADW*CC]; // bn1+pad (NHWC fp32, natural)
__device__ __align__(256) __half g_DWH[IMG*NN*CC];        // dwconv out hi (perm)
__device__ __align__(256) __half g_DW6[IMG*NN*CC];        // dwconv residual*2^6 (perm)
__device__ __align__(256) float  g_BR [IMG*NN*CC];        // branch out / attention a (natural)
__device__ __align__(256) float  g_QS [IMG*NN*CC];
__device__ __align__(256) float  g_KS [IMG*NN*CC];
__device__ __align__(256) float  g_VS [IMG*NN*CC];
__device__ __align__(256) __half g_AS [IMG*NN*CC];        // spikes of attention (perm)
__device__ __align__(256) __half g_WH [CC*CC];            // weight hi (perm k)
__device__ __align__(256) __half g_W6 [CC*CC];            // weight residual*2^6 (perm k)
__device__ __align__(256) float  g_KVP[4*TT*BB*HEADS*DH*DH];
__device__ __align__(256) float  g_KV [TT*BB*HEADS*DH*DH];

__device__ __forceinline__ void mmaf16(float* c, uint32_t a0, uint32_t a1, uint32_t a2, uint32_t a3,
                                       uint32_t b0, uint32_t b1) {
    asm volatile("mma.sync.aligned.m16n8k16.row.col.f32.f16.f16.f32 "
                 "{%0,%1,%2,%3}, {%4,%5,%6,%7}, {%8,%9}, {%0,%1,%2,%3};"
                 : "+f"(c[0]), "+f"(c[1]), "+f"(c[2]), "+f"(c[3])
                 : "r"(a0), "r"(a1), "r"(a2), "r"(a3), "r"(b0), "r"(b1));
}
__device__ __forceinline__ uint32_t h2s6(uint32_t x) {   // packed half2 * 2^-6
    uint32_t d;
    asm("mul.rn.f16x2 %0, %1, %2;" : "=r"(d) : "r"(x), "r"(0x24002400u));
    return d;
}
__device__ __forceinline__ void cp16(uint32_t dst, const void* src) {
    asm volatile("cp.async.cg.shared.global [%0], [%1], 16;" :: "r"(dst), "l"(src));
}
#define CP_COMMIT() asm volatile("cp.async.commit_group;" ::: "memory")
#define CP_WAIT0()  asm volatile("cp.async.wait_group 0;" ::: "memory")
#define CP_WAIT1()  asm volatile("cp.async.wait_group 1;" ::: "memory")
__device__ __forceinline__ uint32_t s2u(const void* p) {
    uint32_t a;
    asm("{ .reg .u64 t; cvta.to.shared.u64 t, %1; cvt.u32.u64 %0, t; }" : "=r"(a) : "l"(p));
    return a;
}
// perm within each 32-chunk so thread lc's fragment halves [2lc,2lc+1,2lc+8,2lc+9]
// for both k16 groups are 16 contiguous bytes: k=16g+8h+2q+b -> pos = q*8+g*4+h*2+b
__device__ __forceinline__ int perm32(int c) {
    int ch = c & ~31, r = c & 31;
    return ch + ((r & 7) >> 1) * 8 + ((r >> 4) & 1) * 4 + ((r >> 3) & 1) * 2 + (r & 1);
}

// ---- smem layout (bytes): 3 stages of [AH 16K | A6 16K | WH 8K | W6 8K]
#define AH_B 0
#define A6_B 16384
#define WH_B 32768
#define W6_B 40960
#define STAGE_B 49152
#define NSTAGE 3
// scale/bias parked after the 3 stages (3*49152 = 147456 bytes = float idx 36864)
#define SCL_F 36864
#define SBS_F 36992
#define SMEM_BYTES 148480
// mode-2 transpose scratch reuses stage bytes [0, 139264) AFTER the trailing barrier

// ---------------- conv1x1: fp16 split-precision mma, 3-stage cp.async pipeline ----------------
// D[p][o] = sum_c A[p][c]*W[o][c]; CTA 256(M) x 128(N), K=384 in 12 chunks of 32.
// 16 warps 4(m)x4(n); warp tile 64x32; mma m16n8k16 f16 -> f32.
// One __syncthreads per chunk: with 3 stages the barrier before compute(ch) proves
// all warps finished compute(ch-1), whose stage is the one issue(ch+2) overwrites.
// mode 0: A binary (2 passes), bn1 epilogue -> PAD interior (NHWC fp32)
// mode 1: A hi/lo (3 passes), bn2*bn3 epilogue -> NHWC fp32
// mode 2: like 1, writes NCHW (d_out)
__global__ void __launch_bounds__(512, 1)
conv_mma_kernel(const __half* __restrict__ AHg, const __half* __restrict__ A6g,
                const __half* __restrict__ WHg, const __half* __restrict__ W6g,
                float* __restrict__ OUT,
                const float* __restrict__ wA, const float* __restrict__ bA,
                const float* __restrict__ mA, const float* __restrict__ vA,
                const float* __restrict__ wB, const float* __restrict__ bB2,
                const float* __restrict__ mB, const float* __restrict__ vB,
                int mode) {
    extern __shared__ char smem[];
    float* smf = (float*)smem;
    const int tx = threadIdx.x;
    const int wid = tx >> 5, lane = tx & 31;
    const int lr = lane >> 2, lc = lane & 3;
    const int wm = wid >> 2, wn = wid & 3;
    const int img = blockIdx.z;
    const int p0 = blockIdx.x * 256;
    const int n0 = blockIdx.y * 128;
    const bool dense = (mode != 0);
    const size_t arow0 = (size_t)img * NN + p0;
    const uint32_t smb = s2u(smem);

    if (tx < 128) {
        int o = n0 + tx;
        float s, bias;
        if (mode == 0) {
            float inv = wA[o] * rsqrtf(vA[o] + EPS);
            s = inv; bias = bA[o] - mA[o] * inv;
        } else {
            float s2 = wA[o] * rsqrtf(vA[o] + EPS);
            float t2 = bA[o] - mA[o] * s2;
            float s3 = wB[o] * rsqrtf(vB[o] + EPS);
            float t3 = bB2[o] - mB[o] * s3;
            s = s2 * s3; bias = t2 * s3 + t3;
        }
        smf[SCL_F + tx] = s;
        smf[SBS_F + tx] = bias;
    }

    auto issue_chunk = [&](int ch, int st) {
        int c0 = ch * 32;
        uint32_t stb = smb + (uint32_t)st * STAGE_B;
#pragma unroll
        for (int it = 0; it < 2; it++) {
            int u = tx + it * 512;
            int row = u >> 2, q = u & 3;
            cp16(stb + AH_B + row * 64 + q * 16, AHg + (arow0 + row) * CC + c0 + q * 8);
        }
        if (dense) {
#pragma unroll
            for (int it = 0; it < 2; it++) {
                int u = tx + it * 512;
                int row = u >> 2, q = u & 3;
                cp16(stb + A6_B + row * 64 + q * 16, A6g + (arow0 + row) * CC + c0 + q * 8);
            }
        }
        {
            int row = tx >> 2, q = tx & 3;
            cp16(stb + WH_B + row * 64 + q * 16, WHg + (size_t)(n0 + row) * CC + c0 + q * 8);
            cp16(stb + W6_B + row * 64 + q * 16, W6g + (size_t)(n0 + row) * CC + c0 + q * 8);
        }
    };

    float acc[4][4][4];
#pragma unroll
    for (int a = 0; a < 4; a++)
#pragma unroll
        for (int b = 0; b < 4; b++)
#pragma unroll
            for (int c = 0; c < 4; c++) acc[a][b][c] = 0.0f;

    auto compute = [&](int st) {
        const char* Sb = smem + st * STAGE_B;
        uint4 Bh[4], W6f[4];
#pragma unroll
        for (int nt = 0; nt < 4; nt++) {
            int n = wn * 32 + nt * 8 + lr;
            Bh[nt]  = *(const uint4*)(Sb + WH_B + n * 64 + lc * 16);
            W6f[nt] = *(const uint4*)(Sb + W6_B + n * 64 + lc * 16);
        }
#pragma unroll
        for (int mt = 0; mt < 4; mt++) {
            int r = wm * 64 + mt * 16 + lr;
            uint4 A0 = *(const uint4*)(Sb + AH_B + r * 64 + lc * 16);
            uint4 A1 = *(const uint4*)(Sb + AH_B + (r + 8) * 64 + lc * 16);
            // pass 1: Ah * Wh  (both k16 groups)
#pragma unroll
            for (int nt = 0; nt < 4; nt++) {
                mmaf16(acc[mt][nt], A0.x, A1.x, A0.y, A1.y, Bh[nt].x, Bh[nt].y);
                mmaf16(acc[mt][nt], A0.z, A1.z, A0.w, A1.w, Bh[nt].z, Bh[nt].w);
            }
            // pass 2: (Ah*2^-6) * W6
            A0.x = h2s6(A0.x); A0.y = h2s6(A0.y); A0.z = h2s6(A0.z); A0.w = h2s6(A0.w);
            A1.x = h2s6(A1.x); A1.y = h2s6(A1.y); A1.z = h2s6(A1.z); A1.w = h2s6(A1.w);
#pragma unroll
            for (int nt = 0; nt < 4; nt++) {
                mmaf16(acc[mt][nt], A0.x, A1.x, A0.y, A1.y, W6f[nt].x, W6f[nt].y);
                mmaf16(acc[mt][nt], A0.z, A1.z, A0.w, A1.w, W6f[nt].z, W6f[nt].w);
            }
        }
        if (dense) {
            // pass 3: A6 * (Wh*2^-6)
#pragma unroll
            for (int nt = 0; nt < 4; nt++) {
                Bh[nt].x = h2s6(Bh[nt].x); Bh[nt].y = h2s6(Bh[nt].y);
                Bh[nt].z = h2s6(Bh[nt].z); Bh[nt].w = h2s6(Bh[nt].w);
            }
#pragma unroll
            for (int mt = 0; mt < 4; mt++) {
                int r = wm * 64 + mt * 16 + lr;
                uint4 A0 = *(const uint4*)(Sb + A6_B + r * 64 + lc * 16);
                uint4 A1 = *(const uint4*)(Sb + A6_B + (r + 8) * 64 + lc * 16);
#pragma unroll
                for (int nt = 0; nt < 4; nt++) {
                    mmaf16(acc[mt][nt], A0.x, A1.x, A0.y, A1.y, Bh[nt].x, Bh[nt].y);
                    mmaf16(acc[mt][nt], A0.z, A1.z, A0.w, A1.w, Bh[nt].z, Bh[nt].w);
                }
            }
        }
    };

    // 3-stage pipeline, one barrier per chunk
    issue_chunk(0, 0); CP_COMMIT();
    issue_chunk(1, 1); CP_COMMIT();
    int st = 0;
    for (int ch = 0; ch < 12; ch++) {
        if (ch < 11) CP_WAIT1(); else CP_WAIT0();
        __syncthreads();
        compute(st);
        if (ch < 10) {
            int st2 = st + 2; if (st2 >= NSTAGE) st2 -= NSTAGE;
            issue_chunk(ch + 2, st2);
            CP_COMMIT();
        }
        if (++st == NSTAGE) st = 0;
    }
    __syncthreads();   // stages are dead; mode-2 transpose may reuse them

    // ---------------- epilogue ----------------
    if (mode != 2) {
#pragma unroll
        for (int mt = 0; mt < 4; mt++) {
            int pa = p0 + wm * 64 + mt * 16 + lr;
            int pb = pa + 8;
#pragma unroll
            for (int nt = 0; nt < 4; nt++) {
                int ol = wn * 32 + nt * 8 + 2 * lc;
                float s0 = smf[SCL_F + ol], s1 = smf[SCL_F + ol + 1];
                float z0 = smf[SBS_F + ol], z1 = smf[SBS_F + ol + 1];
                float2 v0 = make_float2(acc[mt][nt][0] * s0 + z0, acc[mt][nt][1] * s1 + z1);
                float2 v1 = make_float2(acc[mt][nt][2] * s0 + z0, acc[mt][nt][3] * s1 + z1);
                if (mode == 0) {
                    int ra = (pa & 4095) >> 6, ca = pa & 63;
                    int rb = (pb & 4095) >> 6, cb = pb & 63;
                    *(float2*)(OUT + ((((size_t)img * PADW + ra + 1) * PADW + ca + 1) * CC) + n0 + ol) = v0;
                    *(float2*)(OUT + ((((size_t)img * PADW + rb + 1) * PADW + cb + 1) * CC) + n0 + ol) = v1;
                } else {
                    *(float2*)(OUT + ((size_t)img * NN + pa) * CC + n0 + ol) = v0;
                    *(float2*)(OUT + ((size_t)img * NN + pb) * CC + n0 + ol) = v1;
                }
            }
        }
    } else {
        // NCHW out: per-warp 32(n) x 64(m) transpose (reuses dead stage bytes)
        float* T = smf + wid * (32 * 68);
#pragma unroll
        for (int mt = 0; mt < 4; mt++) {
            int mm = mt * 16 + lr;
#pragma unroll
            for (int nt = 0; nt < 4; nt++) {
                int nl = nt * 8 + 2 * lc;
                int ol = wn * 32 + nl;
                float s0 = smf[SCL_F + ol], s1 = smf[SCL_F + ol + 1];
                float z0 = smf[SBS_F + ol], z1 = smf[SBS_F + ol + 1];
                T[nl * 68 + mm]           = acc[mt][nt][0] * s0 + z0;
                T[(nl + 1) * 68 + mm]     = acc[mt][nt][1] * s1 + z1;
                T[nl * 68 + mm + 8]       = acc[mt][nt][2] * s0 + z0;
                T[(nl + 1) * 68 + mm + 8] = acc[mt][nt][3] * s1 + z1;
            }
        }
        __syncwarp();
#pragma unroll
        for (int ol = 0; ol < 32; ol++) {
            int o = n0 + wn * 32 + ol;
            float2 v = *(float2*)&T[ol * 68 + lane * 2];
            *(float2*)(OUT + ((size_t)img * CC + o) * NN + p0 + wm * 64 + lane * 2) = v;
        }
    }
}

// ---------------- weight presplit (fp16 hi + residual*2^6, k-permuted) ----------------
__global__ void presplit_kernel(const float* __restrict__ W,
                                __half* __restrict__ WHo, __half* __restrict__ W6o) {
    int idx = blockIdx.x * 256 + threadIdx.x;
    if (idx >= CC * CC) return;
    int o = idx / CC, c = idx % CC;
    float v = W[idx];
    __half h = __float2half_rn(v);
    float r = (v - __half2float(h)) * 64.0f;
    WHo[(size_t)o * CC + perm32(c)] = h;
    W6o[(size_t)o * CC + perm32(c)] = __float2half_rn(r);
}

// ---------------- ALIF first (NCHW fp32 -> NHWC perm fp16 spikes) ----------------
__global__ void alif_first_kernel(const float* __restrict__ in, __half* __restrict__ out,
                                  const float* __restrict__ vth_ptr) {
    __shared__ float s[32][33];
    int tx = threadIdx.x, ty = threadIdx.y;
    int n0 = blockIdx.x * 32;
    int c0 = blockIdx.y * 32;
    int b = blockIdx.z;
    float vth = vth_ptr[0];
    int cp = c0 + perm32(tx);
    float v[4] = {0.f, 0.f, 0.f, 0.f};
#pragma unroll
    for (int t = 0; t < TT; t++) {
#pragma unroll
        for (int k = 0; k < 4; k++) {
            int c = c0 + ty + 8 * k;
            float xv = in[(((size_t)(t * BB + b) * CC + c) * NN) + n0 + tx];
            v[k] = v[k] + (xv - v[k]) * 0.5f;
            s[ty + 8 * k][tx] = (v[k] - vth >= 0.0f) ? 1.0f : 0.0f;
        }
        __syncthreads();
#pragma unroll
        for (int k = 0; k < 4; k++) {
            int n = n0 + ty + 8 * k;
            out[((size_t)(t * BB + b) * NN + n) * CC + cp] = __float2half_rn(s[tx][ty + 8 * k]);
        }
        __syncthreads();
    }
}

// ---------------- ALIF fp32 out (q/k/v, natural layout) ----------------
__global__ void alif_kernel(const float* __restrict__ in, float* __restrict__ out,
                            const float* __restrict__ vth_ptr, int vidx) {
    int j = blockIdx.x * blockDim.x + threadIdx.x;
    if (j >= BCN) return;
    float vth = vth_ptr[vidx];
    float v = 0.0f;
#pragma unroll
    for (int t = 0; t < TT; t++) {
        float x = in[(size_t)j + (size_t)t * BCN];
        v = v + (x - v) * 0.5f;
        out[(size_t)j + (size_t)t * BCN] = (v - vth >= 0.0f) ? 1.0f : 0.0f;
    }
}

// ---------------- ALIF fp16 permuted out (attention spikes -> conv input) ----------------
__global__ void alif_f16p_kernel(const float* __restrict__ in, __half* __restrict__ out,
                                 const float* __restrict__ vth_ptr, int vidx) {
    int j = blockIdx.x * blockDim.x + threadIdx.x;
    if (j >= BCN) return;
    float vth = vth_ptr[vidx];
    int c = j % CC;
    size_t jo = (size_t)(j - c + perm32(c));
    float v = 0.0f;
#pragma unroll
    for (int t = 0; t < TT; t++) {
        float x = in[(size_t)j + (size_t)t * BCN];
        v = v + (x - v) * 0.5f;
        out[jo + (size_t)t * BCN] = __float2half_rn((v - vth >= 0.0f) ? 1.0f : 0.0f);
    }
}

// ---------------- pad border fill (NHWC fp32 natural) ----------------
__global__ void padfill_kernel(float* __restrict__ pad,
                               const float* __restrict__ bw, const float* __restrict__ bb,
                               const float* __restrict__ bm, const float* __restrict__ bv) {
    int t = blockIdx.x;
    int img = blockIdx.y;
    int c = threadIdx.x;
    float inv = bw[c] * rsqrtf(bv[c] + EPS);
    float pv = bb[c] - bm[c] * inv;
    int r, cl;
    if      (t < 66)  { r = 0;           cl = t;        }
    else if (t < 132) { r = 65;          cl = t - 66;   }
    else if (t < 196) { r = t - 132 + 1; cl = 0;        }
    else              { r = t - 196 + 1; cl = 65;       }
    pad[(((size_t)img * PADW + r) * PADW + cl) * CC + c] = pv;
}

// ---------------- depthwise 3x3 (NHWC fp32) -> fp16 hi + residual*2^6, perm ----------------
__global__ void dwconv_kernel(const float* __restrict__ pad, const float* __restrict__ w9,
                              __half* __restrict__ outH, __half* __restrict__ outL) {
    int c = threadIdx.x;
    int p = blockIdx.x;
    int img = blockIdx.y;
    int r = p >> 6, cl = p & 63;
    const float* base = pad + (((size_t)img * PADW + r) * PADW + cl) * CC + c;
    float wr[9];
#pragma unroll
    for (int k = 0; k < 9; k++) wr[k] = __ldg(w9 + c * 9 + k);
    float sacc = 0.0f;
#pragma unroll
    for (int i = 0; i < 3; i++)
#pragma unroll
        for (int j = 0; j < 3; j++)
            sacc += wr[i * 3 + j] * base[(size_t)(i * PADW + j) * CC];
    int pc = perm32(c);
    __half h = __float2half_rn(sacc);
    float rr = (sacc - __half2float(h)) * 64.0f;
    outH[((size_t)img * NN + p) * CC + pc] = h;
    outL[((size_t)img * NN + p) * CC + pc] = __float2half_rn(rr);
}

// ---------------- kv partial (NHWC fp32): kvp[seg][tbh][d][e] ----------------
__global__ void kv_kernel(const float* __restrict__ K, const float* __restrict__ V,
                          float* __restrict__ KVP) {
    int seg = blockIdx.x;
    int tbh = blockIdx.y;
    int tb = tbh / HEADS, h = tbh % HEADS;
    __shared__ float Ks[64][65];
    __shared__ float Vs[64][65];
    int tx = threadIdx.x;
    int td = tx >> 4, te = tx & 15;
    const float* Kb = K + (size_t)tb * NN * CC + h * DH;
    const float* Vb = V + (size_t)tb * NN * CC + h * DH;
    float acc[4][4];
#pragma unroll
    for (int i = 0; i < 4; i++)
#pragma unroll
        for (int j = 0; j < 4; j++) acc[i][j] = 0.0f;

    for (int n0 = seg * 1024; n0 < (seg + 1) * 1024; n0 += 64) {
#pragma unroll
        for (int u = 0; u < 16; u++) {
            int e = tx + u * 256;
            int n = e >> 6, d = e & 63;
            Ks[n][d] = Kb[(size_t)(n0 + n) * CC + d];
            Vs[n][d] = Vb[(size_t)(n0 + n) * CC + d];
        }
        __syncthreads();
#pragma unroll
        for (int n = 0; n < 64; n++) {
            float a0 = Ks[n][td * 4 + 0], a1 = Ks[n][td * 4 + 1];
            float a2 = Ks[n][td * 4 + 2], a3 = Ks[n][td * 4 + 3];
            float b0 = Vs[n][te * 4 + 0], b1 = Vs[n][te * 4 + 1];
            float b2 = Vs[n][te * 4 + 2], b3 = Vs[n][te * 4 + 3];
            acc[0][0] += a0 * b0; acc[0][1] += a0 * b1; acc[0][2] += a0 * b2; acc[0][3] += a0 * b3;
            acc[1][0] += a1 * b0; acc[1][1] += a1 * b1; acc[1][2] += a1 * b2; acc[1][3] += a1 * b3;
            acc[2][0] += a2 * b0; acc[2][1] += a2 * b1; acc[2][2] += a2 * b2; acc[2][3] += a2 * b3;
            acc[3][0] += a3 * b0; acc[3][1] += a3 * b1; acc[3][2] += a3 * b2; acc[3][3] += a3 * b3;
        }
        __syncthreads();
    }
#pragma unroll
    for (int i = 0; i < 4; i++)
#pragma unroll
        for (int j = 0; j < 4; j++)
            KVP[((size_t)seg * (TT * BB * HEADS) + tbh) * (DH * DH) + (td * 4 + i) * DH + te * 4 + j] =
                acc[i][j];
}

__global__ void kvred_kernel(const float* __restrict__ KVP, float* __restrict__ KV) {
    int idx = blockIdx.x * blockDim.x + threadIdx.x;
    const int tot = TT * BB * HEADS * DH * DH;
    if (idx >= tot) return;
    float s = 0.f;
#pragma unroll
    for (int g = 0; g < 4; g++) s += KVP[(size_t)g * tot + idx];
    KV[idx] = s;
}

// ---------------- av (NHWC fp32) ----------------
__global__ void av_kernel(const float* __restrict__ Q, const float* __restrict__ KV,
                          float* __restrict__ A) {
    int nt = blockIdx.x;
    int tbh = blockIdx.y;
    int tb = tbh / HEADS, h = tbh % HEADS;
    __shared__ float kvs[64][65];
    __shared__ float Qs[64][65];
    int tx = threadIdx.x;
    int tn = tx >> 4, te = tx & 15;
    int n0 = nt * 64;
    const float* Qb = Q + (size_t)tb * NN * CC + h * DH;
#pragma unroll
    for (int u = 0; u < 16; u++) {
        int e = tx + u * 256;
        int r = e >> 6, x = e & 63;
        kvs[r][x] = KV[(size_t)tbh * DH * DH + r * DH + x];
        Qs[r][x] = Qb[(size_t)(n0 + r) * CC + x];
    }
    __syncthreads();
    float acc[4][4];
#pragma unroll
    for (int i = 0; i < 4; i++)
#pragma unroll
        for (int j = 0; j < 4; j++) acc[i][j] = 0.0f;
#pragma unroll
    for (int d = 0; d < 64; d++) {
        float a0 = Qs[tn * 4 + 0][d], a1 = Qs[tn * 4 + 1][d];
        float a2 = Qs[tn * 4 + 2][d], a3 = Qs[tn * 4 + 3][d];
        float b0 = kvs[d][te * 4 + 0], b1 = kvs[d][te * 4 + 1];
        float b2 = kvs[d][te * 4 + 2], b3 = kvs[d][te * 4 + 3];
        acc[0][0] += a0 * b0; acc[0][1] += a0 * b1; acc[0][2] += a0 * b2; acc[0][3] += a0 * b3;
        acc[1][0] += a1 * b0; acc[1][1] += a1 * b1; acc[1][2] += a1 * b2; acc[1][3] += a1 * b3;
        acc[2][0] += a2 * b0; acc[2][1] += a2 * b1; acc[2][2] += a2 * b2; acc[2][3] += a2 * b3;
        acc[3][0] += a3 * b0; acc[3][1] += a3 * b1; acc[3][2] += a3 * b2; acc[3][3] += a3 * b3;
    }
#pragma unroll
    for (int i = 0; i < 4; i++) {
        int n = n0 + tn * 4 + i;
        float4 w4;
        w4.x = acc[i][0]; w4.y = acc[i][1]; w4.z = acc[i][2]; w4.w = acc[i][3];
        *(float4*)(A + ((size_t)tb * NN + n) * CC + h * DH + te * 4) = w4;
    }
}

// ---------------- host orchestration ----------------
static void run_branch(const __half* inSpk, int i, float* out, int out_mode,
                       const float* w1, const float* dw, const float* pw,
                       const float* b1w, const float* b1b, const float* b1m, const float* b1v,
                       const float* b2w, const float* b2b, const float* b2m, const float* b2v,
                       const float* b3w, const float* b3b, const float* b3m, const float* b3v,
                       float* PAD, __half* DWH, __half* DW6, __half* WH, __half* W6) {
    presplit_kernel<<<(CC * CC + 255) / 256, 256>>>(w1 + (size_t)i * CC * CC, WH, W6);
    padfill_kernel<<<dim3(260, IMG), CC>>>(PAD, b1w + i * CC, b1b + i * CC, b1m + i * CC, b1v + i * CC);
    conv_mma_kernel<<<dim3(16, 3, IMG), 512, SMEM_BYTES>>>(inSpk, inSpk, WH, W6, PAD,
        b1w + i * CC, b1b + i * CC, b1m + i * CC, b1v + i * CC,
        nullptr, nullptr, nullptr, nullptr, 0);
    dwconv_kernel<<<dim3(NN, IMG), CC>>>(PAD, dw + (size_t)i * CC * 9, DWH, DW6);
    presplit_kernel<<<(CC * CC + 255) / 256, 256>>>(pw + (size_t)i * CC * CC, WH, W6);
    conv_mma_kernel<<<dim3(16, 3, IMG), 512, SMEM_BYTES>>>(DWH, DW6, WH, W6, out,
        b2w + i * CC, b2b + i * CC, b2m + i * CC, b2v + i * CC,
        b3w + i * CC, b3b + i * CC, b3m + i * CC, b3v + i * CC, out_mode);
}

extern "C" void kernel_launch(void* const* d_in, const int* in_sizes, int n_in,
                              void* d_out, int out_size) {
    const float* x   = (const float*)d_in[0];
    const float* w1  = (const float*)d_in[1];
    const float* dw  = (const float*)d_in[2];
    const float* pw  = (const float*)d_in[3];
    const float* b1w = (const float*)d_in[4];
    const float* b1b = (const float*)d_in[5];
    const float* b1m = (const float*)d_in[6];
    const float* b1v = (const float*)d_in[7];
    const float* b2w = (const float*)d_in[8];
    const float* b2b = (const float*)d_in[9];
    const float* b2m = (const float*)d_in[10];
    const float* b2v = (const float*)d_in[11];
    const float* b3w = (const float*)d_in[12];
    const float* b3b = (const float*)d_in[13];
    const float* b3m = (const float*)d_in[14];
    const float* b3v = (const float*)d_in[15];
    const float* vth = (const float*)d_in[16];
    float* out = (float*)d_out;

    cudaFuncSetAttribute(conv_mma_kernel, cudaFuncAttributeMaxDynamicSharedMemorySize, SMEM_BYTES);

    float *PAD, *BR, *QS, *KS, *VS, *KVP, *KV;
    __half *XS, *AS, *DWH, *DW6, *WH, *W6;
    cudaGetSymbolAddress((void**)&XS,  g_XS);
    cudaGetSymbolAddress((void**)&PAD, g_PAD);
    cudaGetSymbolAddress((void**)&DWH, g_DWH);
    cudaGetSymbolAddress((void**)&DW6, g_DW6);
    cudaGetSymbolAddress((void**)&BR,  g_BR);
    cudaGetSymbolAddress((void**)&QS,  g_QS);
    cudaGetSymbolAddress((void**)&KS,  g_KS);
    cudaGetSymbolAddress((void**)&VS,  g_VS);
    cudaGetSymbolAddress((void**)&AS,  g_AS);
    cudaGetSymbolAddress((void**)&WH,  g_WH);
    cudaGetSymbolAddress((void**)&W6,  g_W6);
    cudaGetSymbolAddress((void**)&KVP, g_KVP);
    cudaGetSymbolAddress((void**)&KV,  g_KV);

    const int athreads = 256;
    const int ablocks = (BCN + athreads - 1) / athreads;

    // 1) alif on x: NCHW fp32 -> NHWC perm fp16 spikes
    alif_first_kernel<<<dim3(NN / 32, CC / 32, BB), dim3(32, 8)>>>(x, XS, vth);

    // 2) q/k/v branches
    float* sp[3] = {QS, KS, VS};
    for (int i = 0; i < 3; i++) {
        run_branch(XS, i, BR, 1, w1, dw, pw,
                   b1w, b1b, b1m, b1v, b2w, b2b, b2m, b2v, b3w, b3b, b3m, b3v,
                   PAD, DWH, DW6, WH, W6);
        alif_kernel<<<ablocks, athreads>>>(BR, sp[i], vth, 1 + i);
    }

    // 3) linear attention (exact fp32, natural channels)
    kv_kernel<<<dim3(4, TT * BB * HEADS), 256>>>(KS, VS, KVP);
    kvred_kernel<<<(TT * BB * HEADS * DH * DH + 255) / 256, 256>>>(KVP, KV);
    av_kernel<<<dim3(64, TT * BB * HEADS), 256>>>(QS, KV, BR);
    alif_f16p_kernel<<<ablocks, athreads>>>(BR, AS, vth, 4);

    // 4) final branch -> d_out (NCHW)
    run_branch(AS, 3, out, 2, w1, dw, pw,
               b1w, b1b, b1m, b1v, b2w, b2b, b2m, b2v, b3w, b3b, b3m, b3v,
               PAD, DWH, DW6, WH, W6);
}

// round 12
// speedup vs baseline: 2.3628x; 1.1508x over previous
#include <cuda_runtime.h>
#include <cuda_fp16.h>
#include <cstdint>
#include <cstddef>

#define TT 4
#define BB 4
#define CC 384
#define NN 4096
#define IMG 16
#define BCN (BB*CC*NN)
#define IMGNNC ((size_t)IMG*NN*CC)          // 25165824
#define PADSZ  ((size_t)IMG*PADW*PADW*CC)   // 26763264
#define CCCC (CC*CC)
#define HEADS 6
#define DH 64
#define PADW 66
#define EPS 1e-5f

// ---------------- scratch (static device globals) ----------------
__device__ __align__(256) __half g_XS  [IMG*NN*CC];          // spikes of x (NHWC perm)
__device__ __align__(256) float  g_PAD3[3*IMG*PADW*PADW*CC]; // bn1+pad, 3 branches
__device__ __align__(256) __half g_DWH3[3*IMG*NN*CC];        // dwconv hi, 3 branches (perm)
__device__ __align__(256) __half g_DW63[3*IMG*NN*CC];        // dwconv residual*2^6
__device__ __align__(256) float  g_BR3 [3*IMG*NN*CC];        // branch outs (natural)
__device__ __align__(256) __half g_QKVh[3*IMG*NN*CC];        // q/k/v spikes fp16 (natural)
__device__ __align__(256) __half g_AS  [IMG*NN*CC];          // attention spikes (perm)
__device__ __align__(256) __half g_WH  [8*CC*CC];            // 4x w1 then 4x pw, hi (perm k)
__device__ __align__(256) __half g_W6  [8*CC*CC];            // residual*2^6
__device__ __align__(256) float  g_DWT [4*9*CC];             // dw transposed [br][k][c]
__device__ __align__(256) float  g_KVP [4*TT*BB*HEADS*DH*DH];
__device__ __align__(256) float  g_KV  [TT*BB*HEADS*DH*DH];

__device__ __forceinline__ void mmaf16(float* c, uint32_t a0, uint32_t a1, uint32_t a2, uint32_t a3,
                                       uint32_t b0, uint32_t b1) {
    asm volatile("mma.sync.aligned.m16n8k16.row.col.f32.f16.f16.f32 "
                 "{%0,%1,%2,%3}, {%4,%5,%6,%7}, {%8,%9}, {%0,%1,%2,%3};"
                 : "+f"(c[0]), "+f"(c[1]), "+f"(c[2]), "+f"(c[3])
                 : "r"(a0), "r"(a1), "r"(a2), "r"(a3), "r"(b0), "r"(b1));
}
__device__ __forceinline__ uint32_t h2s6(uint32_t x) {   // packed half2 * 2^-6
    uint32_t d;
    asm("mul.rn.f16x2 %0, %1, %2;" : "=r"(d) : "r"(x), "r"(0x24002400u));
    return d;
}
__device__ __forceinline__ void cp16(uint32_t dst, const void* src) {
    asm volatile("cp.async.cg.shared.global [%0], [%1], 16;" :: "r"(dst), "l"(src));
}
#define CP_COMMIT() asm volatile("cp.async.commit_group;" ::: "memory")
#define CP_WAIT0()  asm volatile("cp.async.wait_group 0;" ::: "memory")
#define CP_WAIT1()  asm volatile("cp.async.wait_group 1;" ::: "memory")
__device__ __forceinline__ uint32_t s2u(const void* p) {
    uint32_t a;
    asm("{ .reg .u64 t; cvta.to.shared.u64 t, %1; cvt.u32.u64 %0, t; }" : "=r"(a) : "l"(p));
    return a;
}
// perm within each 32-chunk: k=16g+8h+2q+b -> pos = q*8+g*4+h*2+b
__device__ __forceinline__ int perm32(int c) {
    int ch = c & ~31, r = c & 31;
    return ch + ((r & 7) >> 1) * 8 + ((r >> 4) & 1) * 4 + ((r >> 3) & 1) * 2 + (r & 1);
}

// ---- smem layout (bytes): 3 stages of [AH 16K | A6 16K | WH 8K | W6 8K]
#define AH_B 0
#define A6_B 16384
#define WH_B 32768
#define W6_B 40960
#define STAGE_B 49152
#define NSTAGE 3
#define SCL_F 36864
#define SBS_F 36992
#define SMEM_BYTES 148480

// ---------------- conv1x1: fp16 split-precision mma, 3-stage pipeline, branch-batched ----------------
// grid (16, 3, NBR*IMG); br = blockIdx.z/IMG offsets A, W(+br*CCCC), OUT, BN(+br*CC).
// mode 0: binary A (2 passes) -> PAD interior; mode 1: hi/lo A (3 passes) -> NHWC;
// mode 2: hi/lo A -> NCHW (d_out).
__global__ void __launch_bounds__(512, 1)
conv_mma_kernel(const __half* __restrict__ AHg, const __half* __restrict__ A6g,
                const __half* __restrict__ WHg, const __half* __restrict__ W6g,
                float* __restrict__ OUT,
                const float* __restrict__ wA, const float* __restrict__ bA,
                const float* __restrict__ mA, const float* __restrict__ vA,
                const float* __restrict__ wB, const float* __restrict__ bB2,
                const float* __restrict__ mB, const float* __restrict__ vB,
                int mode, size_t aBrStride, size_t oBrStride) {
    extern __shared__ char smem[];
    float* smf = (float*)smem;
    const int tx = threadIdx.x;
    const int wid = tx >> 5, lane = tx & 31;
    const int lr = lane >> 2, lc = lane & 3;
    const int wm = wid >> 2, wn = wid & 3;
    const int br  = blockIdx.z >> 4;       // IMG = 16
    const int img = blockIdx.z & 15;
    const int p0 = blockIdx.x * 256;
    const int n0 = blockIdx.y * 128;
    const bool dense = (mode != 0);
    // branch offsets
    AHg += (size_t)br * aBrStride;
    A6g += (size_t)br * aBrStride;
    WHg += (size_t)br * CCCC;
    W6g += (size_t)br * CCCC;
    OUT += (size_t)br * oBrStride;
    wA += br * CC; bA += br * CC; mA += br * CC; vA += br * CC;
    if (wB) { wB += br * CC; bB2 += br * CC; mB += br * CC; vB += br * CC; }

    const size_t arow0 = (size_t)img * NN + p0;
    const uint32_t smb = s2u(smem);

    if (tx < 128) {
        int o = n0 + tx;
        float s, bias;
        if (mode == 0) {
            float inv = wA[o] * rsqrtf(vA[o] + EPS);
            s = inv; bias = bA[o] - mA[o] * inv;
        } else {
            float s2 = wA[o] * rsqrtf(vA[o] + EPS);
            float t2 = bA[o] - mA[o] * s2;
            float s3 = wB[o] * rsqrtf(vB[o] + EPS);
            float t3 = bB2[o] - mB[o] * s3;
            s = s2 * s3; bias = t2 * s3 + t3;
        }
        smf[SCL_F + tx] = s;
        smf[SBS_F + tx] = bias;
    }

    auto issue_chunk = [&](int ch, int st) {
        int c0 = ch * 32;
        uint32_t stb = smb + (uint32_t)st * STAGE_B;
#pragma unroll
        for (int it = 0; it < 2; it++) {
            int u = tx + it * 512;
            int row = u >> 2, q = u & 3;
            cp16(stb + AH_B + row * 64 + q * 16, AHg + (arow0 + row) * CC + c0 + q * 8);
        }
        if (dense) {
#pragma unroll
            for (int it = 0; it < 2; it++) {
                int u = tx + it * 512;
                int row = u >> 2, q = u & 3;
                cp16(stb + A6_B + row * 64 + q * 16, A6g + (arow0 + row) * CC + c0 + q * 8);
            }
        }
        {
            int row = tx >> 2, q = tx & 3;
            cp16(stb + WH_B + row * 64 + q * 16, WHg + (size_t)(n0 + row) * CC + c0 + q * 8);
            cp16(stb + W6_B + row * 64 + q * 16, W6g + (size_t)(n0 + row) * CC + c0 + q * 8);
        }
    };

    float acc[4][4][4];
#pragma unroll
    for (int a = 0; a < 4; a++)
#pragma unroll
        for (int b = 0; b < 4; b++)
#pragma unroll
            for (int c = 0; c < 4; c++) acc[a][b][c] = 0.0f;

    auto compute = [&](int st) {
        const char* Sb = smem + st * STAGE_B;
        uint4 Bh[4], W6f[4];
#pragma unroll
        for (int nt = 0; nt < 4; nt++) {
            int n = wn * 32 + nt * 8 + lr;
            Bh[nt]  = *(const uint4*)(Sb + WH_B + n * 64 + lc * 16);
            W6f[nt] = *(const uint4*)(Sb + W6_B + n * 64 + lc * 16);
        }
#pragma unroll
        for (int mt = 0; mt < 4; mt++) {
            int r = wm * 64 + mt * 16 + lr;
            uint4 A0 = *(const uint4*)(Sb + AH_B + r * 64 + lc * 16);
            uint4 A1 = *(const uint4*)(Sb + AH_B + (r + 8) * 64 + lc * 16);
#pragma unroll
            for (int nt = 0; nt < 4; nt++) {
                mmaf16(acc[mt][nt], A0.x, A1.x, A0.y, A1.y, Bh[nt].x, Bh[nt].y);
                mmaf16(acc[mt][nt], A0.z, A1.z, A0.w, A1.w, Bh[nt].z, Bh[nt].w);
            }
            A0.x = h2s6(A0.x); A0.y = h2s6(A0.y); A0.z = h2s6(A0.z); A0.w = h2s6(A0.w);
            A1.x = h2s6(A1.x); A1.y = h2s6(A1.y); A1.z = h2s6(A1.z); A1.w = h2s6(A1.w);
#pragma unroll
            for (int nt = 0; nt < 4; nt++) {
                mmaf16(acc[mt][nt], A0.x, A1.x, A0.y, A1.y, W6f[nt].x, W6f[nt].y);
                mmaf16(acc[mt][nt], A0.z, A1.z, A0.w, A1.w, W6f[nt].z, W6f[nt].w);
            }
        }
        if (dense) {
#pragma unroll
            for (int nt = 0; nt < 4; nt++) {
                Bh[nt].x = h2s6(Bh[nt].x); Bh[nt].y = h2s6(Bh[nt].y);
                Bh[nt].z = h2s6(Bh[nt].z); Bh[nt].w = h2s6(Bh[nt].w);
            }
#pragma unroll
            for (int mt = 0; mt < 4; mt++) {
                int r = wm * 64 + mt * 16 + lr;
                uint4 A0 = *(const uint4*)(Sb + A6_B + r * 64 + lc * 16);
                uint4 A1 = *(const uint4*)(Sb + A6_B + (r + 8) * 64 + lc * 16);
#pragma unroll
                for (int nt = 0; nt < 4; nt++) {
                    mmaf16(acc[mt][nt], A0.x, A1.x, A0.y, A1.y, Bh[nt].x, Bh[nt].y);
                    mmaf16(acc[mt][nt], A0.z, A1.z, A0.w, A1.w, Bh[nt].z, Bh[nt].w);
                }
            }
        }
    };

    issue_chunk(0, 0); CP_COMMIT();
    issue_chunk(1, 1); CP_COMMIT();
    int st = 0;
    for (int ch = 0; ch < 12; ch++) {
        if (ch < 11) CP_WAIT1(); else CP_WAIT0();
        __syncthreads();
        compute(st);
        if (ch < 10) {
            int st2 = st + 2; if (st2 >= NSTAGE) st2 -= NSTAGE;
            issue_chunk(ch + 2, st2);
            CP_COMMIT();
        }
        if (++st == NSTAGE) st = 0;
    }
    __syncthreads();

    if (mode != 2) {
#pragma unroll
        for (int mt = 0; mt < 4; mt++) {
            int pa = p0 + wm * 64 + mt * 16 + lr;
            int pb = pa + 8;
#pragma unroll
            for (int nt = 0; nt < 4; nt++) {
                int ol = wn * 32 + nt * 8 + 2 * lc;
                float s0 = smf[SCL_F + ol], s1 = smf[SCL_F + ol + 1];
                float z0 = smf[SBS_F + ol], z1 = smf[SBS_F + ol + 1];
                float2 v0 = make_float2(acc[mt][nt][0] * s0 + z0, acc[mt][nt][1] * s1 + z1);
                float2 v1 = make_float2(acc[mt][nt][2] * s0 + z0, acc[mt][nt][3] * s1 + z1);
                if (mode == 0) {
                    int ra = (pa & 4095) >> 6, ca = pa & 63;
                    int rb = (pb & 4095) >> 6, cb = pb & 63;
                    *(float2*)(OUT + ((((size_t)img * PADW + ra + 1) * PADW + ca + 1) * CC) + n0 + ol) = v0;
                    *(float2*)(OUT + ((((size_t)img * PADW + rb + 1) * PADW + cb + 1) * CC) + n0 + ol) = v1;
                } else {
                    *(float2*)(OUT + ((size_t)img * NN + pa) * CC + n0 + ol) = v0;
                    *(float2*)(OUT + ((size_t)img * NN + pb) * CC + n0 + ol) = v1;
                }
            }
        }
    } else {
        float* T = smf + wid * (32 * 68);
#pragma unroll
        for (int mt = 0; mt < 4; mt++) {
            int mm = mt * 16 + lr;
#pragma unroll
            for (int nt = 0; nt < 4; nt++) {
                int nl = nt * 8 + 2 * lc;
                int ol = wn * 32 + nl;
                float s0 = smf[SCL_F + ol], s1 = smf[SCL_F + ol + 1];
                float z0 = smf[SBS_F + ol], z1 = smf[SBS_F + ol + 1];
                T[nl * 68 + mm]           = acc[mt][nt][0] * s0 + z0;
                T[(nl + 1) * 68 + mm]     = acc[mt][nt][1] * s1 + z1;
                T[nl * 68 + mm + 8]       = acc[mt][nt][2] * s0 + z0;
                T[(nl + 1) * 68 + mm + 8] = acc[mt][nt][3] * s1 + z1;
            }
        }
        __syncwarp();
#pragma unroll
        for (int ol = 0; ol < 32; ol++) {
            int o = n0 + wn * 32 + ol;
            float2 v = *(float2*)&T[ol * 68 + lane * 2];
            *(float2*)(OUT + ((size_t)img * CC + o) * NN + p0 + wm * 64 + lane * 2) = v;
        }
    }
}

// ---------------- presplit ALL 8 weight matrices (4x w1, 4x pw) ----------------
__global__ void presplit_all_kernel(const float* __restrict__ w1, const float* __restrict__ pw,
                                    __half* __restrict__ WHo, __half* __restrict__ W6o) {
    int idx = blockIdx.x * 256 + threadIdx.x;
    if (idx >= 8 * CCCC) return;
    int m = idx / CCCC, e = idx % CCCC;
    int o = e / CC, c = e % CC;
    const float* src = (m < 4) ? (w1 + (size_t)m * CCCC) : (pw + (size_t)(m - 4) * CCCC);
    float v = src[e];
    __half h = __float2half_rn(v);
    float r = (v - __half2float(h)) * 64.0f;
    WHo[(size_t)m * CCCC + (size_t)o * CC + perm32(c)] = h;
    W6o[(size_t)m * CCCC + (size_t)o * CC + perm32(c)] = __float2half_rn(r);
}

// ---------------- transpose depthwise weights: [4][CC][9] -> [4][9][CC] ----------------
__global__ void dwt_kernel(const float* __restrict__ dw, float* __restrict__ dwt) {
    int idx = blockIdx.x * 256 + threadIdx.x;
    if (idx >= 4 * 9 * CC) return;
    int br = idx / (9 * CC), rr = idx % (9 * CC);
    int k = rr / CC, c = rr % CC;
    dwt[idx] = dw[(size_t)br * CC * 9 + c * 9 + k];
}

// ---------------- ALIF first (NCHW fp32 -> NHWC perm fp16 spikes) ----------------
__global__ void alif_first_kernel(const float* __restrict__ in, __half* __restrict__ out,
                                  const float* __restrict__ vth_ptr) {
    __shared__ float s[32][33];
    int tx = threadIdx.x, ty = threadIdx.y;
    int n0 = blockIdx.x * 32;
    int c0 = blockIdx.y * 32;
    int b = blockIdx.z;
    float vth = vth_ptr[0];
    int cp = c0 + perm32(tx);
    float v[4] = {0.f, 0.f, 0.f, 0.f};
#pragma unroll
    for (int t = 0; t < TT; t++) {
#pragma unroll
        for (int k = 0; k < 4; k++) {
            int c = c0 + ty + 8 * k;
            float xv = in[(((size_t)(t * BB + b) * CC + c) * NN) + n0 + tx];
            v[k] = v[k] + (xv - v[k]) * 0.5f;
            s[ty + 8 * k][tx] = (v[k] - vth >= 0.0f) ? 1.0f : 0.0f;
        }
        __syncthreads();
#pragma unroll
        for (int k = 0; k < 4; k++) {
            int n = n0 + ty + 8 * k;
            out[((size_t)(t * BB + b) * NN + n) * CC + cp] = __float2half_rn(s[tx][ty + 8 * k]);
        }
        __syncthreads();
    }
}

// ---------------- ALIF for q/k/v, batched over 3 branches, fp16 natural out ----------------
__global__ void alif_qkv_kernel(const float* __restrict__ in, __half* __restrict__ out,
                                const float* __restrict__ vth_ptr) {
    int j = blockIdx.x * blockDim.x + threadIdx.x;
    if (j >= BCN) return;
    int br = blockIdx.y;
    const float* ib = in + (size_t)br * IMGNNC;
    __half* ob = out + (size_t)br * IMGNNC;
    float vth = vth_ptr[1 + br];
    float v = 0.0f;
#pragma unroll
    for (int t = 0; t < TT; t++) {
        float x = ib[(size_t)j + (size_t)t * BCN];
        v = v + (x - v) * 0.5f;
        ob[(size_t)j + (size_t)t * BCN] = __float2half_rn((v - vth >= 0.0f) ? 1.0f : 0.0f);
    }
}

// ---------------- ALIF fp16 permuted out (attention spikes -> conv input) ----------------
__global__ void alif_f16p_kernel(const float* __restrict__ in, __half* __restrict__ out,
                                 const float* __restrict__ vth_ptr, int vidx) {
    int j = blockIdx.x * blockDim.x + threadIdx.x;
    if (j >= BCN) return;
    float vth = vth_ptr[vidx];
    int c = j % CC;
    size_t jo = (size_t)(j - c + perm32(c));
    float v = 0.0f;
#pragma unroll
    for (int t = 0; t < TT; t++) {
        float x = in[(size_t)j + (size_t)t * BCN];
        v = v + (x - v) * 0.5f;
        out[jo + (size_t)t * BCN] = __float2half_rn((v - vth >= 0.0f) ? 1.0f : 0.0f);
    }
}

// ---------------- pad border fill (NHWC fp32, batched over branches) ----------------
__global__ void padfill_kernel(float* __restrict__ pad,
                               const float* __restrict__ bw, const float* __restrict__ bb,
                               const float* __restrict__ bm, const float* __restrict__ bv) {
    int t = blockIdx.x;
    int br = blockIdx.y >> 4, img = blockIdx.y & 15;
    int c = threadIdx.x;
    float inv = bw[br * CC + c] * rsqrtf(bv[br * CC + c] + EPS);
    float pv = bb[br * CC + c] - bm[br * CC + c] * inv;
    int r, cl;
    if      (t < 66)  { r = 0;           cl = t;        }
    else if (t < 132) { r = 65;          cl = t - 66;   }
    else if (t < 196) { r = t - 132 + 1; cl = 0;        }
    else              { r = t - 196 + 1; cl = 65;       }
    pad[(size_t)br * PADSZ + (((size_t)img * PADW + r) * PADW + cl) * CC + c] = pv;
}

// ---------------- depthwise 3x3 (vectorized float4, branch dim) ----------------
// grid (NN/4, IMG, NBR), block (96, 4). Each thread: 4 channels x 1 position.
__global__ void dwconv_kernel(const float* __restrict__ pad, const float* __restrict__ dwt,
                              __half* __restrict__ outH, __half* __restrict__ outL) {
    int br = blockIdx.z;
    int img = blockIdx.y;
    int p = blockIdx.x * 4 + threadIdx.y;
    int c4 = threadIdx.x * 4;
    int r = p >> 6, cl = p & 63;
    const float* base = pad + (size_t)br * PADSZ + (((size_t)img * PADW + r) * PADW + cl) * CC + c4;
    const float* wt = dwt + (size_t)br * 9 * CC + c4;
    float4 acc = make_float4(0.f, 0.f, 0.f, 0.f);
#pragma unroll
    for (int i = 0; i < 3; i++)
#pragma unroll
        for (int j = 0; j < 3; j++) {
            float4 xv = *(const float4*)(base + (size_t)(i * PADW + j) * CC);
            float4 wv = *(const float4*)(wt + (i * 3 + j) * CC);
            acc.x += wv.x * xv.x; acc.y += wv.y * xv.y;
            acc.z += wv.z * xv.z; acc.w += wv.w * xv.w;
        }
    // split hi + residual*2^6
    __half h0 = __float2half_rn(acc.x), h1 = __float2half_rn(acc.y);
    __half h2 = __float2half_rn(acc.z), h3 = __float2half_rn(acc.w);
    __half l0 = __float2half_rn((acc.x - __half2float(h0)) * 64.0f);
    __half l1 = __float2half_rn((acc.y - __half2float(h1)) * 64.0f);
    __half l2 = __float2half_rn((acc.z - __half2float(h2)) * 64.0f);
    __half l3 = __float2half_rn((acc.w - __half2float(h3)) * 64.0f);
    // perm positions: c4 -> pos, pos+1, pos+8, pos+9
    int ch = c4 & ~31, r32 = c4 & 31;
    int pos = ch + ((r32 & 7) >> 1) * 8 + ((r32 >> 4) & 1) * 4 + ((r32 >> 3) & 1) * 2;
    size_t off = (size_t)br * IMGNNC + ((size_t)img * NN + p) * CC;
    *(__half2*)(outH + off + pos)     = __halves2half2(h0, h1);
    *(__half2*)(outH + off + pos + 8) = __halves2half2(h2, h3);
    *(__half2*)(outL + off + pos)     = __halves2half2(l0, l1);
    *(__half2*)(outL + off + pos + 8) = __halves2half2(l2, l3);
}

// ---------------- kv partial (fp16 in, fp32 math): kvp[seg][tbh][d][e] ----------------
__global__ void kv_kernel(const __half* __restrict__ K, const __half* __restrict__ V,
                          float* __restrict__ KVP) {
    int seg = blockIdx.x;
    int tbh = blockIdx.y;
    int tb = tbh / HEADS, h = tbh % HEADS;
    __shared__ float Ks[64][65];
    __shared__ float Vs[64][65];
    int tx = threadIdx.x;
    int td = tx >> 4, te = tx & 15;
    const __half* Kb = K + (size_t)tb * NN * CC + h * DH;
    const __half* Vb = V + (size_t)tb * NN * CC + h * DH;
    float acc[4][4];
#pragma unroll
    for (int i = 0; i < 4; i++)
#pragma unroll
        for (int j = 0; j < 4; j++) acc[i][j] = 0.0f;

    for (int n0 = seg * 1024; n0 < (seg + 1) * 1024; n0 += 64) {
#pragma unroll
        for (int u = 0; u < 16; u++) {
            int e = tx + u * 256;
            int n = e >> 6, d = e & 63;
            Ks[n][d] = __half2float(Kb[(size_t)(n0 + n) * CC + d]);
            Vs[n][d] = __half2float(Vb[(size_t)(n0 + n) * CC + d]);
        }
        __syncthreads();
#pragma unroll
        for (int n = 0; n < 64; n++) {
            float a0 = Ks[n][td * 4 + 0], a1 = Ks[n][td * 4 + 1];
            float a2 = Ks[n][td * 4 + 2], a3 = Ks[n][td * 4 + 3];
            float b0 = Vs[n][te * 4 + 0], b1 = Vs[n][te * 4 + 1];
            float b2 = Vs[n][te * 4 + 2], b3 = Vs[n][te * 4 + 3];
            acc[0][0] += a0 * b0; acc[0][1] += a0 * b1; acc[0][2] += a0 * b2; acc[0][3] += a0 * b3;
            acc[1][0] += a1 * b0; acc[1][1] += a1 * b1; acc[1][2] += a1 * b2; acc[1][3] += a1 * b3;
            acc[2][0] += a2 * b0; acc[2][1] += a2 * b1; acc[2][2] += a2 * b2; acc[2][3] += a2 * b3;
            acc[3][0] += a3 * b0; acc[3][1] += a3 * b1; acc[3][2] += a3 * b2; acc[3][3] += a3 * b3;
        }
        __syncthreads();
    }
#pragma unroll
    for (int i = 0; i < 4; i++)
#pragma unroll
        for (int j = 0; j < 4; j++)
            KVP[((size_t)seg * (TT * BB * HEADS) + tbh) * (DH * DH) + (td * 4 + i) * DH + te * 4 + j] =
                acc[i][j];
}

__global__ void kvred_kernel(const float* __restrict__ KVP, float* __restrict__ KV) {
    int idx = blockIdx.x * blockDim.x + threadIdx.x;
    const int tot = TT * BB * HEADS * DH * DH;
    if (idx >= tot) return;
    float s = 0.f;
#pragma unroll
    for (int g = 0; g < 4; g++) s += KVP[(size_t)g * tot + idx];
    KV[idx] = s;
}

// ---------------- av (fp16 Q in, fp32 out) ----------------
__global__ void av_kernel(const __half* __restrict__ Q, const float* __restrict__ KV,
                          float* __restrict__ A) {
    int nt = blockIdx.x;
    int tbh = blockIdx.y;
    int tb = tbh / HEADS, h = tbh % HEADS;
    __shared__ float kvs[64][65];
    __shared__ float Qs[64][65];
    int tx = threadIdx.x;
    int tn = tx >> 4, te = tx & 15;
    int n0 = nt * 64;
    const __half* Qb = Q + (size_t)tb * NN * CC + h * DH;
#pragma unroll
    for (int u = 0; u < 16; u++) {
        int e = tx + u * 256;
        int r = e >> 6, x = e & 63;
        kvs[r][x] = KV[(size_t)tbh * DH * DH + r * DH + x];
        Qs[r][x] = __half2float(Qb[(size_t)(n0 + r) * CC + x]);
    }
    __syncthreads();
    float acc[4][4];
#pragma unroll
    for (int i = 0; i < 4; i++)
#pragma unroll
        for (int j = 0; j < 4; j++) acc[i][j] = 0.0f;
#pragma unroll
    for (int d = 0; d < 64; d++) {
        float a0 = Qs[tn * 4 + 0][d], a1 = Qs[tn * 4 + 1][d];
        float a2 = Qs[tn * 4 + 2][d], a3 = Qs[tn * 4 + 3][d];
        float b0 = kvs[d][te * 4 + 0], b1 = kvs[d][te * 4 + 1];
        float b2 = kvs[d][te * 4 + 2], b3 = kvs[d][te * 4 + 3];
        acc[0][0] += a0 * b0; acc[0][1] += a0 * b1; acc[0][2] += a0 * b2; acc[0][3] += a0 * b3;
        acc[1][0] += a1 * b0; acc[1][1] += a1 * b1; acc[1][2] += a1 * b2; acc[1][3] += a1 * b3;
        acc[2][0] += a2 * b0; acc[2][1] += a2 * b1; acc[2][2] += a2 * b2; acc[2][3] += a2 * b3;
        acc[3][0] += a3 * b0; acc[3][1] += a3 * b1; acc[3][2] += a3 * b2; acc[3][3] += a3 * b3;
    }
#pragma unroll
    for (int i = 0; i < 4; i++) {
        int n = n0 + tn * 4 + i;
        float4 w4;
        w4.x = acc[i][0]; w4.y = acc[i][1]; w4.z = acc[i][2]; w4.w = acc[i][3];
        *(float4*)(A + ((size_t)tb * NN + n) * CC + h * DH + te * 4) = w4;
    }
}

// ---------------- host orchestration ----------------
extern "C" void kernel_launch(void* const* d_in, const int* in_sizes, int n_in,
                              void* d_out, int out_size) {
    const float* x   = (const float*)d_in[0];
    const float* w1  = (const float*)d_in[1];
    const float* dw  = (const float*)d_in[2];
    const float* pw  = (const float*)d_in[3];
    const float* b1w = (const float*)d_in[4];
    const float* b1b = (const float*)d_in[5];
    const float* b1m = (const float*)d_in[6];
    const float* b1v = (const float*)d_in[7];
    const float* b2w = (const float*)d_in[8];
    const float* b2b = (const float*)d_in[9];
    const float* b2m = (const float*)d_in[10];
    const float* b2v = (const float*)d_in[11];
    const float* b3w = (const float*)d_in[12];
    const float* b3b = (const float*)d_in[13];
    const float* b3m = (const float*)d_in[14];
    const float* b3v = (const float*)d_in[15];
    const float* vth = (const float*)d_in[16];
    float* out = (float*)d_out;

    cudaFuncSetAttribute(conv_mma_kernel, cudaFuncAttributeMaxDynamicSharedMemorySize, SMEM_BYTES);

    float *PAD3, *BR3, *DWT, *KVP, *KV;
    __half *XS, *AS, *DWH3, *DW63, *QKVh, *WH, *W6;
    cudaGetSymbolAddress((void**)&XS,   g_XS);
    cudaGetSymbolAddress((void**)&PAD3, g_PAD3);
    cudaGetSymbolAddress((void**)&DWH3, g_DWH3);
    cudaGetSymbolAddress((void**)&DW63, g_DW63);
    cudaGetSymbolAddress((void**)&BR3,  g_BR3);
    cudaGetSymbolAddress((void**)&QKVh, g_QKVh);
    cudaGetSymbolAddress((void**)&AS,   g_AS);
    cudaGetSymbolAddress((void**)&WH,   g_WH);
    cudaGetSymbolAddress((void**)&W6,   g_W6);
    cudaGetSymbolAddress((void**)&DWT,  g_DWT);
    cudaGetSymbolAddress((void**)&KVP,  g_KVP);
    cudaGetSymbolAddress((void**)&KV,   g_KV);

    const int athreads = 256;
    const int ablocks = (BCN + athreads - 1) / athreads;

    // 0) weight prep (all 8 matrices) + dw transpose
    presplit_all_kernel<<<(8 * CCCC + 255) / 256, 256>>>(w1, pw, WH, W6);
    dwt_kernel<<<(4 * 9 * CC + 255) / 256, 256>>>(dw, DWT);

    // 1) alif on x: NCHW fp32 -> NHWC perm fp16 spikes
    alif_first_kernel<<<dim3(NN / 32, CC / 32, BB), dim3(32, 8)>>>(x, XS, vth);

    // 2) q/k/v branches, batched over 3 branches
    padfill_kernel<<<dim3(260, IMG * 3), CC>>>(PAD3, b1w, b1b, b1m, b1v);
    conv_mma_kernel<<<dim3(16, 3, IMG * 3), 512, SMEM_BYTES>>>(XS, XS, WH, W6, PAD3,
        b1w, b1b, b1m, b1v, nullptr, nullptr, nullptr, nullptr, 0, 0, PADSZ);
    dwconv_kernel<<<dim3(NN / 4, IMG, 3), dim3(96, 4)>>>(PAD3, DWT, DWH3, DW63);
    conv_mma_kernel<<<dim3(16, 3, IMG * 3), 512, SMEM_BYTES>>>(DWH3, DW63,
        WH + 4 * (size_t)CCCC, W6 + 4 * (size_t)CCCC, BR3,
        b2w, b2b, b2m, b2v, b3w, b3b, b3m, b3v, 1, IMGNNC, IMGNNC);
    alif_qkv_kernel<<<dim3(ablocks, 3), athreads>>>(BR3, QKVh, vth);

    // 3) linear attention (fp32 math, fp16 spike storage)
    kv_kernel<<<dim3(4, TT * BB * HEADS), 256>>>(QKVh + IMGNNC, QKVh + 2 * IMGNNC, KVP);
    kvred_kernel<<<(TT * BB * HEADS * DH * DH + 255) / 256, 256>>>(KVP, KV);
    av_kernel<<<dim3(64, TT * BB * HEADS), 256>>>(QKVh, KV, BR3);
    alif_f16p_kernel<<<ablocks, athreads>>>(BR3, AS, vth, 4);

    // 4) final branch (index 3) -> d_out (NCHW); pointers pre-offset, br=0
    padfill_kernel<<<dim3(260, IMG), CC>>>(PAD3, b1w + 3 * CC, b1b + 3 * CC, b1m + 3 * CC, b1v + 3 * CC);
    conv_mma_kernel<<<dim3(16, 3, IMG), 512, SMEM_BYTES>>>(AS, AS,
        WH + 3 * (size_t)CCCC, W6 + 3 * (size_t)CCCC, PAD3,
        b1w + 3 * CC, b1b + 3 * CC, b1m + 3 * CC, b1v + 3 * CC,
        nullptr, nullptr, nullptr, nullptr, 0, 0, 0);
    dwconv_kernel<<<dim3(NN / 4, IMG, 1), dim3(96, 4)>>>(PAD3, DWT + 3 * 9 * CC, DWH3, DW63);
    conv_mma_kernel<<<dim3(16, 3, IMG), 512, SMEM_BYTES>>>(DWH3, DW63,
        WH + 7 * (size_t)CCCC, W6 + 7 * (size_t)CCCC, out,
        b2w + 3 * CC, b2b + 3 * CC, b2m + 3 * CC, b2v + 3 * CC,
        b3w + 3 * CC, b3b + 3 * CC, b3m + 3 * CC, b3v + 3 * CC, 2, 0, 0);
}

// round 13
// speedup vs baseline: 2.4171x; 1.0230x over previous
#include <cuda_runtime.h>
#include <cuda_fp16.h>
#include <cstdint>
#include <cstddef>

#define TT 4
#define BB 4
#define CC 384
#define NN 4096
#define IMG 16
#define BCN (BB*CC*NN)
#define IMGNNC ((size_t)IMG*NN*CC)
#define PADSZ  ((size_t)IMG*PADW*PADW*CC)
#define CCCC (CC*CC)
#define HEADS 6
#define DH 64
#define PADW 66
#define EPS 1e-5f

// ---------------- scratch (static device globals) ----------------
__device__ __align__(256) __half g_XS  [IMG*NN*CC];
__device__ __align__(256) float  g_PAD3[3*IMG*PADW*PADW*CC];
__device__ __align__(256) __half g_DWH3[3*IMG*NN*CC];
__device__ __align__(256) __half g_DW63[3*IMG*NN*CC];
__device__ __align__(256) float  g_BR3 [3*IMG*NN*CC];
__device__ __align__(256) __half g_QKVh[3*IMG*NN*CC];
__device__ __align__(256) __half g_AS  [IMG*NN*CC];
__device__ __align__(256) __half g_WH  [8*CC*CC];
__device__ __align__(256) __half g_W6  [8*CC*CC];
__device__ __align__(256) float  g_DWT [4*9*CC];
__device__ __align__(256) float  g_KVP [4*TT*BB*HEADS*DH*DH];
__device__ __align__(256) float  g_KV  [TT*BB*HEADS*DH*DH];

__device__ __forceinline__ void mmaf16(float* c, uint32_t a0, uint32_t a1, uint32_t a2, uint32_t a3,
                                       uint32_t b0, uint32_t b1) {
    asm volatile("mma.sync.aligned.m16n8k16.row.col.f32.f16.f16.f32 "
                 "{%0,%1,%2,%3}, {%4,%5,%6,%7}, {%8,%9}, {%0,%1,%2,%3};"
                 : "+f"(c[0]), "+f"(c[1]), "+f"(c[2]), "+f"(c[3])
                 : "r"(a0), "r"(a1), "r"(a2), "r"(a3), "r"(b0), "r"(b1));
}
__device__ __forceinline__ uint32_t h2s6(uint32_t x) {
    uint32_t d;
    asm("mul.rn.f16x2 %0, %1, %2;" : "=r"(d) : "r"(x), "r"(0x24002400u));
    return d;
}
__device__ __forceinline__ void cp16(uint32_t dst, const void* src) {
    asm volatile("cp.async.cg.shared.global [%0], [%1], 16;" :: "r"(dst), "l"(src));
}
#define CP_COMMIT() asm volatile("cp.async.commit_group;" ::: "memory")
#define CP_WAIT0()  asm volatile("cp.async.wait_group 0;" ::: "memory")
#define CP_WAIT1()  asm volatile("cp.async.wait_group 1;" ::: "memory")
__device__ __forceinline__ uint32_t s2u(const void* p) {
    uint32_t a;
    asm("{ .reg .u64 t; cvta.to.shared.u64 t, %1; cvt.u32.u64 %0, t; }" : "=r"(a) : "l"(p));
    return a;
}
__device__ __forceinline__ int perm32(int c) {
    int ch = c & ~31, r = c & 31;
    return ch + ((r & 7) >> 1) * 8 + ((r >> 4) & 1) * 4 + ((r >> 3) & 1) * 2 + (r & 1);
}

// ---- smem layout (bytes): 3 stages of [AH 16K | A6 16K | WH 8K | W6 8K]
#define AH_B 0
#define A6_B 16384
#define WH_B 32768
#define W6_B 40960
#define STAGE_B 49152
#define NSTAGE 3
#define SCL_F 36864
#define SBS_F 36992
#define SMEM_BYTES 148480

// ---------------- conv1x1: 8 warps, warp tile 64x64, streamed W6/A6 ----------------
// CTA 256(M) x 128(N), K=384 in 12 chunks of 32. grid (16, 3, NBR*IMG).
// mode 0: binary A (2 passes) -> PAD interior; 1: hi/lo A (3 passes) -> NHWC; 2: -> NCHW.
__global__ void __launch_bounds__(256, 1)
conv_mma_kernel(const __half* __restrict__ AHg, const __half* __restrict__ A6g,
                const __half* __restrict__ WHg, const __half* __restrict__ W6g,
                float* __restrict__ OUT,
                const float* __restrict__ wA, const float* __restrict__ bA,
                const float* __restrict__ mA, const float* __restrict__ vA,
                const float* __restrict__ wB, const float* __restrict__ bB2,
                const float* __restrict__ mB, const float* __restrict__ vB,
                int mode, size_t aBrStride, size_t oBrStride) {
    extern __shared__ char smem[];
    float* smf = (float*)smem;
    const int tx = threadIdx.x;
    const int wid = tx >> 5, lane = tx & 31;
    const int lr = lane >> 2, lc = lane & 3;
    const int wm = wid >> 1, wn = wid & 1;      // 4(m) x 2(n); warp tile 64x64
    const int br  = blockIdx.z >> 4;
    const int img = blockIdx.z & 15;
    const int p0 = blockIdx.x * 256;
    const int n0 = blockIdx.y * 128;
    const bool dense = (mode != 0);
    AHg += (size_t)br * aBrStride;
    A6g += (size_t)br * aBrStride;
    WHg += (size_t)br * CCCC;
    W6g += (size_t)br * CCCC;
    OUT += (size_t)br * oBrStride;
    wA += br * CC; bA += br * CC; mA += br * CC; vA += br * CC;
    if (wB) { wB += br * CC; bB2 += br * CC; mB += br * CC; vB += br * CC; }

    const size_t arow0 = (size_t)img * NN + p0;
    const uint32_t smb = s2u(smem);

    if (tx < 128) {
        int o = n0 + tx;
        float s, bias;
        if (mode == 0) {
            float inv = wA[o] * rsqrtf(vA[o] + EPS);
            s = inv; bias = bA[o] - mA[o] * inv;
        } else {
            float s2 = wA[o] * rsqrtf(vA[o] + EPS);
            float t2 = bA[o] - mA[o] * s2;
            float s3 = wB[o] * rsqrtf(vB[o] + EPS);
            float t3 = bB2[o] - mB[o] * s3;
            s = s2 * s3; bias = t2 * s3 + t3;
        }
        smf[SCL_F + tx] = s;
        smf[SBS_F + tx] = bias;
    }

    auto issue_chunk = [&](int ch, int st) {
        int c0 = ch * 32;
        uint32_t stb = smb + (uint32_t)st * STAGE_B;
#pragma unroll
        for (int it = 0; it < 4; it++) {
            int u = tx + it * 256;
            int row = u >> 2, q = u & 3;
            cp16(stb + AH_B + row * 64 + q * 16, AHg + (arow0 + row) * CC + c0 + q * 8);
        }
        if (dense) {
#pragma unroll
            for (int it = 0; it < 4; it++) {
                int u = tx + it * 256;
                int row = u >> 2, q = u & 3;
                cp16(stb + A6_B + row * 64 + q * 16, A6g + (arow0 + row) * CC + c0 + q * 8);
            }
        }
#pragma unroll
        for (int it = 0; it < 2; it++) {
            int u = tx + it * 256;
            int row = u >> 2, q = u & 3;
            cp16(stb + WH_B + row * 64 + q * 16, WHg + (size_t)(n0 + row) * CC + c0 + q * 8);
            cp16(stb + W6_B + row * 64 + q * 16, W6g + (size_t)(n0 + row) * CC + c0 + q * 8);
        }
    };

    float acc[4][8][4];
#pragma unroll
    for (int a = 0; a < 4; a++)
#pragma unroll
        for (int b = 0; b < 8; b++)
#pragma unroll
            for (int c = 0; c < 4; c++) acc[a][b][c] = 0.0f;

    auto compute = [&](int st) {
        const char* Sb = smem + st * STAGE_B;
        uint4 Bh[8];
#pragma unroll
        for (int nt = 0; nt < 8; nt++) {
            int n = wn * 64 + nt * 8 + lr;
            Bh[nt] = *(const uint4*)(Sb + WH_B + n * 64 + lc * 16);
        }
        uint4 Ah0[4], Ah1[4];
#pragma unroll
        for (int mt = 0; mt < 4; mt++) {
            int r = wm * 64 + mt * 16 + lr;
            Ah0[mt] = *(const uint4*)(Sb + AH_B + r * 64 + lc * 16);
            Ah1[mt] = *(const uint4*)(Sb + AH_B + (r + 8) * 64 + lc * 16);
        }
        // pass 1: Ah * Wh
#pragma unroll
        for (int mt = 0; mt < 4; mt++)
#pragma unroll
            for (int nt = 0; nt < 8; nt++) {
                mmaf16(acc[mt][nt], Ah0[mt].x, Ah1[mt].x, Ah0[mt].y, Ah1[mt].y, Bh[nt].x, Bh[nt].y);
                mmaf16(acc[mt][nt], Ah0[mt].z, Ah1[mt].z, Ah0[mt].w, Ah1[mt].w, Bh[nt].z, Bh[nt].w);
            }
        // pass 2: (Ah*2^-6) * W6 (W6 streamed)
#pragma unroll
        for (int mt = 0; mt < 4; mt++) {
            Ah0[mt].x = h2s6(Ah0[mt].x); Ah0[mt].y = h2s6(Ah0[mt].y);
            Ah0[mt].z = h2s6(Ah0[mt].z); Ah0[mt].w = h2s6(Ah0[mt].w);
            Ah1[mt].x = h2s6(Ah1[mt].x); Ah1[mt].y = h2s6(Ah1[mt].y);
            Ah1[mt].z = h2s6(Ah1[mt].z); Ah1[mt].w = h2s6(Ah1[mt].w);
        }
#pragma unroll
        for (int nt = 0; nt < 8; nt++) {
            int n = wn * 64 + nt * 8 + lr;
            uint4 W6f = *(const uint4*)(Sb + W6_B + n * 64 + lc * 16);
#pragma unroll
            for (int mt = 0; mt < 4; mt++) {
                mmaf16(acc[mt][nt], Ah0[mt].x, Ah1[mt].x, Ah0[mt].y, Ah1[mt].y, W6f.x, W6f.y);
                mmaf16(acc[mt][nt], Ah0[mt].z, Ah1[mt].z, Ah0[mt].w, Ah1[mt].w, W6f.z, W6f.w);
            }
        }
        // pass 3 (dense): A6 * (Wh*2^-6) (A6 streamed)
        if (dense) {
#pragma unroll
            for (int nt = 0; nt < 8; nt++) {
                Bh[nt].x = h2s6(Bh[nt].x); Bh[nt].y = h2s6(Bh[nt].y);
                Bh[nt].z = h2s6(Bh[nt].z); Bh[nt].w = h2s6(Bh[nt].w);
            }
#pragma unroll
            for (int mt = 0; mt < 4; mt++) {
                int r = wm * 64 + mt * 16 + lr;
                uint4 A60 = *(const uint4*)(Sb + A6_B + r * 64 + lc * 16);
                uint4 A61 = *(const uint4*)(Sb + A6_B + (r + 8) * 64 + lc * 16);
#pragma unroll
                for (int nt = 0; nt < 8; nt++) {
                    mmaf16(acc[mt][nt], A60.x, A61.x, A60.y, A61.y, Bh[nt].x, Bh[nt].y);
                    mmaf16(acc[mt][nt], A60.z, A61.z, A60.w, A61.w, Bh[nt].z, Bh[nt].w);
                }
            }
        }
    };

    issue_chunk(0, 0); CP_COMMIT();
    issue_chunk(1, 1); CP_COMMIT();
    int st = 0;
    for (int ch = 0; ch < 12; ch++) {
        if (ch < 11) CP_WAIT1(); else CP_WAIT0();
        __syncthreads();
        compute(st);
        if (ch < 10) {
            int st2 = st + 2; if (st2 >= NSTAGE) st2 -= NSTAGE;
            issue_chunk(ch + 2, st2);
            CP_COMMIT();
        }
        if (++st == NSTAGE) st = 0;
    }
    __syncthreads();

    if (mode != 2) {
#pragma unroll
        for (int mt = 0; mt < 4; mt++) {
            int pa = p0 + wm * 64 + mt * 16 + lr;
            int pb = pa + 8;
#pragma unroll
            for (int nt = 0; nt < 8; nt++) {
                int ol = wn * 64 + nt * 8 + 2 * lc;
                float s0 = smf[SCL_F + ol], s1 = smf[SCL_F + ol + 1];
                float z0 = smf[SBS_F + ol], z1 = smf[SBS_F + ol + 1];
                float2 v0 = make_float2(acc[mt][nt][0] * s0 + z0, acc[mt][nt][1] * s1 + z1);
                float2 v1 = make_float2(acc[mt][nt][2] * s0 + z0, acc[mt][nt][3] * s1 + z1);
                if (mode == 0) {
                    int ra = (pa & 4095) >> 6, ca = pa & 63;
                    int rb = (pb & 4095) >> 6, cb = pb & 63;
                    *(float2*)(OUT + ((((size_t)img * PADW + ra + 1) * PADW + ca + 1) * CC) + n0 + ol) = v0;
                    *(float2*)(OUT + ((((size_t)img * PADW + rb + 1) * PADW + cb + 1) * CC) + n0 + ol) = v1;
                } else {
                    *(float2*)(OUT + ((size_t)img * NN + pa) * CC + n0 + ol) = v0;
                    *(float2*)(OUT + ((size_t)img * NN + pb) * CC + n0 + ol) = v1;
                }
            }
        }
    } else {
        float* T = smf + wid * (64 * 68);
#pragma unroll
        for (int mt = 0; mt < 4; mt++) {
            int mm = mt * 16 + lr;
#pragma unroll
            for (int nt = 0; nt < 8; nt++) {
                int nl = nt * 8 + 2 * lc;
                int ol = wn * 64 + nl;
                float s0 = smf[SCL_F + ol], s1 = smf[SCL_F + ol + 1];
                float z0 = smf[SBS_F + ol], z1 = smf[SBS_F + ol + 1];
                T[nl * 68 + mm]           = acc[mt][nt][0] * s0 + z0;
                T[(nl + 1) * 68 + mm]     = acc[mt][nt][1] * s1 + z1;
                T[nl * 68 + mm + 8]       = acc[mt][nt][2] * s0 + z0;
                T[(nl + 1) * 68 + mm + 8] = acc[mt][nt][3] * s1 + z1;
            }
        }
        __syncwarp();
#pragma unroll
        for (int ol = 0; ol < 64; ol++) {
            int o = n0 + wn * 64 + ol;
            float2 v = *(float2*)&T[ol * 68 + lane * 2];
            *(float2*)(OUT + ((size_t)img * CC + o) * NN + p0 + wm * 64 + lane * 2) = v;
        }
    }
}

// ---------------- presplit ALL 8 weight matrices ----------------
__global__ void presplit_all_kernel(const float* __restrict__ w1, const float* __restrict__ pw,
                                    __half* __restrict__ WHo, __half* __restrict__ W6o) {
    int idx = blockIdx.x * 256 + threadIdx.x;
    if (idx >= 8 * CCCC) return;
    int m = idx / CCCC, e = idx % CCCC;
    int o = e / CC, c = e % CC;
    const float* src = (m < 4) ? (w1 + (size_t)m * CCCC) : (pw + (size_t)(m - 4) * CCCC);
    float v = src[e];
    __half h = __float2half_rn(v);
    float r = (v - __half2float(h)) * 64.0f;
    WHo[(size_t)m * CCCC + (size_t)o * CC + perm32(c)] = h;
    W6o[(size_t)m * CCCC + (size_t)o * CC + perm32(c)] = __float2half_rn(r);
}

__global__ void dwt_kernel(const float* __restrict__ dw, float* __restrict__ dwt) {
    int idx = blockIdx.x * 256 + threadIdx.x;
    if (idx >= 4 * 9 * CC) return;
    int br = idx / (9 * CC), rr = idx % (9 * CC);
    int k = rr / CC, c = rr % CC;
    dwt[idx] = dw[(size_t)br * CC * 9 + c * 9 + k];
}

// ---------------- ALIF first ----------------
__global__ void alif_first_kernel(const float* __restrict__ in, __half* __restrict__ out,
                                  const float* __restrict__ vth_ptr) {
    __shared__ float s[32][33];
    int tx = threadIdx.x, ty = threadIdx.y;
    int n0 = blockIdx.x * 32;
    int c0 = blockIdx.y * 32;
    int b = blockIdx.z;
    float vth = vth_ptr[0];
    int cp = c0 + perm32(tx);
    float v[4] = {0.f, 0.f, 0.f, 0.f};
#pragma unroll
    for (int t = 0; t < TT; t++) {
#pragma unroll
        for (int k = 0; k < 4; k++) {
            int c = c0 + ty + 8 * k;
            float xv = in[(((size_t)(t * BB + b) * CC + c) * NN) + n0 + tx];
            v[k] = v[k] + (xv - v[k]) * 0.5f;
            s[ty + 8 * k][tx] = (v[k] - vth >= 0.0f) ? 1.0f : 0.0f;
        }
        __syncthreads();
#pragma unroll
        for (int k = 0; k < 4; k++) {
            int n = n0 + ty + 8 * k;
            out[((size_t)(t * BB + b) * NN + n) * CC + cp] = __float2half_rn(s[tx][ty + 8 * k]);
        }
        __syncthreads();
    }
}

// ---------------- ALIF q/k/v batched ----------------
__global__ void alif_qkv_kernel(const float* __restrict__ in, __half* __restrict__ out,
                                const float* __restrict__ vth_ptr) {
    int j = blockIdx.x * blockDim.x + threadIdx.x;
    if (j >= BCN) return;
    int br = blockIdx.y;
    const float* ib = in + (size_t)br * IMGNNC;
    __half* ob = out + (size_t)br * IMGNNC;
    float vth = vth_ptr[1 + br];
    float v = 0.0f;
#pragma unroll
    for (int t = 0; t < TT; t++) {
        float x = ib[(size_t)j + (size_t)t * BCN];
        v = v + (x - v) * 0.5f;
        ob[(size_t)j + (size_t)t * BCN] = __float2half_rn((v - vth >= 0.0f) ? 1.0f : 0.0f);
    }
}

// ---------------- pad border fill ----------------
__global__ void padfill_kernel(float* __restrict__ pad,
                               const float* __restrict__ bw, const float* __restrict__ bb,
                               const float* __restrict__ bm, const float* __restrict__ bv) {
    int t = blockIdx.x;
    int br = blockIdx.y >> 4, img = blockIdx.y & 15;
    int c = threadIdx.x;
    float inv = bw[br * CC + c] * rsqrtf(bv[br * CC + c] + EPS);
    float pv = bb[br * CC + c] - bm[br * CC + c] * inv;
    int r, cl;
    if      (t < 66)  { r = 0;           cl = t;        }
    else if (t < 132) { r = 65;          cl = t - 66;   }
    else if (t < 196) { r = t - 132 + 1; cl = 0;        }
    else              { r = t - 196 + 1; cl = 65;       }
    pad[(size_t)br * PADSZ + (((size_t)img * PADW + r) * PADW + cl) * CC + c] = pv;
}

// ---------------- depthwise 3x3 vectorized ----------------
__global__ void dwconv_kernel(const float* __restrict__ pad, const float* __restrict__ dwt,
                              __half* __restrict__ outH, __half* __restrict__ outL) {
    int br = blockIdx.z;
    int img = blockIdx.y;
    int p = blockIdx.x * 4 + threadIdx.y;
    int c4 = threadIdx.x * 4;
    int r = p >> 6, cl = p & 63;
    const float* base = pad + (size_t)br * PADSZ + (((size_t)img * PADW + r) * PADW + cl) * CC + c4;
    const float* wt = dwt + (size_t)br * 9 * CC + c4;
    float4 acc = make_float4(0.f, 0.f, 0.f, 0.f);
#pragma unroll
    for (int i = 0; i < 3; i++)
#pragma unroll
        for (int j = 0; j < 3; j++) {
            float4 xv = *(const float4*)(base + (size_t)(i * PADW + j) * CC);
            float4 wv = *(const float4*)(wt + (i * 3 + j) * CC);
            acc.x += wv.x * xv.x; acc.y += wv.y * xv.y;
            acc.z += wv.z * xv.z; acc.w += wv.w * xv.w;
        }
    __half h0 = __float2half_rn(acc.x), h1 = __float2half_rn(acc.y);
    __half h2 = __float2half_rn(acc.z), h3 = __float2half_rn(acc.w);
    __half l0 = __float2half_rn((acc.x - __half2float(h0)) * 64.0f);
    __half l1 = __float2half_rn((acc.y - __half2float(h1)) * 64.0f);
    __half l2 = __float2half_rn((acc.z - __half2float(h2)) * 64.0f);
    __half l3 = __float2half_rn((acc.w - __half2float(h3)) * 64.0f);
    int ch = c4 & ~31, r32 = c4 & 31;
    int pos = ch + ((r32 & 7) >> 1) * 8 + ((r32 >> 4) & 1) * 4 + ((r32 >> 3) & 1) * 2;
    size_t off = (size_t)br * IMGNNC + ((size_t)img * NN + p) * CC;
    *(__half2*)(outH + off + pos)     = __halves2half2(h0, h1);
    *(__half2*)(outH + off + pos + 8) = __halves2half2(h2, h3);
    *(__half2*)(outL + off + pos)     = __halves2half2(l0, l1);
    *(__half2*)(outL + off + pos + 8) = __halves2half2(l2, l3);
}

// ---------------- kv partial ----------------
__global__ void kv_kernel(const __half* __restrict__ K, const __half* __restrict__ V,
                          float* __restrict__ KVP) {
    int seg = blockIdx.x;
    int tbh = blockIdx.y;
    int tb = tbh / HEADS, h = tbh % HEADS;
    __shared__ float Ks[64][65];
    __shared__ float Vs[64][65];
    int tx = threadIdx.x;
    int td = tx >> 4, te = tx & 15;
    const __half* Kb = K + (size_t)tb * NN * CC + h * DH;
    const __half* Vb = V + (size_t)tb * NN * CC + h * DH;
    float acc[4][4];
#pragma unroll
    for (int i = 0; i < 4; i++)
#pragma unroll
        for (int j = 0; j < 4; j++) acc[i][j] = 0.0f;

    for (int n0 = seg * 1024; n0 < (seg + 1) * 1024; n0 += 64) {
#pragma unroll
        for (int u = 0; u < 16; u++) {
            int e = tx + u * 256;
            int n = e >> 6, d = e & 63;
            Ks[n][d] = __half2float(Kb[(size_t)(n0 + n) * CC + d]);
            Vs[n][d] = __half2float(Vb[(size_t)(n0 + n) * CC + d]);
        }
        __syncthreads();
#pragma unroll
        for (int n = 0; n < 64; n++) {
            float a0 = Ks[n][td * 4 + 0], a1 = Ks[n][td * 4 + 1];
            float a2 = Ks[n][td * 4 + 2], a3 = Ks[n][td * 4 + 3];
            float b0 = Vs[n][te * 4 + 0], b1 = Vs[n][te * 4 + 1];
            float b2 = Vs[n][te * 4 + 2], b3 = Vs[n][te * 4 + 3];
            acc[0][0] += a0 * b0; acc[0][1] += a0 * b1; acc[0][2] += a0 * b2; acc[0][3] += a0 * b3;
            acc[1][0] += a1 * b0; acc[1][1] += a1 * b1; acc[1][2] += a1 * b2; acc[1][3] += a1 * b3;
            acc[2][0] += a2 * b0; acc[2][1] += a2 * b1; acc[2][2] += a2 * b2; acc[2][3] += a2 * b3;
            acc[3][0] += a3 * b0; acc[3][1] += a3 * b1; acc[3][2] += a3 * b2; acc[3][3] += a3 * b3;
        }
        __syncthreads();
    }
#pragma unroll
    for (int i = 0; i < 4; i++)
#pragma unroll
        for (int j = 0; j < 4; j++)
            KVP[((size_t)seg * (TT * BB * HEADS) + tbh) * (DH * DH) + (td * 4 + i) * DH + te * 4 + j] =
                acc[i][j];
}

__global__ void kvred_kernel(const float* __restrict__ KVP, float* __restrict__ KV) {
    int idx = blockIdx.x * blockDim.x + threadIdx.x;
    const int tot = TT * BB * HEADS * DH * DH;
    if (idx >= tot) return;
    float s = 0.f;
#pragma unroll
    for (int g = 0; g < 4; g++) s += KVP[(size_t)g * tot + idx];
    KV[idx] = s;
}

// ---------------- FUSED av + final alif: loops all T, scans membrane in regs ----------------
// grid (64 n-tiles, B*HEADS); block 256. Writes fp16 perm spikes directly to AS.
__global__ void avalif_kernel(const __half* __restrict__ Q, const float* __restrict__ KV,
                              __half* __restrict__ AS, const float* __restrict__ vth_ptr) {
    int nt = blockIdx.x;
    int bh = blockIdx.y;
    int b = bh / HEADS, h = bh % HEADS;
    __shared__ float kvs[64][65];
    __shared__ float Qs[64][65];
    int tx = threadIdx.x;
    int tn = tx >> 4, te = tx & 15;
    int n0 = nt * 64;
    float vth = vth_ptr[4];
    float vmem[4][4];
#pragma unroll
    for (int i = 0; i < 4; i++)
#pragma unroll
        for (int j = 0; j < 4; j++) vmem[i][j] = 0.0f;

    // perm write position for c4 = h*64 + te*4
    int c4 = h * DH + te * 4;
    int chb = c4 & ~31, r32 = c4 & 31;
    int pos = chb + ((r32 & 7) >> 1) * 8 + ((r32 >> 4) & 1) * 4 + ((r32 >> 3) & 1) * 2;

    for (int t = 0; t < TT; t++) {
        int tb = t * BB + b;
        int tbh = tb * HEADS + h;
        const __half* Qb = Q + (size_t)tb * NN * CC + h * DH;
#pragma unroll
        for (int u = 0; u < 16; u++) {
            int e = tx + u * 256;
            int r = e >> 6, x = e & 63;
            kvs[r][x] = KV[(size_t)tbh * DH * DH + r * DH + x];
            Qs[r][x] = __half2float(Qb[(size_t)(n0 + r) * CC + x]);
        }
        __syncthreads();
        float acc[4][4];
#pragma unroll
        for (int i = 0; i < 4; i++)
#pragma unroll
            for (int j = 0; j < 4; j++) acc[i][j] = 0.0f;
#pragma unroll
        for (int d = 0; d < 64; d++) {
            float a0 = Qs[tn * 4 + 0][d], a1 = Qs[tn * 4 + 1][d];
            float a2 = Qs[tn * 4 + 2][d], a3 = Qs[tn * 4 + 3][d];
            float b0 = kvs[d][te * 4 + 0], b1 = kvs[d][te * 4 + 1];
            float b2 = kvs[d][te * 4 + 2], b3 = kvs[d][te * 4 + 3];
            acc[0][0] += a0 * b0; acc[0][1] += a0 * b1; acc[0][2] += a0 * b2; acc[0][3] += a0 * b3;
            acc[1][0] += a1 * b0; acc[1][1] += a1 * b1; acc[1][2] += a1 * b2; acc[1][3] += a1 * b3;
            acc[2][0] += a2 * b0; acc[2][1] += a2 * b1; acc[2][2] += a2 * b2; acc[2][3] += a2 * b3;
            acc[3][0] += a3 * b0; acc[3][1] += a3 * b1; acc[3][2] += a3 * b2; acc[3][3] += a3 * b3;
        }
        // membrane scan + spike write (fp16 perm)
#pragma unroll
        for (int i = 0; i < 4; i++) {
            int n = n0 + tn * 4 + i;
            __half sp[4];
#pragma unroll
            for (int j = 0; j < 4; j++) {
                vmem[i][j] = vmem[i][j] + (acc[i][j] - vmem[i][j]) * 0.5f;
                sp[j] = __float2half_rn((vmem[i][j] - vth >= 0.0f) ? 1.0f : 0.0f);
            }
            size_t base = ((size_t)tb * NN + n) * CC;
            *(__half2*)(AS + base + pos)     = __halves2half2(sp[0], sp[1]);
            *(__half2*)(AS + base + pos + 8) = __halves2half2(sp[2], sp[3]);
        }
        __syncthreads();
    }
}

// ---------------- host orchestration ----------------
extern "C" void kernel_launch(void* const* d_in, const int* in_sizes, int n_in,
                              void* d_out, int out_size) {
    const float* x   = (const float*)d_in[0];
    const float* w1  = (const float*)d_in[1];
    const float* dw  = (const float*)d_in[2];
    const float* pw  = (const float*)d_in[3];
    const float* b1w = (const float*)d_in[4];
    const float* b1b = (const float*)d_in[5];
    const float* b1m = (const float*)d_in[6];
    const float* b1v = (const float*)d_in[7];
    const float* b2w = (const float*)d_in[8];
    const float* b2b = (const float*)d_in[9];
    const float* b2m = (const float*)d_in[10];
    const float* b2v = (const float*)d_in[11];
    const float* b3w = (const float*)d_in[12];
    const float* b3b = (const float*)d_in[13];
    const float* b3m = (const float*)d_in[14];
    const float* b3v = (const float*)d_in[15];
    const float* vth = (const float*)d_in[16];
    float* out = (float*)d_out;

    cudaFuncSetAttribute(conv_mma_kernel, cudaFuncAttributeMaxDynamicSharedMemorySize, SMEM_BYTES);

    float *PAD3, *BR3, *DWT, *KVP, *KV;
    __half *XS, *AS, *DWH3, *DW63, *QKVh, *WH, *W6;
    cudaGetSymbolAddress((void**)&XS,   g_XS);
    cudaGetSymbolAddress((void**)&PAD3, g_PAD3);
    cudaGetSymbolAddress((void**)&DWH3, g_DWH3);
    cudaGetSymbolAddress((void**)&DW63, g_DW63);
    cudaGetSymbolAddress((void**)&BR3,  g_BR3);
    cudaGetSymbolAddress((void**)&QKVh, g_QKVh);
    cudaGetSymbolAddress((void**)&AS,   g_AS);
    cudaGetSymbolAddress((void**)&WH,   g_WH);
    cudaGetSymbolAddress((void**)&W6,   g_W6);
    cudaGetSymbolAddress((void**)&DWT,  g_DWT);
    cudaGetSymbolAddress((void**)&KVP,  g_KVP);
    cudaGetSymbolAddress((void**)&KV,   g_KV);

    const int athreads = 256;
    const int ablocks = (BCN + athreads - 1) / athreads;

    // 0) weight prep
    presplit_all_kernel<<<(8 * CCCC + 255) / 256, 256>>>(w1, pw, WH, W6);
    dwt_kernel<<<(4 * 9 * CC + 255) / 256, 256>>>(dw, DWT);

    // 1) alif on x
    alif_first_kernel<<<dim3(NN / 32, CC / 32, BB), dim3(32, 8)>>>(x, XS, vth);

    // 2) q/k/v branches batched
    padfill_kernel<<<dim3(260, IMG * 3), CC>>>(PAD3, b1w, b1b, b1m, b1v);
    conv_mma_kernel<<<dim3(16, 3, IMG * 3), 256, SMEM_BYTES>>>(XS, XS, WH, W6, PAD3,
        b1w, b1b, b1m, b1v, nullptr, nullptr, nullptr, nullptr, 0, 0, PADSZ);
    dwconv_kernel<<<dim3(NN / 4, IMG, 3), dim3(96, 4)>>>(PAD3, DWT, DWH3, DW63);
    conv_mma_kernel<<<dim3(16, 3, IMG * 3), 256, SMEM_BYTES>>>(DWH3, DW63,
        WH + 4 * (size_t)CCCC, W6 + 4 * (size_t)CCCC, BR3,
        b2w, b2b, b2m, b2v, b3w, b3b, b3m, b3v, 1, IMGNNC, IMGNNC);
    alif_qkv_kernel<<<dim3(ablocks, 3), athreads>>>(BR3, QKVh, vth);

    // 3) attention: kv + fused av/alif
    kv_kernel<<<dim3(4, TT * BB * HEADS), 256>>>(QKVh + IMGNNC, QKVh + 2 * IMGNNC, KVP);
    kvred_kernel<<<(TT * BB * HEADS * DH * DH + 255) / 256, 256>>>(KVP, KV);
    avalif_kernel<<<dim3(64, BB * HEADS), 256>>>(QKVh, KV, AS, vth);

    // 4) final branch -> d_out
    padfill_kernel<<<dim3(260, IMG), CC>>>(PAD3, b1w + 3 * CC, b1b + 3 * CC, b1m + 3 * CC, b1v + 3 * CC);
    conv_mma_kernel<<<dim3(16, 3, IMG), 256, SMEM_BYTES>>>(AS, AS,
        WH + 3 * (size_t)CCCC, W6 + 3 * (size_t)CCCC, PAD3,
        b1w + 3 * CC, b1b + 3 * CC, b1m + 3 * CC, b1v + 3 * CC,
        nullptr, nullptr, nullptr, nullptr, 0, 0, 0);
    dwconv_kernel<<<dim3(NN / 4, IMG, 1), dim3(96, 4)>>>(PAD3, DWT + 3 * 9 * CC, DWH3, DW63);
    conv_mma_kernel<<<dim3(16, 3, IMG), 256, SMEM_BYTES>>>(DWH3, DW63,
        WH + 7 * (size_t)CCCC, W6 + 7 * (size_t)CCCC, out,
        b2w + 3 * CC, b2b + 3 * CC, b2m + 3 * CC, b2v + 3 * CC,
        b3w + 3 * CC, b3b + 3 * CC, b3m + 3 * CC, b3v + 3 * CC, 2, 0, 0);
}

// round 14
// speedup vs baseline: 2.5473x; 1.0539x over previous
#include <cuda_runtime.h>
#include <cuda_fp16.h>
#include <cstdint>
#include <cstddef>

#define TT 4
#define BB 4
#define CC 384
#define NN 4096
#define IMG 16
#define BCN (BB*CC*NN)
#define IMGNNC ((size_t)IMG*NN*CC)
#define PADSZ  ((size_t)IMG*PADW*PADW*CC)
#define CCCC (CC*CC)
#define HEADS 6
#define DH 64
#define PADW 66
#define EPS 1e-5f

// ---------------- scratch (static device globals) ----------------
__device__ __align__(256) __half g_XS  [IMG*NN*CC];          // FILTERED spikes of x (perm)
__device__ __align__(256) float  g_PAD3[3*IMG*PADW*PADW*CC];
__device__ __align__(256) __half g_DWH3[3*IMG*NN*CC];
__device__ __align__(256) __half g_DW63[3*IMG*NN*CC];
__device__ __align__(256) __half g_QKVh[3*IMG*NN*CC];        // q/k/v spikes fp16 (natural)
__device__ __align__(256) __half g_AS  [IMG*NN*CC];          // attention spikes (perm)
__device__ __align__(256) __half g_WH  [8*CC*CC];
__device__ __align__(256) __half g_W6  [8*CC*CC];
__device__ __align__(256) float  g_DWT [4*9*CC];
__device__ __align__(256) float  g_KVP [4*TT*BB*HEADS*DH*DH];
__device__ __align__(256) float  g_KV  [TT*BB*HEADS*DH*DH];

__device__ __forceinline__ void mmaf16(float* c, uint32_t a0, uint32_t a1, uint32_t a2, uint32_t a3,
                                       uint32_t b0, uint32_t b1) {
    asm volatile("mma.sync.aligned.m16n8k16.row.col.f32.f16.f16.f32 "
                 "{%0,%1,%2,%3}, {%4,%5,%6,%7}, {%8,%9}, {%0,%1,%2,%3};"
                 : "+f"(c[0]), "+f"(c[1]), "+f"(c[2]), "+f"(c[3])
                 : "r"(a0), "r"(a1), "r"(a2), "r"(a3), "r"(b0), "r"(b1));
}
__device__ __forceinline__ uint32_t h2s6(uint32_t x) {
    uint32_t d;
    asm("mul.rn.f16x2 %0, %1, %2;" : "=r"(d) : "r"(x), "r"(0x24002400u));
    return d;
}
__device__ __forceinline__ void cp16(uint32_t dst, const void* src) {
    asm volatile("cp.async.cg.shared.global [%0], [%1], 16;" :: "r"(dst), "l"(src));
}
#define CP_COMMIT() asm volatile("cp.async.commit_group;" ::: "memory")
#define CP_WAIT0()  asm volatile("cp.async.wait_group 0;" ::: "memory")
#define CP_WAIT1()  asm volatile("cp.async.wait_group 1;" ::: "memory")
__device__ __forceinline__ uint32_t s2u(const void* p) {
    uint32_t a;
    asm("{ .reg .u64 t; cvta.to.shared.u64 t, %1; cvt.u32.u64 %0, t; }" : "=r"(a) : "l"(p));
    return a;
}
__device__ __forceinline__ int perm32(int c) {
    int ch = c & ~31, r = c & 31;
    return ch + ((r & 7) >> 1) * 8 + ((r >> 4) & 1) * 4 + ((r >> 3) & 1) * 2 + (r & 1);
}
__device__ __constant__ float c_ST[4] = {0.5f, 0.75f, 0.875f, 0.9375f};

// ---- smem layout (bytes): 3 stages of [AH 16K | A6 16K | WH 8K | W6 8K]
#define AH_B 0
#define A6_B 16384
#define WH_B 32768
#define W6_B 40960
#define STAGE_B 49152
#define NSTAGE 3
#define SCL_F 36864
#define SBS_F 36992
#define SMEM_BYTES 148480

// ---------------- conv1x1: 8 warps, warp tile 64x64, streamed W6/A6 ----------------
// CTA 256(M) x 128(N), K=384 in 12 chunks. grid (16, 3, NBR*IMG).
// mode 0: binary/filtered A (2 passes) -> PAD interior (bias*st if scaled)
// mode 2: hi/lo A (3 passes) -> NCHW fp32 (d_out)
// mode 3: hi/lo A (3 passes) -> fused bn + membrane-threshold -> fp16 spikes NHWC
__global__ void __launch_bounds__(256, 1)
conv_mma_kernel(const __half* __restrict__ AHg, const __half* __restrict__ A6g,
                const __half* __restrict__ WHg, const __half* __restrict__ W6g,
                float* __restrict__ OUT,
                const float* __restrict__ wA, const float* __restrict__ bA,
                const float* __restrict__ mA, const float* __restrict__ vA,
                const float* __restrict__ wB, const float* __restrict__ bB2,
                const float* __restrict__ mB, const float* __restrict__ vB,
                int mode, size_t aBrStride, size_t oBrStride,
                const float* __restrict__ vthp, int scaled) {
    extern __shared__ char smem[];
    float* smf = (float*)smem;
    const int tx = threadIdx.x;
    const int wid = tx >> 5, lane = tx & 31;
    const int lr = lane >> 2, lc = lane & 3;
    const int wm = wid >> 1, wn = wid & 1;
    const int br  = blockIdx.z >> 4;
    const int img = blockIdx.z & 15;
    const int p0 = blockIdx.x * 256;
    const int n0 = blockIdx.y * 128;
    const bool dense = (mode != 0);
    AHg += (size_t)br * aBrStride;
    A6g += (size_t)br * aBrStride;
    WHg += (size_t)br * CCCC;
    W6g += (size_t)br * CCCC;
    OUT += (size_t)br * oBrStride;
    wA += br * CC; bA += br * CC; mA += br * CC; vA += br * CC;
    if (wB) { wB += br * CC; bB2 += br * CC; mB += br * CC; vB += br * CC; }
    const float bscale = scaled ? c_ST[img >> 2] : 1.0f;
    const float vthv = vthp ? (vthp[1 + br]) : 0.0f;

    const size_t arow0 = (size_t)img * NN + p0;
    const uint32_t smb = s2u(smem);

    if (tx < 128) {
        int o = n0 + tx;
        float s, bias;
        if (mode == 0) {
            float inv = wA[o] * rsqrtf(vA[o] + EPS);
            s = inv; bias = (bA[o] - mA[o] * inv) * bscale;
        } else {
            float s2 = wA[o] * rsqrtf(vA[o] + EPS);
            float t2 = bA[o] - mA[o] * s2;
            float s3 = wB[o] * rsqrtf(vB[o] + EPS);
            float t3 = bB2[o] - mB[o] * s3;
            s = s2 * s3; bias = (t2 * s3 + t3) * bscale;
        }
        smf[SCL_F + tx] = s;
        smf[SBS_F + tx] = bias;
    }

    auto issue_chunk = [&](int ch, int st) {
        int c0 = ch * 32;
        uint32_t stb = smb + (uint32_t)st * STAGE_B;
#pragma unroll
        for (int it = 0; it < 4; it++) {
            int u = tx + it * 256;
            int row = u >> 2, q = u & 3;
            cp16(stb + AH_B + row * 64 + q * 16, AHg + (arow0 + row) * CC + c0 + q * 8);
        }
        if (dense) {
#pragma unroll
            for (int it = 0; it < 4; it++) {
                int u = tx + it * 256;
                int row = u >> 2, q = u & 3;
                cp16(stb + A6_B + row * 64 + q * 16, A6g + (arow0 + row) * CC + c0 + q * 8);
            }
        }
#pragma unroll
        for (int it = 0; it < 2; it++) {
            int u = tx + it * 256;
            int row = u >> 2, q = u & 3;
            cp16(stb + WH_B + row * 64 + q * 16, WHg + (size_t)(n0 + row) * CC + c0 + q * 8);
            cp16(stb + W6_B + row * 64 + q * 16, W6g + (size_t)(n0 + row) * CC + c0 + q * 8);
        }
    };

    float acc[4][8][4];
#pragma unroll
    for (int a = 0; a < 4; a++)
#pragma unroll
        for (int b = 0; b < 8; b++)
#pragma unroll
            for (int c = 0; c < 4; c++) acc[a][b][c] = 0.0f;

    auto compute = [&](int st) {
        const char* Sb = smem + st * STAGE_B;
        uint4 Bh[8];
#pragma unroll
        for (int nt = 0; nt < 8; nt++) {
            int n = wn * 64 + nt * 8 + lr;
            Bh[nt] = *(const uint4*)(Sb + WH_B + n * 64 + lc * 16);
        }
        uint4 Ah0[4], Ah1[4];
#pragma unroll
        for (int mt = 0; mt < 4; mt++) {
            int r = wm * 64 + mt * 16 + lr;
            Ah0[mt] = *(const uint4*)(Sb + AH_B + r * 64 + lc * 16);
            Ah1[mt] = *(const uint4*)(Sb + AH_B + (r + 8) * 64 + lc * 16);
        }
#pragma unroll
        for (int mt = 0; mt < 4; mt++)
#pragma unroll
            for (int nt = 0; nt < 8; nt++) {
                mmaf16(acc[mt][nt], Ah0[mt].x, Ah1[mt].x, Ah0[mt].y, Ah1[mt].y, Bh[nt].x, Bh[nt].y);
                mmaf16(acc[mt][nt], Ah0[mt].z, Ah1[mt].z, Ah0[mt].w, Ah1[mt].w, Bh[nt].z, Bh[nt].w);
            }
#pragma unroll
        for (int mt = 0; mt < 4; mt++) {
            Ah0[mt].x = h2s6(Ah0[mt].x); Ah0[mt].y = h2s6(Ah0[mt].y);
            Ah0[mt].z = h2s6(Ah0[mt].z); Ah0[mt].w = h2s6(Ah0[mt].w);
            Ah1[mt].x = h2s6(Ah1[mt].x); Ah1[mt].y = h2s6(Ah1[mt].y);
            Ah1[mt].z = h2s6(Ah1[mt].z); Ah1[mt].w = h2s6(Ah1[mt].w);
        }
#pragma unroll
        for (int nt = 0; nt < 8; nt++) {
            int n = wn * 64 + nt * 8 + lr;
            uint4 W6f = *(const uint4*)(Sb + W6_B + n * 64 + lc * 16);
#pragma unroll
            for (int mt = 0; mt < 4; mt++) {
                mmaf16(acc[mt][nt], Ah0[mt].x, Ah1[mt].x, Ah0[mt].y, Ah1[mt].y, W6f.x, W6f.y);
                mmaf16(acc[mt][nt], Ah0[mt].z, Ah1[mt].z, Ah0[mt].w, Ah1[mt].w, W6f.z, W6f.w);
            }
        }
        if (dense) {
#pragma unroll
            for (int nt = 0; nt < 8; nt++) {
                Bh[nt].x = h2s6(Bh[nt].x); Bh[nt].y = h2s6(Bh[nt].y);
                Bh[nt].z = h2s6(Bh[nt].z); Bh[nt].w = h2s6(Bh[nt].w);
            }
#pragma unroll
            for (int mt = 0; mt < 4; mt++) {
                int r = wm * 64 + mt * 16 + lr;
                uint4 A60 = *(const uint4*)(Sb + A6_B + r * 64 + lc * 16);
                uint4 A61 = *(const uint4*)(Sb + A6_B + (r + 8) * 64 + lc * 16);
#pragma unroll
                for (int nt = 0; nt < 8; nt++) {
                    mmaf16(acc[mt][nt], A60.x, A61.x, A60.y, A61.y, Bh[nt].x, Bh[nt].y);
                    mmaf16(acc[mt][nt], A60.z, A61.z, A60.w, A61.w, Bh[nt].z, Bh[nt].w);
                }
            }
        }
    };

    issue_chunk(0, 0); CP_COMMIT();
    issue_chunk(1, 1); CP_COMMIT();
    int st = 0;
    for (int ch = 0; ch < 12; ch++) {
        if (ch < 11) CP_WAIT1(); else CP_WAIT0();
        __syncthreads();
        compute(st);
        if (ch < 10) {
            int st2 = st + 2; if (st2 >= NSTAGE) st2 -= NSTAGE;
            issue_chunk(ch + 2, st2);
            CP_COMMIT();
        }
        if (++st == NSTAGE) st = 0;
    }
    __syncthreads();

    if (mode == 0) {
#pragma unroll
        for (int mt = 0; mt < 4; mt++) {
            int pa = p0 + wm * 64 + mt * 16 + lr;
            int pb = pa + 8;
#pragma unroll
            for (int nt = 0; nt < 8; nt++) {
                int ol = wn * 64 + nt * 8 + 2 * lc;
                float s0 = smf[SCL_F + ol], s1 = smf[SCL_F + ol + 1];
                float z0 = smf[SBS_F + ol], z1 = smf[SBS_F + ol + 1];
                float2 v0 = make_float2(acc[mt][nt][0] * s0 + z0, acc[mt][nt][1] * s1 + z1);
                float2 v1 = make_float2(acc[mt][nt][2] * s0 + z0, acc[mt][nt][3] * s1 + z1);
                int ra = (pa & 4095) >> 6, ca = pa & 63;
                int rb = (pb & 4095) >> 6, cb = pb & 63;
                *(float2*)(OUT + ((((size_t)img * PADW + ra + 1) * PADW + ca + 1) * CC) + n0 + ol) = v0;
                *(float2*)(OUT + ((((size_t)img * PADW + rb + 1) * PADW + cb + 1) * CC) + n0 + ol) = v1;
            }
        }
    } else if (mode == 3) {
        // fused bn + threshold: write fp16 spikes (NHWC natural)
        __half* OH = (__half*)OUT;
#pragma unroll
        for (int mt = 0; mt < 4; mt++) {
            int pa = p0 + wm * 64 + mt * 16 + lr;
            int pb = pa + 8;
#pragma unroll
            for (int nt = 0; nt < 8; nt++) {
                int ol = wn * 64 + nt * 8 + 2 * lc;
                float s0 = smf[SCL_F + ol], s1 = smf[SCL_F + ol + 1];
                float z0 = smf[SBS_F + ol], z1 = smf[SBS_F + ol + 1];
                __half q0 = __float2half_rn((acc[mt][nt][0] * s0 + z0 - vthv >= 0.0f) ? 1.0f : 0.0f);
                __half q1 = __float2half_rn((acc[mt][nt][1] * s1 + z1 - vthv >= 0.0f) ? 1.0f : 0.0f);
                __half q2 = __float2half_rn((acc[mt][nt][2] * s0 + z0 - vthv >= 0.0f) ? 1.0f : 0.0f);
                __half q3 = __float2half_rn((acc[mt][nt][3] * s1 + z1 - vthv >= 0.0f) ? 1.0f : 0.0f);
                *(__half2*)(OH + ((size_t)img * NN + pa) * CC + n0 + ol) = __halves2half2(q0, q1);
                *(__half2*)(OH + ((size_t)img * NN + pb) * CC + n0 + ol) = __halves2half2(q2, q3);
            }
        }
    } else {
        float* T = smf + wid * (64 * 68);
#pragma unroll
        for (int mt = 0; mt < 4; mt++) {
            int mm = mt * 16 + lr;
#pragma unroll
            for (int nt = 0; nt < 8; nt++) {
                int nl = nt * 8 + 2 * lc;
                int ol = wn * 64 + nl;
                float s0 = smf[SCL_F + ol], s1 = smf[SCL_F + ol + 1];
                float z0 = smf[SBS_F + ol], z1 = smf[SBS_F + ol + 1];
                T[nl * 68 + mm]           = acc[mt][nt][0] * s0 + z0;
                T[(nl + 1) * 68 + mm]     = acc[mt][nt][1] * s1 + z1;
                T[nl * 68 + mm + 8]       = acc[mt][nt][2] * s0 + z0;
                T[(nl + 1) * 68 + mm + 8] = acc[mt][nt][3] * s1 + z1;
            }
        }
        __syncwarp();
#pragma unroll
        for (int ol = 0; ol < 64; ol++) {
            int o = n0 + wn * 64 + ol;
            float2 v = *(float2*)&T[ol * 68 + lane * 2];
            *(float2*)(OUT + ((size_t)img * CC + o) * NN + p0 + wm * 64 + lane * 2) = v;
        }
    }
}

// ---------------- presplit ALL 8 weight matrices ----------------
__global__ void presplit_all_kernel(const float* __restrict__ w1, const float* __restrict__ pw,
                                    __half* __restrict__ WHo, __half* __restrict__ W6o) {
    int idx = blockIdx.x * 256 + threadIdx.x;
    if (idx >= 8 * CCCC) return;
    int m = idx / CCCC, e = idx % CCCC;
    int o = e / CC, c = e % CC;
    const float* src = (m < 4) ? (w1 + (size_t)m * CCCC) : (pw + (size_t)(m - 4) * CCCC);
    float v = src[e];
    __half h = __float2half_rn(v);
    float r = (v - __half2float(h)) * 64.0f;
    WHo[(size_t)m * CCCC + (size_t)o * CC + perm32(c)] = h;
    W6o[(size_t)m * CCCC + (size_t)o * CC + perm32(c)] = __float2half_rn(r);
}

__global__ void dwt_kernel(const float* __restrict__ dw, float* __restrict__ dwt) {
    int idx = blockIdx.x * 256 + threadIdx.x;
    if (idx >= 4 * 9 * CC) return;
    int br = idx / (9 * CC), rr = idx % (9 * CC);
    int k = rr / CC, c = rr % CC;
    dwt[idx] = dw[(size_t)br * CC * 9 + c * 9 + k];
}

// ---------------- ALIF first: NCHW fp32 -> FILTERED spikes a~(t) (perm fp16; exact) ----------------
__global__ void alif_first_kernel(const float* __restrict__ in, __half* __restrict__ out,
                                  const float* __restrict__ vth_ptr) {
    __shared__ float s[32][33];
    int tx = threadIdx.x, ty = threadIdx.y;
    int n0 = blockIdx.x * 32;
    int c0 = blockIdx.y * 32;
    int b = blockIdx.z;
    float vth = vth_ptr[0];
    int cp = c0 + perm32(tx);
    float v[4] = {0.f, 0.f, 0.f, 0.f};
    float u[4] = {0.f, 0.f, 0.f, 0.f};
#pragma unroll
    for (int t = 0; t < TT; t++) {
#pragma unroll
        for (int k = 0; k < 4; k++) {
            int c = c0 + ty + 8 * k;
            float xv = in[(((size_t)(t * BB + b) * CC + c) * NN) + n0 + tx];
            v[k] = v[k] + (xv - v[k]) * 0.5f;
            float sp = (v[k] - vth >= 0.0f) ? 1.0f : 0.0f;
            s[ty + 8 * k][tx] = sp;
        }
        __syncthreads();
#pragma unroll
        for (int k = 0; k < 4; k++) {
            int n = n0 + ty + 8 * k;
            u[k] = u[k] * 0.5f + s[tx][ty + 8 * k] * 0.5f;   // filtered spike (exact /16 multiples)
            out[((size_t)(t * BB + b) * NN + n) * CC + cp] = __float2half_rn(u[k]);
        }
        __syncthreads();
    }
}

// ---------------- pad border fill (pv scaled by s_t when scaled) ----------------
__global__ void padfill_kernel(float* __restrict__ pad,
                               const float* __restrict__ bw, const float* __restrict__ bb,
                               const float* __restrict__ bm, const float* __restrict__ bv,
                               int scaled) {
    int t = blockIdx.x;
    int br = blockIdx.y >> 4, img = blockIdx.y & 15;
    int c = threadIdx.x;
    float inv = bw[br * CC + c] * rsqrtf(bv[br * CC + c] + EPS);
    float pv = (bb[br * CC + c] - bm[br * CC + c] * inv) * (scaled ? c_ST[img >> 2] : 1.0f);
    int r, cl;
    if      (t < 66)  { r = 0;           cl = t;        }
    else if (t < 132) { r = 65;          cl = t - 66;   }
    else if (t < 196) { r = t - 132 + 1; cl = 0;        }
    else              { r = t - 196 + 1; cl = 65;       }
    pad[(size_t)br * PADSZ + (((size_t)img * PADW + r) * PADW + cl) * CC + c] = pv;
}

// ---------------- depthwise 3x3 vectorized ----------------
__global__ void dwconv_kernel(const float* __restrict__ pad, const float* __restrict__ dwt,
                              __half* __restrict__ outH, __half* __restrict__ outL) {
    int br = blockIdx.z;
    int img = blockIdx.y;
    int p = blockIdx.x * 4 + threadIdx.y;
    int c4 = threadIdx.x * 4;
    int r = p >> 6, cl = p & 63;
    const float* base = pad + (size_t)br * PADSZ + (((size_t)img * PADW + r) * PADW + cl) * CC + c4;
    const float* wt = dwt + (size_t)br * 9 * CC + c4;
    float4 acc = make_float4(0.f, 0.f, 0.f, 0.f);
#pragma unroll
    for (int i = 0; i < 3; i++)
#pragma unroll
        for (int j = 0; j < 3; j++) {
            float4 xv = *(const float4*)(base + (size_t)(i * PADW + j) * CC);
            float4 wv = *(const float4*)(wt + (i * 3 + j) * CC);
            acc.x += wv.x * xv.x; acc.y += wv.y * xv.y;
            acc.z += wv.z * xv.z; acc.w += wv.w * xv.w;
        }
    __half h0 = __float2half_rn(acc.x), h1 = __float2half_rn(acc.y);
    __half h2 = __float2half_rn(acc.z), h3 = __float2half_rn(acc.w);
    __half l0 = __float2half_rn((acc.x - __half2float(h0)) * 64.0f);
    __half l1 = __float2half_rn((acc.y - __half2float(h1)) * 64.0f);
    __half l2 = __float2half_rn((acc.z - __half2float(h2)) * 64.0f);
    __half l3 = __float2half_rn((acc.w - __half2float(h3)) * 64.0f);
    int ch = c4 & ~31, r32 = c4 & 31;
    int pos = ch + ((r32 & 7) >> 1) * 8 + ((r32 >> 4) & 1) * 4 + ((r32 >> 3) & 1) * 2;
    size_t off = (size_t)br * IMGNNC + ((size_t)img * NN + p) * CC;
    *(__half2*)(outH + off + pos)     = __halves2half2(h0, h1);
    *(__half2*)(outH + off + pos + 8) = __halves2half2(h2, h3);
    *(__half2*)(outL + off + pos)     = __halves2half2(l0, l1);
    *(__half2*)(outL + off + pos + 8) = __halves2half2(l2, l3);
}

// ---------------- kv partial ----------------
__global__ void kv_kernel(const __half* __restrict__ K, const __half* __restrict__ V,
                          float* __restrict__ KVP) {
    int seg = blockIdx.x;
    int tbh = blockIdx.y;
    int tb = tbh / HEADS, h = tbh % HEADS;
    __shared__ float Ks[64][65];
    __shared__ float Vs[64][65];
    int tx = threadIdx.x;
    int td = tx >> 4, te = tx & 15;
    const __half* Kb = K + (size_t)tb * NN * CC + h * DH;
    const __half* Vb = V + (size_t)tb * NN * CC + h * DH;
    float acc[4][4];
#pragma unroll
    for (int i = 0; i < 4; i++)
#pragma unroll
        for (int j = 0; j < 4; j++) acc[i][j] = 0.0f;

    for (int n0 = seg * 1024; n0 < (seg + 1) * 1024; n0 += 64) {
#pragma unroll
        for (int u = 0; u < 16; u++) {
            int e = tx + u * 256;
            int n = e >> 6, d = e & 63;
            Ks[n][d] = __half2float(Kb[(size_t)(n0 + n) * CC + d]);
            Vs[n][d] = __half2float(Vb[(size_t)(n0 + n) * CC + d]);
        }
        __syncthreads();
#pragma unroll
        for (int n = 0; n < 64; n++) {
            float a0 = Ks[n][td * 4 + 0], a1 = Ks[n][td * 4 + 1];
            float a2 = Ks[n][td * 4 + 2], a3 = Ks[n][td * 4 + 3];
            float b0 = Vs[n][te * 4 + 0], b1 = Vs[n][te * 4 + 1];
            float b2 = Vs[n][te * 4 + 2], b3 = Vs[n][te * 4 + 3];
            acc[0][0] += a0 * b0; acc[0][1] += a0 * b1; acc[0][2] += a0 * b2; acc[0][3] += a0 * b3;
            acc[1][0] += a1 * b0; acc[1][1] += a1 * b1; acc[1][2] += a1 * b2; acc[1][3] += a1 * b3;
            acc[2][0] += a2 * b0; acc[2][1] += a2 * b1; acc[2][2] += a2 * b2; acc[2][3] += a2 * b3;
            acc[3][0] += a3 * b0; acc[3][1] += a3 * b1; acc[3][2] += a3 * b2; acc[3][3] += a3 * b3;
        }
        __syncthreads();
    }
#pragma unroll
    for (int i = 0; i < 4; i++)
#pragma unroll
        for (int j = 0; j < 4; j++)
            KVP[((size_t)seg * (TT * BB * HEADS) + tbh) * (DH * DH) + (td * 4 + i) * DH + te * 4 + j] =
                acc[i][j];
}

__global__ void kvred_kernel(const float* __restrict__ KVP, float* __restrict__ KV) {
    int idx = blockIdx.x * blockDim.x + threadIdx.x;
    const int tot = TT * BB * HEADS * DH * DH;
    if (idx >= tot) return;
    float s = 0.f;
#pragma unroll
    for (int g = 0; g < 4; g++) s += KVP[(size_t)g * tot + idx];
    KV[idx] = s;
}

// ---------------- FUSED av + attention alif ----------------
__global__ void avalif_kernel(const __half* __restrict__ Q, const float* __restrict__ KV,
                              __half* __restrict__ AS, const float* __restrict__ vth_ptr) {
    int nt = blockIdx.x;
    int bh = blockIdx.y;
    int b = bh / HEADS, h = bh % HEADS;
    __shared__ float kvs[64][65];
    __shared__ float Qs[64][65];
    int tx = threadIdx.x;
    int tn = tx >> 4, te = tx & 15;
    int n0 = nt * 64;
    float vth = vth_ptr[4];
    float vmem[4][4];
#pragma unroll
    for (int i = 0; i < 4; i++)
#pragma unroll
        for (int j = 0; j < 4; j++) vmem[i][j] = 0.0f;

    int c4 = h * DH + te * 4;
    int chb = c4 & ~31, r32 = c4 & 31;
    int pos = chb + ((r32 & 7) >> 1) * 8 + ((r32 >> 4) & 1) * 4 + ((r32 >> 3) & 1) * 2;

    for (int t = 0; t < TT; t++) {
        int tb = t * BB + b;
        int tbh = tb * HEADS + h;
        const __half* Qb = Q + (size_t)tb * NN * CC + h * DH;
#pragma unroll
        for (int u = 0; u < 16; u++) {
            int e = tx + u * 256;
            int r = e >> 6, x = e & 63;
            kvs[r][x] = KV[(size_t)tbh * DH * DH + r * DH + x];
            Qs[r][x] = __half2float(Qb[(size_t)(n0 + r) * CC + x]);
        }
        __syncthreads();
        float acc[4][4];
#pragma unroll
        for (int i = 0; i < 4; i++)
#pragma unroll
            for (int j = 0; j < 4; j++) acc[i][j] = 0.0f;
#pragma unroll
        for (int d = 0; d < 64; d++) {
            float a0 = Qs[tn * 4 + 0][d], a1 = Qs[tn * 4 + 1][d];
            float a2 = Qs[tn * 4 + 2][d], a3 = Qs[tn * 4 + 3][d];
            float b0 = kvs[d][te * 4 + 0], b1 = kvs[d][te * 4 + 1];
            float b2 = kvs[d][te * 4 + 2], b3 = kvs[d][te * 4 + 3];
            acc[0][0] += a0 * b0; acc[0][1] += a0 * b1; acc[0][2] += a0 * b2; acc[0][3] += a0 * b3;
            acc[1][0] += a1 * b0; acc[1][1] += a1 * b1; acc[1][2] += a1 * b2; acc[1][3] += a1 * b3;
            acc[2][0] += a2 * b0; acc[2][1] += a2 * b1; acc[2][2] += a2 * b2; acc[2][3] += a2 * b3;
            acc[3][0] += a3 * b0; acc[3][1] += a3 * b1; acc[3][2] += a3 * b2; acc[3][3] += a3 * b3;
        }
#pragma unroll
        for (int i = 0; i < 4; i++) {
            int n = n0 + tn * 4 + i;
            __half sp[4];
#pragma unroll
            for (int j = 0; j < 4; j++) {
                vmem[i][j] = vmem[i][j] + (acc[i][j] - vmem[i][j]) * 0.5f;
                sp[j] = __float2half_rn((vmem[i][j] - vth >= 0.0f) ? 1.0f : 0.0f);
            }
            size_t base = ((size_t)tb * NN + n) * CC;
            *(__half2*)(AS + base + pos)     = __halves2half2(sp[0], sp[1]);
            *(__half2*)(AS + base + pos + 8) = __halves2half2(sp[2], sp[3]);
        }
        __syncthreads();
    }
}

// ---------------- host orchestration ----------------
extern "C" void kernel_launch(void* const* d_in, const int* in_sizes, int n_in,
                              void* d_out, int out_size) {
    const float* x   = (const float*)d_in[0];
    const float* w1  = (const float*)d_in[1];
    const float* dw  = (const float*)d_in[2];
    const float* pw  = (const float*)d_in[3];
    const float* b1w = (const float*)d_in[4];
    const float* b1b = (const float*)d_in[5];
    const float* b1m = (const float*)d_in[6];
    const float* b1v = (const float*)d_in[7];
    const float* b2w = (const float*)d_in[8];
    const float* b2b = (const float*)d_in[9];
    const float* b2m = (const float*)d_in[10];
    const float* b2v = (const float*)d_in[11];
    const float* b3w = (const float*)d_in[12];
    const float* b3b = (const float*)d_in[13];
    const float* b3m = (const float*)d_in[14];
    const float* b3v = (const float*)d_in[15];
    const float* vth = (const float*)d_in[16];
    float* out = (float*)d_out;

    cudaFuncSetAttribute(conv_mma_kernel, cudaFuncAttributeMaxDynamicSharedMemorySize, SMEM_BYTES);

    float *PAD3, *DWT, *KVP, *KV;
    __half *XS, *AS, *DWH3, *DW63, *QKVh, *WH, *W6;
    cudaGetSymbolAddress((void**)&XS,   g_XS);
    cudaGetSymbolAddress((void**)&PAD3, g_PAD3);
    cudaGetSymbolAddress((void**)&DWH3, g_DWH3);
    cudaGetSymbolAddress((void**)&DW63, g_DW63);
    cudaGetSymbolAddress((void**)&QKVh, g_QKVh);
    cudaGetSymbolAddress((void**)&AS,   g_AS);
    cudaGetSymbolAddress((void**)&WH,   g_WH);
    cudaGetSymbolAddress((void**)&W6,   g_W6);
    cudaGetSymbolAddress((void**)&DWT,  g_DWT);
    cudaGetSymbolAddress((void**)&KVP,  g_KVP);
    cudaGetSymbolAddress((void**)&KV,   g_KV);

    // 0) weight prep
    presplit_all_kernel<<<(8 * CCCC + 255) / 256, 256>>>(w1, pw, WH, W6);
    dwt_kernel<<<(4 * 9 * CC + 255) / 256, 256>>>(dw, DWT);

    // 1) alif on x -> FILTERED spikes (perm fp16, exact)
    alif_first_kernel<<<dim3(NN / 32, CC / 32, BB), dim3(32, 8)>>>(x, XS, vth);

    // 2) q/k/v branches batched; conv2 fuses bn + threshold -> spikes (no alif pass)
    padfill_kernel<<<dim3(260, IMG * 3), CC>>>(PAD3, b1w, b1b, b1m, b1v, 1);
    conv_mma_kernel<<<dim3(16, 3, IMG * 3), 256, SMEM_BYTES>>>(XS, XS, WH, W6, PAD3,
        b1w, b1b, b1m, b1v, nullptr, nullptr, nullptr, nullptr, 0, 0, PADSZ, nullptr, 1);
    dwconv_kernel<<<dim3(NN / 4, IMG, 3), dim3(96, 4)>>>(PAD3, DWT, DWH3, DW63);
    conv_mma_kernel<<<dim3(16, 3, IMG * 3), 256, SMEM_BYTES>>>(DWH3, DW63,
        WH + 4 * (size_t)CCCC, W6 + 4 * (size_t)CCCC, (float*)QKVh,
        b2w, b2b, b2m, b2v, b3w, b3b, b3m, b3v, 3, IMGNNC, IMGNNC / 2, vth, 1);
        // oBrStride in floats: QKVh is __half, so stride IMGNNC halves = IMGNNC/2 floats

    // 3) attention: kv + fused av/alif
    kv_kernel<<<dim3(4, TT * BB * HEADS), 256>>>(QKVh + IMGNNC, QKVh + 2 * IMGNNC, KVP);
    kvred_kernel<<<(TT * BB * HEADS * DH * DH + 255) / 256, 256>>>(KVP, KV);
    avalif_kernel<<<dim3(64, BB * HEADS), 256>>>(QKVh, KV, AS, vth);

    // 4) final branch (plain spikes, unscaled biases) -> d_out
    padfill_kernel<<<dim3(260, IMG), CC>>>(PAD3, b1w + 3 * CC, b1b + 3 * CC, b1m + 3 * CC, b1v + 3 * CC, 0);
    conv_mma_kernel<<<dim3(16, 3, IMG), 256, SMEM_BYTES>>>(AS, AS,
        WH + 3 * (size_t)CCCC, W6 + 3 * (size_t)CCCC, PAD3,
        b1w + 3 * CC, b1b + 3 * CC, b1m + 3 * CC, b1v + 3 * CC,
        nullptr, nullptr, nullptr, nullptr, 0, 0, 0, nullptr, 0);
    dwconv_kernel<<<dim3(NN / 4, IMG, 1), dim3(96, 4)>>>(PAD3, DWT + 3 * 9 * CC, DWH3, DW63);
    conv_mma_kernel<<<dim3(16, 3, IMG), 256, SMEM_BYTES>>>(DWH3, DW63,
        WH + 7 * (size_t)CCCC, W6 + 7 * (size_t)CCCC, out,
        b2w + 3 * CC, b2b + 3 * CC, b2m + 3 * CC, b2v + 3 * CC,
        b3w + 3 * CC, b3b + 3 * CC, b3m + 3 * CC, b3v + 3 * CC, 2, 0, 0, nullptr, 0);
}

// round 15
// speedup vs baseline: 2.7171x; 1.0666x over previous
#include <cuda_runtime.h>
#include <cuda_fp16.h>
#include <cstdint>
#include <cstddef>

#define TT 4
#define BB 4
#define CC 384
#define NN 4096
#define IMG 16
#define BCN (BB*CC*NN)
#define IMGNNC ((size_t)IMG*NN*CC)
#define PADSZ  ((size_t)IMG*PADW*PADW*CC)
#define CCCC (CC*CC)
#define HEADS 6
#define DH 64
#define PADW 66
#define EPS 1e-5f

// ---------------- scratch (static device globals) ----------------
__device__ __align__(256) __half g_XS  [IMG*NN*CC];          // FILTERED spikes of x (perm)
__device__ __align__(256) float  g_PAD3[3*IMG*PADW*PADW*CC];
__device__ __align__(256) __half g_DWH3[3*IMG*NN*CC];
__device__ __align__(256) __half g_DW63[3*IMG*NN*CC];
__device__ __align__(256) __half g_QKVh[3*IMG*NN*CC];        // q/k/v spikes fp16 (natural)
__device__ __align__(256) __half g_AS  [IMG*NN*CC];          // attention spikes (perm)
__device__ __align__(256) __half g_WH  [8*CC*CC];
__device__ __align__(256) __half g_W6  [8*CC*CC];
__device__ __align__(256) float  g_DWT [4*9*CC];
__device__ __align__(256) float  g_KVP [4*TT*BB*HEADS*DH*DH];
__device__ __align__(256) float  g_KV  [TT*BB*HEADS*DH*DH];

__device__ __forceinline__ void mmaf16(float* c, uint32_t a0, uint32_t a1, uint32_t a2, uint32_t a3,
                                       uint32_t b0, uint32_t b1) {
    asm volatile("mma.sync.aligned.m16n8k16.row.col.f32.f16.f16.f32 "
                 "{%0,%1,%2,%3}, {%4,%5,%6,%7}, {%8,%9}, {%0,%1,%2,%3};"
                 : "+f"(c[0]), "+f"(c[1]), "+f"(c[2]), "+f"(c[3])
                 : "r"(a0), "r"(a1), "r"(a2), "r"(a3), "r"(b0), "r"(b1));
}
__device__ __forceinline__ uint32_t h2s6(uint32_t x) {
    uint32_t d;
    asm("mul.rn.f16x2 %0, %1, %2;" : "=r"(d) : "r"(x), "r"(0x24002400u));
    return d;
}
__device__ __forceinline__ void cp16(uint32_t dst, const void* src) {
    asm volatile("cp.async.cg.shared.global [%0], [%1], 16;" :: "r"(dst), "l"(src));
}
#define CP_COMMIT() asm volatile("cp.async.commit_group;" ::: "memory")
#define CP_WAIT0()  asm volatile("cp.async.wait_group 0;" ::: "memory")
#define CP_WAIT1()  asm volatile("cp.async.wait_group 1;" ::: "memory")
__device__ __forceinline__ uint32_t s2u(const void* p) {
    uint32_t a;
    asm("{ .reg .u64 t; cvta.to.shared.u64 t, %1; cvt.u32.u64 %0, t; }" : "=r"(a) : "l"(p));
    return a;
}
__device__ __forceinline__ int perm32(int c) {
    int ch = c & ~31, r = c & 31;
    return ch + ((r & 7) >> 1) * 8 + ((r >> 4) & 1) * 4 + ((r >> 3) & 1) * 2 + (r & 1);
}
__device__ __constant__ float c_ST[4] = {0.5f, 0.75f, 0.875f, 0.9375f};

// ---- smem layout (bytes): 3 stages of [AH 16K | A6 16K | WH 8K | W6 8K]
#define AH_B 0
#define A6_B 16384
#define WH_B 32768
#define W6_B 40960
#define STAGE_B 49152
#define NSTAGE 3
#define SCL_F 36864
#define SBS_F 36992
#define SMEM_BYTES 148480

// ---------------- conv1x1: 8 warps, warp tile 64x64, streamed W6/A6 ----------------
// CTA 256(M) x 128(N), K=384 in 12 chunks. grid (16, 3, NBR*IMG).
// mode 0: binary/filtered A (2 passes) -> PAD interior (bias*st if scaled)
// mode 2: hi/lo A (3 passes) -> NCHW fp32 (d_out)
// mode 3: hi/lo A (3 passes) -> fused bn + membrane-threshold -> fp16 spikes NHWC
__global__ void __launch_bounds__(256, 1)
conv_mma_kernel(const __half* __restrict__ AHg, const __half* __restrict__ A6g,
                const __half* __restrict__ WHg, const __half* __restrict__ W6g,
                float* __restrict__ OUT,
                const float* __restrict__ wA, const float* __restrict__ bA,
                const float* __restrict__ mA, const float* __restrict__ vA,
                const float* __restrict__ wB, const float* __restrict__ bB2,
                const float* __restrict__ mB, const float* __restrict__ vB,
                int mode, size_t aBrStride, size_t oBrStride,
                const float* __restrict__ vthp, int scaled) {
    extern __shared__ char smem[];
    float* smf = (float*)smem;
    const int tx = threadIdx.x;
    const int wid = tx >> 5, lane = tx & 31;
    const int lr = lane >> 2, lc = lane & 3;
    const int wm = wid >> 1, wn = wid & 1;
    const int br  = blockIdx.z >> 4;
    const int img = blockIdx.z & 15;
    const int p0 = blockIdx.x * 256;
    const int n0 = blockIdx.y * 128;
    const bool dense = (mode != 0);
    AHg += (size_t)br * aBrStride;
    A6g += (size_t)br * aBrStride;
    WHg += (size_t)br * CCCC;
    W6g += (size_t)br * CCCC;
    OUT += (size_t)br * oBrStride;
    wA += br * CC; bA += br * CC; mA += br * CC; vA += br * CC;
    if (wB) { wB += br * CC; bB2 += br * CC; mB += br * CC; vB += br * CC; }
    const float bscale = scaled ? c_ST[img >> 2] : 1.0f;
    const float vthv = vthp ? (vthp[1 + br]) : 0.0f;

    const size_t arow0 = (size_t)img * NN + p0;
    const uint32_t smb = s2u(smem);

    if (tx < 128) {
        int o = n0 + tx;
        float s, bias;
        if (mode == 0) {
            float inv = wA[o] * rsqrtf(vA[o] + EPS);
            s = inv; bias = (bA[o] - mA[o] * inv) * bscale;
        } else {
            float s2 = wA[o] * rsqrtf(vA[o] + EPS);
            float t2 = bA[o] - mA[o] * s2;
            float s3 = wB[o] * rsqrtf(vB[o] + EPS);
            float t3 = bB2[o] - mB[o] * s3;
            s = s2 * s3; bias = (t2 * s3 + t3) * bscale;
        }
        smf[SCL_F + tx] = s;
        smf[SBS_F + tx] = bias;
    }

    auto issue_chunk = [&](int ch, int st) {
        int c0 = ch * 32;
        uint32_t stb = smb + (uint32_t)st * STAGE_B;
#pragma unroll
        for (int it = 0; it < 4; it++) {
            int u = tx + it * 256;
            int row = u >> 2, q = u & 3;
            cp16(stb + AH_B + row * 64 + q * 16, AHg + (arow0 + row) * CC + c0 + q * 8);
        }
        if (dense) {
#pragma unroll
            for (int it = 0; it < 4; it++) {
                int u = tx + it * 256;
                int row = u >> 2, q = u & 3;
                cp16(stb + A6_B + row * 64 + q * 16, A6g + (arow0 + row) * CC + c0 + q * 8);
            }
        }
#pragma unroll
        for (int it = 0; it < 2; it++) {
            int u = tx + it * 256;
            int row = u >> 2, q = u & 3;
            cp16(stb + WH_B + row * 64 + q * 16, WHg + (size_t)(n0 + row) * CC + c0 + q * 8);
            cp16(stb + W6_B + row * 64 + q * 16, W6g + (size_t)(n0 + row) * CC + c0 + q * 8);
        }
    };

    float acc[4][8][4];
#pragma unroll
    for (int a = 0; a < 4; a++)
#pragma unroll
        for (int b = 0; b < 8; b++)
#pragma unroll
            for (int c = 0; c < 4; c++) acc[a][b][c] = 0.0f;

    auto compute = [&](int st) {
        const char* Sb = smem + st * STAGE_B;
        uint4 Bh[8];
#pragma unroll
        for (int nt = 0; nt < 8; nt++) {
            int n = wn * 64 + nt * 8 + lr;
            Bh[nt] = *(const uint4*)(Sb + WH_B + n * 64 + lc * 16);
        }
        uint4 Ah0[4], Ah1[4];
#pragma unroll
        for (int mt = 0; mt < 4; mt++) {
            int r = wm * 64 + mt * 16 + lr;
            Ah0[mt] = *(const uint4*)(Sb + AH_B + r * 64 + lc * 16);
            Ah1[mt] = *(const uint4*)(Sb + AH_B + (r + 8) * 64 + lc * 16);
        }
#pragma unroll
        for (int mt = 0; mt < 4; mt++)
#pragma unroll
            for (int nt = 0; nt < 8; nt++) {
                mmaf16(acc[mt][nt], Ah0[mt].x, Ah1[mt].x, Ah0[mt].y, Ah1[mt].y, Bh[nt].x, Bh[nt].y);
                mmaf16(acc[mt][nt], Ah0[mt].z, Ah1[mt].z, Ah0[mt].w, Ah1[mt].w, Bh[nt].z, Bh[nt].w);
            }
#pragma unroll
        for (int mt = 0; mt < 4; mt++) {
            Ah0[mt].x = h2s6(Ah0[mt].x); Ah0[mt].y = h2s6(Ah0[mt].y);
            Ah0[mt].z = h2s6(Ah0[mt].z); Ah0[mt].w = h2s6(Ah0[mt].w);
            Ah1[mt].x = h2s6(Ah1[mt].x); Ah1[mt].y = h2s6(Ah1[mt].y);
            Ah1[mt].z = h2s6(Ah1[mt].z); Ah1[mt].w = h2s6(Ah1[mt].w);
        }
#pragma unroll
        for (int nt = 0; nt < 8; nt++) {
            int n = wn * 64 + nt * 8 + lr;
            uint4 W6f = *(const uint4*)(Sb + W6_B + n * 64 + lc * 16);
#pragma unroll
            for (int mt = 0; mt < 4; mt++) {
                mmaf16(acc[mt][nt], Ah0[mt].x, Ah1[mt].x, Ah0[mt].y, Ah1[mt].y, W6f.x, W6f.y);
                mmaf16(acc[mt][nt], Ah0[mt].z, Ah1[mt].z, Ah0[mt].w, Ah1[mt].w, W6f.z, W6f.w);
            }
        }
        if (dense) {
#pragma unroll
            for (int nt = 0; nt < 8; nt++) {
                Bh[nt].x = h2s6(Bh[nt].x); Bh[nt].y = h2s6(Bh[nt].y);
                Bh[nt].z = h2s6(Bh[nt].z); Bh[nt].w = h2s6(Bh[nt].w);
            }
#pragma unroll
            for (int mt = 0; mt < 4; mt++) {
                int r = wm * 64 + mt * 16 + lr;
                uint4 A60 = *(const uint4*)(Sb + A6_B + r * 64 + lc * 16);
                uint4 A61 = *(const uint4*)(Sb + A6_B + (r + 8) * 64 + lc * 16);
#pragma unroll
                for (int nt = 0; nt < 8; nt++) {
                    mmaf16(acc[mt][nt], A60.x, A61.x, A60.y, A61.y, Bh[nt].x, Bh[nt].y);
                    mmaf16(acc[mt][nt], A60.z, A61.z, A60.w, A61.w, Bh[nt].z, Bh[nt].w);
                }
            }
        }
    };

    issue_chunk(0, 0); CP_COMMIT();
    issue_chunk(1, 1); CP_COMMIT();
    int st = 0;
    for (int ch = 0; ch < 12; ch++) {
        if (ch < 11) CP_WAIT1(); else CP_WAIT0();
        __syncthreads();
        compute(st);
        if (ch < 10) {
            int st2 = st + 2; if (st2 >= NSTAGE) st2 -= NSTAGE;
            issue_chunk(ch + 2, st2);
            CP_COMMIT();
        }
        if (++st == NSTAGE) st = 0;
    }
    __syncthreads();

    if (mode == 0) {
#pragma unroll
        for (int mt = 0; mt < 4; mt++) {
            int pa = p0 + wm * 64 + mt * 16 + lr;
            int pb = pa + 8;
#pragma unroll
            for (int nt = 0; nt < 8; nt++) {
                int ol = wn * 64 + nt * 8 + 2 * lc;
                float s0 = smf[SCL_F + ol], s1 = smf[SCL_F + ol + 1];
                float z0 = smf[SBS_F + ol], z1 = smf[SBS_F + ol + 1];
                float2 v0 = make_float2(acc[mt][nt][0] * s0 + z0, acc[mt][nt][1] * s1 + z1);
                float2 v1 = make_float2(acc[mt][nt][2] * s0 + z0, acc[mt][nt][3] * s1 + z1);
                int ra = (pa & 4095) >> 6, ca = pa & 63;
                int rb = (pb & 4095) >> 6, cb = pb & 63;
                *(float2*)(OUT + ((((size_t)img * PADW + ra + 1) * PADW + ca + 1) * CC) + n0 + ol) = v0;
                *(float2*)(OUT + ((((size_t)img * PADW + rb + 1) * PADW + cb + 1) * CC) + n0 + ol) = v1;
            }
        }
    } else if (mode == 3) {
        __half* OH = (__half*)OUT;
#pragma unroll
        for (int mt = 0; mt < 4; mt++) {
            int pa = p0 + wm * 64 + mt * 16 + lr;
            int pb = pa + 8;
#pragma unroll
            for (int nt = 0; nt < 8; nt++) {
                int ol = wn * 64 + nt * 8 + 2 * lc;
                float s0 = smf[SCL_F + ol], s1 = smf[SCL_F + ol + 1];
                float z0 = smf[SBS_F + ol], z1 = smf[SBS_F + ol + 1];
                __half q0 = __float2half_rn((acc[mt][nt][0] * s0 + z0 - vthv >= 0.0f) ? 1.0f : 0.0f);
                __half q1 = __float2half_rn((acc[mt][nt][1] * s1 + z1 - vthv >= 0.0f) ? 1.0f : 0.0f);
                __half q2 = __float2half_rn((acc[mt][nt][2] * s0 + z0 - vthv >= 0.0f) ? 1.0f : 0.0f);
                __half q3 = __float2half_rn((acc[mt][nt][3] * s1 + z1 - vthv >= 0.0f) ? 1.0f : 0.0f);
                *(__half2*)(OH + ((size_t)img * NN + pa) * CC + n0 + ol) = __halves2half2(q0, q1);
                *(__half2*)(OH + ((size_t)img * NN + pb) * CC + n0 + ol) = __halves2half2(q2, q3);
            }
        }
    } else {
        float* T = smf + wid * (64 * 68);
#pragma unroll
        for (int mt = 0; mt < 4; mt++) {
            int mm = mt * 16 + lr;
#pragma unroll
            for (int nt = 0; nt < 8; nt++) {
                int nl = nt * 8 + 2 * lc;
                int ol = wn * 64 + nl;
                float s0 = smf[SCL_F + ol], s1 = smf[SCL_F + ol + 1];
                float z0 = smf[SBS_F + ol], z1 = smf[SBS_F + ol + 1];
                T[nl * 68 + mm]           = acc[mt][nt][0] * s0 + z0;
                T[(nl + 1) * 68 + mm]     = acc[mt][nt][1] * s1 + z1;
                T[nl * 68 + mm + 8]       = acc[mt][nt][2] * s0 + z0;
                T[(nl + 1) * 68 + mm + 8] = acc[mt][nt][3] * s1 + z1;
            }
        }
        __syncwarp();
#pragma unroll
        for (int ol = 0; ol < 64; ol++) {
            int o = n0 + wn * 64 + ol;
            float2 v = *(float2*)&T[ol * 68 + lane * 2];
            *(float2*)(OUT + ((size_t)img * CC + o) * NN + p0 + wm * 64 + lane * 2) = v;
        }
    }
}

// ---------------- presplit ALL 8 weight matrices + dw transpose (fused) ----------------
__global__ void presplit_all_kernel(const float* __restrict__ w1, const float* __restrict__ pw,
                                    const float* __restrict__ dw,
                                    __half* __restrict__ WHo, __half* __restrict__ W6o,
                                    float* __restrict__ dwt) {
    int idx = blockIdx.x * 256 + threadIdx.x;
    if (idx < 4 * 9 * CC) {
        int br = idx / (9 * CC), rr = idx % (9 * CC);
        int k = rr / CC, c = rr % CC;
        dwt[idx] = dw[(size_t)br * CC * 9 + c * 9 + k];
    }
    if (idx >= 8 * CCCC) return;
    int m = idx / CCCC, e = idx % CCCC;
    int o = e / CC, c = e % CC;
    const float* src = (m < 4) ? (w1 + (size_t)m * CCCC) : (pw + (size_t)(m - 4) * CCCC);
    float v = src[e];
    __half h = __float2half_rn(v);
    float r = (v - __half2float(h)) * 64.0f;
    WHo[(size_t)m * CCCC + (size_t)o * CC + perm32(c)] = h;
    W6o[(size_t)m * CCCC + (size_t)o * CC + perm32(c)] = __float2half_rn(r);
}

// ---------------- ALIF first: NCHW fp32 -> FILTERED spikes (perm fp16; exact) ----------------
__global__ void alif_first_kernel(const float* __restrict__ in, __half* __restrict__ out,
                                  const float* __restrict__ vth_ptr) {
    __shared__ float s[32][33];
    int tx = threadIdx.x, ty = threadIdx.y;
    int n0 = blockIdx.x * 32;
    int c0 = blockIdx.y * 32;
    int b = blockIdx.z;
    float vth = vth_ptr[0];
    int cp = c0 + perm32(tx);
    float v[4] = {0.f, 0.f, 0.f, 0.f};
    float u[4] = {0.f, 0.f, 0.f, 0.f};
#pragma unroll
    for (int t = 0; t < TT; t++) {
#pragma unroll
        for (int k = 0; k < 4; k++) {
            int c = c0 + ty + 8 * k;
            float xv = in[(((size_t)(t * BB + b) * CC + c) * NN) + n0 + tx];
            v[k] = v[k] + (xv - v[k]) * 0.5f;
            float sp = (v[k] - vth >= 0.0f) ? 1.0f : 0.0f;
            s[ty + 8 * k][tx] = sp;
        }
        __syncthreads();
#pragma unroll
        for (int k = 0; k < 4; k++) {
            int n = n0 + ty + 8 * k;
            u[k] = u[k] * 0.5f + s[tx][ty + 8 * k] * 0.5f;
            out[((size_t)(t * BB + b) * NN + n) * CC + cp] = __float2half_rn(u[k]);
        }
        __syncthreads();
    }
}

// ---------------- pad border fill ----------------
__global__ void padfill_kernel(float* __restrict__ pad,
                               const float* __restrict__ bw, const float* __restrict__ bb,
                               const float* __restrict__ bm, const float* __restrict__ bv,
                               int scaled) {
    int t = blockIdx.x;
    int br = blockIdx.y >> 4, img = blockIdx.y & 15;
    int c = threadIdx.x;
    float inv = bw[br * CC + c] * rsqrtf(bv[br * CC + c] + EPS);
    float pv = (bb[br * CC + c] - bm[br * CC + c] * inv) * (scaled ? c_ST[img >> 2] : 1.0f);
    int r, cl;
    if      (t < 66)  { r = 0;           cl = t;        }
    else if (t < 132) { r = 65;          cl = t - 66;   }
    else if (t < 196) { r = t - 132 + 1; cl = 0;        }
    else              { r = t - 196 + 1; cl = 65;       }
    pad[(size_t)br * PADSZ + (((size_t)img * PADW + r) * PADW + cl) * CC + c] = pv;
}

// ---------------- depthwise 3x3: vertical 4-row register reuse ----------------
// grid (256 = 16 rowgroups x 16 colgroups, IMG, NBR); block (96, 4).
// Thread: 4 consecutive output rows x 4 channels at one column. 18 input float4
// loads + 9 weight float4 loads for 16 outputs (vs 36+9 before).
__global__ void dwconv_kernel(const float* __restrict__ pad, const float* __restrict__ dwt,
                              __half* __restrict__ outH, __half* __restrict__ outL) {
    int br = blockIdx.z;
    int img = blockIdx.y;
    int r0 = (blockIdx.x >> 4) * 4;
    int cl = (blockIdx.x & 15) * 4 + threadIdx.y;
    int c4 = threadIdx.x * 4;
    const float* base = pad + (size_t)br * PADSZ + (((size_t)img * PADW + r0) * PADW + cl) * CC + c4;
    const float* wt = dwt + (size_t)br * 9 * CC + c4;

    float4 acc[4];
#pragma unroll
    for (int r = 0; r < 4; r++) acc[r] = make_float4(0.f, 0.f, 0.f, 0.f);

#pragma unroll
    for (int j = 0; j < 3; j++) {
        float4 w0 = *(const float4*)(wt + (0 * 3 + j) * CC);
        float4 w1 = *(const float4*)(wt + (1 * 3 + j) * CC);
        float4 w2 = *(const float4*)(wt + (2 * 3 + j) * CC);
#pragma unroll
        for (int i = 0; i < 6; i++) {
            float4 xv = *(const float4*)(base + (size_t)(i * PADW + j) * CC);
            if (i < 4) {
                acc[i].x += w0.x * xv.x; acc[i].y += w0.y * xv.y;
                acc[i].z += w0.z * xv.z; acc[i].w += w0.w * xv.w;
            }
            if (i >= 1 && i < 5) {
                acc[i-1].x += w1.x * xv.x; acc[i-1].y += w1.y * xv.y;
                acc[i-1].z += w1.z * xv.z; acc[i-1].w += w1.w * xv.w;
            }
            if (i >= 2) {
                acc[i-2].x += w2.x * xv.x; acc[i-2].y += w2.y * xv.y;
                acc[i-2].z += w2.z * xv.z; acc[i-2].w += w2.w * xv.w;
            }
        }
    }

    int ch = c4 & ~31, r32 = c4 & 31;
    int pos = ch + ((r32 & 7) >> 1) * 8 + ((r32 >> 4) & 1) * 4 + ((r32 >> 3) & 1) * 2;
#pragma unroll
    for (int r = 0; r < 4; r++) {
        int p = (r0 + r) * 64 + cl;
        __half h0 = __float2half_rn(acc[r].x), h1 = __float2half_rn(acc[r].y);
        __half h2 = __float2half_rn(acc[r].z), h3 = __float2half_rn(acc[r].w);
        __half l0 = __float2half_rn((acc[r].x - __half2float(h0)) * 64.0f);
        __half l1 = __float2half_rn((acc[r].y - __half2float(h1)) * 64.0f);
        __half l2 = __float2half_rn((acc[r].z - __half2float(h2)) * 64.0f);
        __half l3 = __float2half_rn((acc[r].w - __half2float(h3)) * 64.0f);
        size_t off = (size_t)br * IMGNNC + ((size_t)img * NN + p) * CC;
        *(__half2*)(outH + off + pos)     = __halves2half2(h0, h1);
        *(__half2*)(outH + off + pos + 8) = __halves2half2(h2, h3);
        *(__half2*)(outL + off + pos)     = __halves2half2(l0, l1);
        *(__half2*)(outL + off + pos + 8) = __halves2half2(l2, l3);
    }
}

// ---------------- kv partial ----------------
__global__ void kv_kernel(const __half* __restrict__ K, const __half* __restrict__ V,
                          float* __restrict__ KVP) {
    int seg = blockIdx.x;
    int tbh = blockIdx.y;
    int tb = tbh / HEADS, h = tbh % HEADS;
    __shared__ float Ks[64][65];
    __shared__ float Vs[64][65];
    int tx = threadIdx.x;
    int td = tx >> 4, te = tx & 15;
    const __half* Kb = K + (size_t)tb * NN * CC + h * DH;
    const __half* Vb = V + (size_t)tb * NN * CC + h * DH;
    float acc[4][4];
#pragma unroll
    for (int i = 0; i < 4; i++)
#pragma unroll
        for (int j = 0; j < 4; j++) acc[i][j] = 0.0f;

    for (int n0 = seg * 1024; n0 < (seg + 1) * 1024; n0 += 64) {
#pragma unroll
        for (int u = 0; u < 16; u++) {
            int e = tx + u * 256;
            int n = e >> 6, d = e & 63;
            Ks[n][d] = __half2float(Kb[(size_t)(n0 + n) * CC + d]);
            Vs[n][d] = __half2float(Vb[(size_t)(n0 + n) * CC + d]);
        }
        __syncthreads();
#pragma unroll
        for (int n = 0; n < 64; n++) {
            float a0 = Ks[n][td * 4 + 0], a1 = Ks[n][td * 4 + 1];
            float a2 = Ks[n][td * 4 + 2], a3 = Ks[n][td * 4 + 3];
            float b0 = Vs[n][te * 4 + 0], b1 = Vs[n][te * 4 + 1];
            float b2 = Vs[n][te * 4 + 2], b3 = Vs[n][te * 4 + 3];
            acc[0][0] += a0 * b0; acc[0][1] += a0 * b1; acc[0][2] += a0 * b2; acc[0][3] += a0 * b3;
            acc[1][0] += a1 * b0; acc[1][1] += a1 * b1; acc[1][2] += a1 * b2; acc[1][3] += a1 * b3;
            acc[2][0] += a2 * b0; acc[2][1] += a2 * b1; acc[2][2] += a2 * b2; acc[2][3] += a2 * b3;
            acc[3][0] += a3 * b0; acc[3][1] += a3 * b1; acc[3][2] += a3 * b2; acc[3][3] += a3 * b3;
        }
        __syncthreads();
    }
#pragma unroll
    for (int i = 0; i < 4; i++)
#pragma unroll
        for (int j = 0; j < 4; j++)
            KVP[((size_t)seg * (TT * BB * HEADS) + tbh) * (DH * DH) + (td * 4 + i) * DH + te * 4 + j] =
                acc[i][j];
}

__global__ void kvred_kernel(const float* __restrict__ KVP, float* __restrict__ KV) {
    int idx = blockIdx.x * blockDim.x + threadIdx.x;
    const int tot = TT * BB * HEADS * DH * DH;
    if (idx >= tot) return;
    float s = 0.f;
#pragma unroll
    for (int g = 0; g < 4; g++) s += KVP[(size_t)g * tot + idx];
    KV[idx] = s;
}

// ---------------- FUSED av + attention alif ----------------
__global__ void avalif_kernel(const __half* __restrict__ Q, const float* __restrict__ KV,
                              __half* __restrict__ AS, const float* __restrict__ vth_ptr) {
    int nt = blockIdx.x;
    int bh = blockIdx.y;
    int b = bh / HEADS, h = bh % HEADS;
    __shared__ float kvs[64][65];
    __shared__ float Qs[64][65];
    int tx = threadIdx.x;
    int tn = tx >> 4, te = tx & 15;
    int n0 = nt * 64;
    float vth = vth_ptr[4];
    float vmem[4][4];
#pragma unroll
    for (int i = 0; i < 4; i++)
#pragma unroll
        for (int j = 0; j < 4; j++) vmem[i][j] = 0.0f;

    int c4 = h * DH + te * 4;
    int chb = c4 & ~31, r32 = c4 & 31;
    int pos = chb + ((r32 & 7) >> 1) * 8 + ((r32 >> 4) & 1) * 4 + ((r32 >> 3) & 1) * 2;

    for (int t = 0; t < TT; t++) {
        int tb = t * BB + b;
        int tbh = tb * HEADS + h;
        const __half* Qb = Q + (size_t)tb * NN * CC + h * DH;
#pragma unroll
        for (int u = 0; u < 16; u++) {
            int e = tx + u * 256;
            int r = e >> 6, x = e & 63;
            kvs[r][x] = KV[(size_t)tbh * DH * DH + r * DH + x];
            Qs[r][x] = __half2float(Qb[(size_t)(n0 + r) * CC + x]);
        }
        __syncthreads();
        float acc[4][4];
#pragma unroll
        for (int i = 0; i < 4; i++)
#pragma unroll
            for (int j = 0; j < 4; j++) acc[i][j] = 0.0f;
#pragma unroll
        for (int d = 0; d < 64; d++) {
            float a0 = Qs[tn * 4 + 0][d], a1 = Qs[tn * 4 + 1][d];
            float a2 = Qs[tn * 4 + 2][d], a3 = Qs[tn * 4 + 3][d];
            float b0 = kvs[d][te * 4 + 0], b1 = kvs[d][te * 4 + 1];
            float b2 = kvs[d][te * 4 + 2], b3 = kvs[d][te * 4 + 3];
            acc[0][0] += a0 * b0; acc[0][1] += a0 * b1; acc[0][2] += a0 * b2; acc[0][3] += a0 * b3;
            acc[1][0] += a1 * b0; acc[1][1] += a1 * b1; acc[1][2] += a1 * b2; acc[1][3] += a1 * b3;
            acc[2][0] += a2 * b0; acc[2][1] += a2 * b1; acc[2][2] += a2 * b2; acc[2][3] += a2 * b3;
            acc[3][0] += a3 * b0; acc[3][1] += a3 * b1; acc[3][2] += a3 * b2; acc[3][3] += a3 * b3;
        }
#pragma unroll
        for (int i = 0; i < 4; i++) {
            int n = n0 + tn * 4 + i;
            __half sp[4];
#pragma unroll
            for (int j = 0; j < 4; j++) {
                vmem[i][j] = vmem[i][j] + (acc[i][j] - vmem[i][j]) * 0.5f;
                sp[j] = __float2half_rn((vmem[i][j] - vth >= 0.0f) ? 1.0f : 0.0f);
            }
            size_t base = ((size_t)tb * NN + n) * CC;
            *(__half2*)(AS + base + pos)     = __halves2half2(sp[0], sp[1]);
            *(__half2*)(AS + base + pos + 8) = __halves2half2(sp[2], sp[3]);
        }
        __syncthreads();
    }
}

// ---------------- host orchestration ----------------
extern "C" void kernel_launch(void* const* d_in, const int* in_sizes, int n_in,
                              void* d_out, int out_size) {
    const float* x   = (const float*)d_in[0];
    const float* w1  = (const float*)d_in[1];
    const float* dw  = (const float*)d_in[2];
    const float* pw  = (const float*)d_in[3];
    const float* b1w = (const float*)d_in[4];
    const float* b1b = (const float*)d_in[5];
    const float* b1m = (const float*)d_in[6];
    const float* b1v = (const float*)d_in[7];
    const float* b2w = (const float*)d_in[8];
    const float* b2b = (const float*)d_in[9];
    const float* b2m = (const float*)d_in[10];
    const float* b2v = (const float*)d_in[11];
    const float* b3w = (const float*)d_in[12];
    const float* b3b = (const float*)d_in[13];
    const float* b3m = (const float*)d_in[14];
    const float* b3v = (const float*)d_in[15];
    const float* vth = (const float*)d_in[16];
    float* out = (float*)d_out;

    cudaFuncSetAttribute(conv_mma_kernel, cudaFuncAttributeMaxDynamicSharedMemorySize, SMEM_BYTES);

    float *PAD3, *DWT, *KVP, *KV;
    __half *XS, *AS, *DWH3, *DW63, *QKVh, *WH, *W6;
    cudaGetSymbolAddress((void**)&XS,   g_XS);
    cudaGetSymbolAddress((void**)&PAD3, g_PAD3);
    cudaGetSymbolAddress((void**)&DWH3, g_DWH3);
    cudaGetSymbolAddress((void**)&DW63, g_DW63);
    cudaGetSymbolAddress((void**)&QKVh, g_QKVh);
    cudaGetSymbolAddress((void**)&AS,   g_AS);
    cudaGetSymbolAddress((void**)&WH,   g_WH);
    cudaGetSymbolAddress((void**)&W6,   g_W6);
    cudaGetSymbolAddress((void**)&DWT,  g_DWT);
    cudaGetSymbolAddress((void**)&KVP,  g_KVP);
    cudaGetSymbolAddress((void**)&KV,   g_KV);

    // 0) weight prep (presplit + dw transpose fused)
    presplit_all_kernel<<<(8 * CCCC + 255) / 256, 256>>>(w1, pw, dw, WH, W6, DWT);

    // 1) alif on x -> FILTERED spikes (perm fp16, exact)
    alif_first_kernel<<<dim3(NN / 32, CC / 32, BB), dim3(32, 8)>>>(x, XS, vth);

    // 2) q/k/v branches batched; conv2 fuses bn + threshold -> spikes
    padfill_kernel<<<dim3(260, IMG * 3), CC>>>(PAD3, b1w, b1b, b1m, b1v, 1);
    conv_mma_kernel<<<dim3(16, 3, IMG * 3), 256, SMEM_BYTES>>>(XS, XS, WH, W6, PAD3,
        b1w, b1b, b1m, b1v, nullptr, nullptr, nullptr, nullptr, 0, 0, PADSZ, nullptr, 1);
    dwconv_kernel<<<dim3(256, IMG, 3), dim3(96, 4)>>>(PAD3, DWT, DWH3, DW63);
    conv_mma_kernel<<<dim3(16, 3, IMG * 3), 256, SMEM_BYTES>>>(DWH3, DW63,
        WH + 4 * (size_t)CCCC, W6 + 4 * (size_t)CCCC, (float*)QKVh,
        b2w, b2b, b2m, b2v, b3w, b3b, b3m, b3v, 3, IMGNNC, IMGNNC / 2, vth, 1);

    // 3) attention: kv + fused av/alif
    kv_kernel<<<dim3(4, TT * BB * HEADS), 256>>>(QKVh + IMGNNC, QKVh + 2 * IMGNNC, KVP);
    kvred_kernel<<<(TT * BB * HEADS * DH * DH + 255) / 256, 256>>>(KVP, KV);
    avalif_kernel<<<dim3(64, BB * HEADS), 256>>>(QKVh, KV, AS, vth);

    // 4) final branch -> d_out
    padfill_kernel<<<dim3(260, IMG), CC>>>(PAD3, b1w + 3 * CC, b1b + 3 * CC, b1m + 3 * CC, b1v + 3 * CC, 0);
    conv_mma_kernel<<<dim3(16, 3, IMG), 256, SMEM_BYTES>>>(AS, AS,
        WH + 3 * (size_t)CCCC, W6 + 3 * (size_t)CCCC, PAD3,
        b1w + 3 * CC, b1b + 3 * CC, b1m + 3 * CC, b1v + 3 * CC,
        nullptr, nullptr, nullptr, nullptr, 0, 0, 0, nullptr, 0);
    dwconv_kernel<<<dim3(256, IMG, 1), dim3(96, 4)>>>(PAD3, DWT + 3 * 9 * CC, DWH3, DW63);
    conv_mma_kernel<<<dim3(16, 3, IMG), 256, SMEM_BYTES>>>(DWH3, DW63,
        WH + 7 * (size_t)CCCC, W6 + 7 * (size_t)CCCC, out,
        b2w + 3 * CC, b2b + 3 * CC, b2m + 3 * CC, b2v + 3 * CC,
        b3w + 3 * CC, b3b + 3 * CC, b3m + 3 * CC, b3v + 3 * CC, 2, 0, 0, nullptr, 0);
}